// round 3
// baseline (speedup 1.0000x reference)
#include <cuda_runtime.h>
#include <cstdint>

// Problem shape (fixed by dataset): E=8, T=2048, D=2048, I=1024
#define E_     8
#define T_     2048
#define D_     2048
#define I_     1024
#define TWOI_  2048
#define EPS_   1e-6f
#define QMAX_  127.0f

// ---------------- scratch (static device globals; no allocation) -------------
__device__ int8_t g_xq1[(long)E_ * T_ * D_];       // quantized x           (33.5MB)
__device__ int8_t g_wq1[(long)E_ * TWOI_ * D_];    // quantized gate_up w   (33.5MB)
__device__ int8_t g_aq [(long)E_ * T_ * I_];       // quantized swiglu act  (16.8MB)
__device__ int8_t g_wq2[(long)E_ * D_ * I_];       // quantized down w      (16.8MB)
__device__ float  g_h  [(long)E_ * T_ * TWOI_];    // GEMM1 output          (134MB)
__device__ float  g_a  [(long)E_ * T_ * I_];       // swiglu output         (67MB)
__device__ float  g_amax_x1[E_ * D_];
__device__ float  g_amax_w1[E_ * D_];
__device__ float  g_amax_a [E_ * I_];
__device__ float  g_amax_w2[E_ * I_];
__device__ float  g_s1 [E_ * D_];
__device__ float  g_s2 [E_ * I_];
__device__ float  g_xs1[E_ * T_];                  // per-token scale, GEMM1
__device__ float  g_ws1[E_ * TWOI_];               // per-row scale, w1
__device__ float  g_xs2[E_ * T_];                  // per-token scale, GEMM2
__device__ float  g_ws2[E_ * D_];                  // per-row scale, w2

// ---------------- column abs-max over rows: out[e,c] = max_r |M[e,r,c]| ------
// grid: (C/256, R/RCH, E), block 256. Accumulated with atomicMax on uint bits
// (valid since values are >= 0 and buffers are zeroed first).
__global__ void colmax_kernel(const float* __restrict__ M, float* __restrict__ out,
                              int R, int C, int RCH) {
    int c = blockIdx.x * 256 + threadIdx.x;
    int e = blockIdx.z;
    const float* p = M + (long)e * R * C + (long)blockIdx.y * RCH * C + c;
    float m = 0.f;
#pragma unroll 4
    for (int r = 0; r < RCH; ++r)
        m = fmaxf(m, fabsf(p[(long)r * C]));
    atomicMax((unsigned int*)(out + e * C + c), __float_as_uint(m));
}

// ---------------- smooth scale: s = max(sqrt(max(ax,eps)/max(aw,eps)), eps) --
__global__ void smooth_scale_kernel(const float* __restrict__ ax,
                                    const float* __restrict__ aw,
                                    float* __restrict__ s, int n) {
    int i = blockIdx.x * 256 + threadIdx.x;
    if (i < n) {
        float v = sqrtf(fmaxf(ax[i], EPS_) / fmaxf(aw[i], EPS_));
        s[i] = fmaxf(v, EPS_);
    }
}

// ---------------- per-row quantization -------------------------------------
// MUL=1: v = row[c]*s[c] (weights). MUL=0: v = row[c]/s[c] (activations).
// rowscale = max(rowmax|v|, eps)/127 ; q = clip(rint(v/rowscale), -127, 127)
// grid: (R, E), block 256.
template <int MUL>
__global__ void quant_rows_kernel(const float* __restrict__ M, const float* __restrict__ s,
                                  int8_t* __restrict__ q, float* __restrict__ rs,
                                  int R, int C) {
    __shared__ float buf[2048];
    __shared__ float red[256];
    int e = blockIdx.y, r = blockIdx.x;
    const float* row = M + ((long)e * R + r) * (long)C;
    const float* sv  = s + (long)e * C;
    float m = 0.f;
    for (int c = threadIdx.x; c < C; c += 256) {
        float v = MUL ? row[c] * sv[c] : row[c] / sv[c];
        buf[c] = v;
        m = fmaxf(m, fabsf(v));
    }
    red[threadIdx.x] = m;
    __syncthreads();
#pragma unroll
    for (int off = 128; off > 0; off >>= 1) {
        if (threadIdx.x < off)
            red[threadIdx.x] = fmaxf(red[threadIdx.x], red[threadIdx.x + off]);
        __syncthreads();
    }
    float scale = fmaxf(red[0], EPS_) * (1.0f / QMAX_);
    if (threadIdx.x == 0) rs[(long)e * R + r] = scale;
    int8_t* qr = q + ((long)e * R + r) * (long)C;
    for (int c = threadIdx.x; c < C; c += 256) {
        float v = rintf(buf[c] / scale);       // rintf = round-half-even (matches jnp.round)
        v = fminf(fmaxf(v, -QMAX_), QMAX_);
        qr[c] = (int8_t)(int)v;
    }
}

// ---------------- int8 GEMM: C[m,n] = (sum_k A[m,k]*B[n,k]) * as[m] * bs[n] --
// A: [E,M,K] int8 row-major, B: [E,N,K] int8 row-major (both K contiguous).
// 128x128 tile / 256 threads / 8x8 per-thread microtile / BK = 32 bytes.
__global__ void __launch_bounds__(256, 2)
gemm_s8_kernel(const int8_t* __restrict__ A, const int8_t* __restrict__ B,
               float* __restrict__ Co, const float* __restrict__ asc_,
               const float* __restrict__ bsc_, int M, int N, int K) {
    __shared__ uint32_t As[8][128];   // [k-word][m]
    __shared__ uint32_t Bs[8][128];   // [k-word][n]

    int e = blockIdx.z;
    const int8_t* Ae = A + (long)e * M * K;
    const int8_t* Be = B + (long)e * N * K;

    int tid = threadIdx.x;
    int tx = tid & 15, ty = tid >> 4;
    int m0 = blockIdx.y * 128, n0 = blockIdx.x * 128;

    // stage load: each thread brings 16B of A and 16B of B per 32B K-chunk
    int lrow = tid >> 1;
    int lw   = (tid & 1) * 4;
    const uint4* gA = reinterpret_cast<const uint4*>(Ae + (long)(m0 + lrow) * K) + (tid & 1);
    const uint4* gB = reinterpret_cast<const uint4*>(Be + (long)(n0 + lrow) * K) + (tid & 1);

    int acc[8][8];
#pragma unroll
    for (int i = 0; i < 8; ++i)
#pragma unroll
        for (int j = 0; j < 8; ++j) acc[i][j] = 0;

    uint4 pa = *gA, pb = *gB;
    int nIter = K >> 5;
    for (int it = 0; it < nIter; ++it) {
        As[lw + 0][lrow] = pa.x; As[lw + 1][lrow] = pa.y;
        As[lw + 2][lrow] = pa.z; As[lw + 3][lrow] = pa.w;
        Bs[lw + 0][lrow] = pb.x; Bs[lw + 1][lrow] = pb.y;
        Bs[lw + 2][lrow] = pb.z; Bs[lw + 3][lrow] = pb.w;
        __syncthreads();
        if (it + 1 < nIter) { gA += 2; gB += 2; pa = *gA; pb = *gB; }
#pragma unroll
        for (int kw = 0; kw < 8; ++kw) {
            uint32_t af[8], bf[8];
#pragma unroll
            for (int i = 0; i < 8; ++i) af[i] = As[kw][ty * 8 + i];
#pragma unroll
            for (int j = 0; j < 8; ++j) bf[j] = Bs[kw][tx * 8 + j];
#pragma unroll
            for (int i = 0; i < 8; ++i)
#pragma unroll
                for (int j = 0; j < 8; ++j)
                    acc[i][j] = __dp4a((int)af[i], (int)bf[j], acc[i][j]);
        }
        __syncthreads();
    }

    const float* asc = asc_ + (long)e * M + m0 + ty * 8;
    const float* bsc = bsc_ + (long)e * N + n0 + tx * 8;
    float bs[8];
#pragma unroll
    for (int j = 0; j < 8; ++j) bs[j] = bsc[j];
    float* Ce = Co + (long)e * M * N;
#pragma unroll
    for (int i = 0; i < 8; ++i) {
        float av = asc[i];
        float4 o0, o1;
        o0.x = (float)acc[i][0] * av * bs[0];
        o0.y = (float)acc[i][1] * av * bs[1];
        o0.z = (float)acc[i][2] * av * bs[2];
        o0.w = (float)acc[i][3] * av * bs[3];
        o1.x = (float)acc[i][4] * av * bs[4];
        o1.y = (float)acc[i][5] * av * bs[5];
        o1.z = (float)acc[i][6] * av * bs[6];
        o1.w = (float)acc[i][7] * av * bs[7];
        float4* dst = reinterpret_cast<float4*>(Ce + (long)(m0 + ty * 8 + i) * N + n0 + tx * 8);
        dst[0] = o0;
        dst[1] = o1;
    }
}

// ---------------- SwiGLU + column amax of result -----------------------------
// a[t,i] = silu(h[t,i]) * h[t, I+i]; amax_a[e,i] = max_t |a|
// grid: (I/256, T/128, E), block 256.
__global__ void swiglu_kernel() {
    int e = blockIdx.z;
    int i = blockIdx.x * 256 + threadIdx.x;
    int t0 = blockIdx.y * 128;
    const float* hb = g_h + ((long)e * T_ + t0) * (long)TWOI_ + i;
    float* ab = g_a + ((long)e * T_ + t0) * (long)I_ + i;
    float m = 0.f;
#pragma unroll 4
    for (int t = 0; t < 128; ++t) {
        float gv = hb[(long)t * TWOI_];
        float uv = hb[(long)t * TWOI_ + I_];
        float v = (gv / (1.0f + expf(-gv))) * uv;   // silu(g) * u
        ab[(long)t * I_] = v;
        m = fmaxf(m, fabsf(v));
    }
    atomicMax((unsigned int*)(g_amax_a + e * I_ + i), __float_as_uint(m));
}

// ---------------- launch ------------------------------------------------------
extern "C" void kernel_launch(void* const* d_in, const int* in_sizes, int n_in,
                              void* d_out, int out_size) {
    const float* x   = (const float*)d_in[0];   // [E, T, D]
    const float* guw = (const float*)d_in[1];   // [E, 2I, D]
    const float* dw  = (const float*)d_in[2];   // [E, D, I]
    float* out = (float*)d_out;                 // [E, T, D]

    int8_t *xq1, *wq1, *aq, *wq2;
    float *h, *a, *ax1, *aw1, *aa, *aw2, *s1, *s2, *xs1, *ws1, *xs2, *ws2;
    cudaGetSymbolAddress((void**)&xq1, g_xq1);
    cudaGetSymbolAddress((void**)&wq1, g_wq1);
    cudaGetSymbolAddress((void**)&aq,  g_aq);
    cudaGetSymbolAddress((void**)&wq2, g_wq2);
    cudaGetSymbolAddress((void**)&h,   g_h);
    cudaGetSymbolAddress((void**)&a,   g_a);
    cudaGetSymbolAddress((void**)&ax1, g_amax_x1);
    cudaGetSymbolAddress((void**)&aw1, g_amax_w1);
    cudaGetSymbolAddress((void**)&aa,  g_amax_a);
    cudaGetSymbolAddress((void**)&aw2, g_amax_w2);
    cudaGetSymbolAddress((void**)&s1,  g_s1);
    cudaGetSymbolAddress((void**)&s2,  g_s2);
    cudaGetSymbolAddress((void**)&xs1, g_xs1);
    cudaGetSymbolAddress((void**)&ws1, g_ws1);
    cudaGetSymbolAddress((void**)&xs2, g_xs2);
    cudaGetSymbolAddress((void**)&ws2, g_ws2);

    // zero the atomic-max accumulators (graph replays need fresh state)
    cudaMemsetAsync(ax1, 0, E_ * D_ * sizeof(float));
    cudaMemsetAsync(aw1, 0, E_ * D_ * sizeof(float));
    cudaMemsetAsync(aa,  0, E_ * I_ * sizeof(float));
    cudaMemsetAsync(aw2, 0, E_ * I_ * sizeof(float));

    // column amaxes for smoothing
    colmax_kernel<<<dim3(D_ / 256, T_ / 256, E_), 256>>>(x,   ax1, T_,    D_, 256);
    colmax_kernel<<<dim3(D_ / 256, TWOI_ / 256, E_), 256>>>(guw, aw1, TWOI_, D_, 256);
    colmax_kernel<<<dim3(I_ / 256, D_ / 256, E_), 256>>>(dw,  aw2, D_,    I_, 256);

    // layer 1: smooth, quantize, int8 GEMM, swiglu
    smooth_scale_kernel<<<(E_ * D_ + 255) / 256, 256>>>(ax1, aw1, s1, E_ * D_);
    quant_rows_kernel<1><<<dim3(TWOI_, E_), 256>>>(guw, s1, wq1, ws1, TWOI_, D_);
    quant_rows_kernel<0><<<dim3(T_,    E_), 256>>>(x,   s1, xq1, xs1, T_,    D_);
    gemm_s8_kernel<<<dim3(TWOI_ / 128, T_ / 128, E_), 256>>>(xq1, wq1, h, xs1, ws1,
                                                             T_, TWOI_, D_);
    swiglu_kernel<<<dim3(I_ / 256, T_ / 128, E_), 256>>>();

    // layer 2: smooth, quantize, int8 GEMM -> out
    smooth_scale_kernel<<<(E_ * I_ + 255) / 256, 256>>>(aa, aw2, s2, E_ * I_);
    quant_rows_kernel<1><<<dim3(D_, E_), 256>>>(dw, s2, wq2, ws2, D_, I_);
    quant_rows_kernel<0><<<dim3(T_, E_), 256>>>(a,  s2, aq,  xs2, T_, I_);
    gemm_s8_kernel<<<dim3(D_ / 128, T_ / 128, E_), 256>>>(aq, wq2, out, xs2, ws2,
                                                          T_, D_, I_);
    (void)in_sizes; (void)n_in; (void)out_size;
}

// round 4
// speedup vs baseline: 1.0134x; 1.0134x over previous
#include <cuda_runtime.h>
#include <cstdint>

// Problem shape (fixed by dataset): E=8, T=2048, D=2048, I=1024
#define E_     8
#define T_     2048
#define D_     2048
#define I_     1024
#define TWOI_  2048
#define EPS_   1e-6f
#define QMAX_  127.0f

// ---------------- scratch (static device globals; no allocation) -------------
__device__ __align__(16) int8_t g_xq1[(long)E_ * T_ * D_];
__device__ __align__(16) int8_t g_wq1[(long)E_ * TWOI_ * D_];
__device__ __align__(16) int8_t g_aq [(long)E_ * T_ * I_];
__device__ __align__(16) int8_t g_wq2[(long)E_ * D_ * I_];
__device__ float  g_h  [(long)E_ * T_ * TWOI_];
__device__ float  g_a  [(long)E_ * T_ * I_];
__device__ float  g_amax_x1[E_ * D_];
__device__ float  g_amax_w1[E_ * D_];
__device__ float  g_amax_a [E_ * I_];
__device__ float  g_amax_w2[E_ * I_];
__device__ float  g_s1 [E_ * D_];
__device__ float  g_s2 [E_ * I_];
__device__ float  g_xs1[E_ * T_];
__device__ float  g_ws1[E_ * TWOI_];
__device__ float  g_xs2[E_ * T_];
__device__ float  g_ws2[E_ * D_];

// ---------------- column abs-max over rows ----------------------------------
__global__ void colmax_kernel(const float* __restrict__ M, float* __restrict__ out,
                              int R, int C, int RCH) {
    int c = blockIdx.x * 256 + threadIdx.x;
    int e = blockIdx.z;
    const float* p = M + (long)e * R * C + (long)blockIdx.y * RCH * C + c;
    float m = 0.f;
#pragma unroll 4
    for (int r = 0; r < RCH; ++r)
        m = fmaxf(m, fabsf(p[(long)r * C]));
    atomicMax((unsigned int*)(out + e * C + c), __float_as_uint(m));
}

// ---------------- smooth scale ----------------------------------------------
__global__ void smooth_scale_kernel(const float* __restrict__ ax,
                                    const float* __restrict__ aw,
                                    float* __restrict__ s, int n) {
    int i = blockIdx.x * 256 + threadIdx.x;
    if (i < n) {
        float v = sqrtf(fmaxf(ax[i], EPS_) / fmaxf(aw[i], EPS_));
        s[i] = fmaxf(v, EPS_);
    }
}

// ---------------- per-row quantization --------------------------------------
template <int MUL>
__global__ void quant_rows_kernel(const float* __restrict__ M, const float* __restrict__ s,
                                  int8_t* __restrict__ q, float* __restrict__ rs,
                                  int R, int C) {
    __shared__ float buf[2048];
    __shared__ float red[256];
    int e = blockIdx.y, r = blockIdx.x;
    const float* row = M + ((long)e * R + r) * (long)C;
    const float* sv  = s + (long)e * C;
    float m = 0.f;
    for (int c = threadIdx.x; c < C; c += 256) {
        float v = MUL ? row[c] * sv[c] : row[c] / sv[c];
        buf[c] = v;
        m = fmaxf(m, fabsf(v));
    }
    red[threadIdx.x] = m;
    __syncthreads();
#pragma unroll
    for (int off = 128; off > 0; off >>= 1) {
        if (threadIdx.x < off)
            red[threadIdx.x] = fmaxf(red[threadIdx.x], red[threadIdx.x + off]);
        __syncthreads();
    }
    float scale = fmaxf(red[0], EPS_) * (1.0f / QMAX_);
    if (threadIdx.x == 0) rs[(long)e * R + r] = scale;
    int8_t* qr = q + ((long)e * R + r) * (long)C;
    for (int c = threadIdx.x; c < C; c += 256) {
        float v = rintf(buf[c] / scale);       // round-half-even, matches jnp.round
        v = fminf(fmaxf(v, -QMAX_), QMAX_);
        qr[c] = (int8_t)(int)v;
    }
}

// ---------------- IMMA int8 GEMM --------------------------------------------
// C[m,n] = (sum_k A[m,k]*B[n,k]) * as[m] * bs[n]
// A: [E,M,K] int8 row-major, B: [E,N,K] int8 row-major.
// Block tile 128x128, BK=64 bytes, 256 threads = 8 warps (4 M x 2 N),
// warp tile 32x64 = 2x8 mma.m16n8k32. 2-stage cp.async double buffer.
// Shared layout As[stage][kc][row][16B] with 32B plane pad (row dim 130):
// bank = (8*kc + 4*row) mod 32 -> conflict-free for both cp.async store
// wavefronts and ldmatrix read phases.

__device__ __forceinline__ uint32_t smem_u32(const void* p) {
    return (uint32_t)__cvta_generic_to_shared(p);
}

#define CP16(dst, src) \
    asm volatile("cp.async.cg.shared.global [%0], [%1], 16;\n" :: "r"(dst), "l"(src))

__global__ void __launch_bounds__(256, 2)
gemm_s8_imma(const int8_t* __restrict__ A, const int8_t* __restrict__ B,
             float* __restrict__ Co, const float* __restrict__ asc_,
             const float* __restrict__ bsc_, int M, int N, int K) {
    __shared__ int8_t As[2][4][130][16];
    __shared__ int8_t Bs[2][4][130][16];

    const int e = blockIdx.z;
    const int8_t* Ae = A + (long)e * M * K;
    const int8_t* Be = B + (long)e * N * K;
    const int m0 = blockIdx.y * 128, n0 = blockIdx.x * 128;

    const int tid = threadIdx.x, lane = tid & 31, warp = tid >> 5;
    const int wm = warp & 3;    // 4 warps along M, 32 rows each
    const int wn = warp >> 2;   // 2 warps along N, 64 cols each

    // global->shared mapping: thread loads row lrow (and lrow+64), k-chunk lkc
    const int lrow = tid >> 2;  // 0..63
    const int lkc  = tid & 3;

    const int8_t* ga0 = Ae + (long)(m0 + lrow) * K + lkc * 16;
    const int8_t* ga1 = Ae + (long)(m0 + 64 + lrow) * K + lkc * 16;
    const int8_t* gb0 = Be + (long)(n0 + lrow) * K + lkc * 16;
    const int8_t* gb1 = Be + (long)(n0 + 64 + lrow) * K + lkc * 16;

    int acc[2][8][4];
#pragma unroll
    for (int mi = 0; mi < 2; ++mi)
#pragma unroll
        for (int ni = 0; ni < 8; ++ni)
#pragma unroll
            for (int v = 0; v < 4; ++v) acc[mi][ni][v] = 0;

    auto load_stage = [&](int s, int kb) {
        CP16(smem_u32(&As[s][lkc][lrow][0]),      ga0 + kb);
        CP16(smem_u32(&As[s][lkc][64 + lrow][0]), ga1 + kb);
        CP16(smem_u32(&Bs[s][lkc][lrow][0]),      gb0 + kb);
        CP16(smem_u32(&Bs[s][lkc][64 + lrow][0]), gb1 + kb);
        asm volatile("cp.async.commit_group;\n");
    };

    auto compute_stage = [&](int s) {
        const int tt = lane >> 3;
#pragma unroll
        for (int kc2 = 0; kc2 < 2; ++kc2) {
            uint32_t a[2][4];
#pragma unroll
            for (int mi = 0; mi < 2; ++mi) {
                // tiles: (rows 0-7, kcE) (rows 8-15, kcE) (rows 0-7, kcO) (rows 8-15, kcO)
                int trow = wm * 32 + mi * 16 + ((tt & 1) ? 8 : 0) + (lane & 7);
                int tkc  = kc2 * 2 + (tt >> 1);
                uint32_t ad = smem_u32(&As[s][tkc][trow][0]);
                asm volatile("ldmatrix.sync.aligned.m8n8.x4.shared.b16 {%0,%1,%2,%3}, [%4];"
                    : "=r"(a[mi][0]), "=r"(a[mi][1]), "=r"(a[mi][2]), "=r"(a[mi][3])
                    : "r"(ad));
            }
            uint32_t b[8][2];
#pragma unroll
            for (int p = 0; p < 4; ++p) {
                // tiles: (nP rows 0-7, kcE) (same, kcO) (nP rows 8-15, kcE) (same, kcO)
                int trow = wn * 64 + p * 16 + ((tt >> 1) ? 8 : 0) + (lane & 7);
                int tkc  = kc2 * 2 + (tt & 1);
                uint32_t ad = smem_u32(&Bs[s][tkc][trow][0]);
                asm volatile("ldmatrix.sync.aligned.m8n8.x4.shared.b16 {%0,%1,%2,%3}, [%4];"
                    : "=r"(b[2 * p][0]), "=r"(b[2 * p][1]),
                      "=r"(b[2 * p + 1][0]), "=r"(b[2 * p + 1][1])
                    : "r"(ad));
            }
#pragma unroll
            for (int mi = 0; mi < 2; ++mi)
#pragma unroll
                for (int ni = 0; ni < 8; ++ni)
                    asm volatile(
                        "mma.sync.aligned.m16n8k32.row.col.s32.s8.s8.s32 "
                        "{%0,%1,%2,%3}, {%4,%5,%6,%7}, {%8,%9}, {%0,%1,%2,%3};"
                        : "+r"(acc[mi][ni][0]), "+r"(acc[mi][ni][1]),
                          "+r"(acc[mi][ni][2]), "+r"(acc[mi][ni][3])
                        : "r"(a[mi][0]), "r"(a[mi][1]), "r"(a[mi][2]), "r"(a[mi][3]),
                          "r"(b[ni][0]), "r"(b[ni][1]));
        }
    };

    const int nIter = K >> 6;
    load_stage(0, 0);
    for (int it = 0; it < nIter; ++it) {
        asm volatile("cp.async.wait_group 0;\n");
        __syncthreads();
        if (it + 1 < nIter) load_stage((it + 1) & 1, (it + 1) << 6);
        compute_stage(it & 1);
    }

    // epilogue: dequant + store
    const float* asc = asc_ + (long)e * M + m0 + wm * 32 + (lane >> 2);
    const float* bsc = bsc_ + (long)e * N + n0 + wn * 64 + (lane & 3) * 2;
    float* Ce = Co + (long)e * M * N;
#pragma unroll
    for (int mi = 0; mi < 2; ++mi) {
        int r = wm * 32 + mi * 16 + (lane >> 2);
        float alo = asc[mi * 16];
        float ahi = asc[mi * 16 + 8];
        float* rowlo = Ce + (long)(m0 + r) * N + n0 + wn * 64 + (lane & 3) * 2;
        float* rowhi = rowlo + 8L * N;
#pragma unroll
        for (int ni = 0; ni < 8; ++ni) {
            float b0 = bsc[ni * 8], b1 = bsc[ni * 8 + 1];
            float2 v0 = make_float2((float)acc[mi][ni][0] * alo * b0,
                                    (float)acc[mi][ni][1] * alo * b1);
            float2 v1 = make_float2((float)acc[mi][ni][2] * ahi * b0,
                                    (float)acc[mi][ni][3] * ahi * b1);
            *(float2*)(rowlo + ni * 8) = v0;
            *(float2*)(rowhi + ni * 8) = v1;
        }
    }
}

// ---------------- SwiGLU + column amax of result -----------------------------
__global__ void swiglu_kernel() {
    int e = blockIdx.z;
    int i = blockIdx.x * 256 + threadIdx.x;
    int t0 = blockIdx.y * 128;
    const float* hb = g_h + ((long)e * T_ + t0) * (long)TWOI_ + i;
    float* ab = g_a + ((long)e * T_ + t0) * (long)I_ + i;
    float m = 0.f;
#pragma unroll 4
    for (int t = 0; t < 128; ++t) {
        float gv = hb[(long)t * TWOI_];
        float uv = hb[(long)t * TWOI_ + I_];
        float v = (gv / (1.0f + expf(-gv))) * uv;   // silu(g) * u
        ab[(long)t * I_] = v;
        m = fmaxf(m, fabsf(v));
    }
    atomicMax((unsigned int*)(g_amax_a + e * I_ + i), __float_as_uint(m));
}

// ---------------- launch ------------------------------------------------------
extern "C" void kernel_launch(void* const* d_in, const int* in_sizes, int n_in,
                              void* d_out, int out_size) {
    const float* x   = (const float*)d_in[0];   // [E, T, D]
    const float* guw = (const float*)d_in[1];   // [E, 2I, D]
    const float* dw  = (const float*)d_in[2];   // [E, D, I]
    float* out = (float*)d_out;                 // [E, T, D]

    int8_t *xq1, *wq1, *aq, *wq2;
    float *h, *a, *ax1, *aw1, *aa, *aw2, *s1, *s2, *xs1, *ws1, *xs2, *ws2;
    cudaGetSymbolAddress((void**)&xq1, g_xq1);
    cudaGetSymbolAddress((void**)&wq1, g_wq1);
    cudaGetSymbolAddress((void**)&aq,  g_aq);
    cudaGetSymbolAddress((void**)&wq2, g_wq2);
    cudaGetSymbolAddress((void**)&h,   g_h);
    cudaGetSymbolAddress((void**)&a,   g_a);
    cudaGetSymbolAddress((void**)&ax1, g_amax_x1);
    cudaGetSymbolAddress((void**)&aw1, g_amax_w1);
    cudaGetSymbolAddress((void**)&aa,  g_amax_a);
    cudaGetSymbolAddress((void**)&aw2, g_amax_w2);
    cudaGetSymbolAddress((void**)&s1,  g_s1);
    cudaGetSymbolAddress((void**)&s2,  g_s2);
    cudaGetSymbolAddress((void**)&xs1, g_xs1);
    cudaGetSymbolAddress((void**)&ws1, g_ws1);
    cudaGetSymbolAddress((void**)&xs2, g_xs2);
    cudaGetSymbolAddress((void**)&ws2, g_ws2);

    // zero the atomic-max accumulators (graph replays need fresh state)
    cudaMemsetAsync(ax1, 0, E_ * D_ * sizeof(float));
    cudaMemsetAsync(aw1, 0, E_ * D_ * sizeof(float));
    cudaMemsetAsync(aa,  0, E_ * I_ * sizeof(float));
    cudaMemsetAsync(aw2, 0, E_ * I_ * sizeof(float));

    // column amaxes for smoothing
    colmax_kernel<<<dim3(D_ / 256, T_ / 256, E_), 256>>>(x,   ax1, T_,    D_, 256);
    colmax_kernel<<<dim3(D_ / 256, TWOI_ / 256, E_), 256>>>(guw, aw1, TWOI_, D_, 256);
    colmax_kernel<<<dim3(I_ / 256, D_ / 256, E_), 256>>>(dw,  aw2, D_,    I_, 256);

    // layer 1: smooth, quantize, int8 GEMM, swiglu
    smooth_scale_kernel<<<(E_ * D_ + 255) / 256, 256>>>(ax1, aw1, s1, E_ * D_);
    quant_rows_kernel<1><<<dim3(TWOI_, E_), 256>>>(guw, s1, wq1, ws1, TWOI_, D_);
    quant_rows_kernel<0><<<dim3(T_,    E_), 256>>>(x,   s1, xq1, xs1, T_,    D_);
    gemm_s8_imma<<<dim3(TWOI_ / 128, T_ / 128, E_), 256>>>(xq1, wq1, h, xs1, ws1,
                                                           T_, TWOI_, D_);
    swiglu_kernel<<<dim3(I_ / 256, T_ / 128, E_), 256>>>();

    // layer 2: smooth, quantize, int8 GEMM -> out
    smooth_scale_kernel<<<(E_ * I_ + 255) / 256, 256>>>(aa, aw2, s2, E_ * I_);
    quant_rows_kernel<1><<<dim3(D_, E_), 256>>>(dw, s2, wq2, ws2, D_, I_);
    quant_rows_kernel<0><<<dim3(T_, E_), 256>>>(a,  s2, aq,  xs2, T_, I_);
    gemm_s8_imma<<<dim3(D_ / 128, T_ / 128, E_), 256>>>(aq, wq2, out, xs2, ws2,
                                                        T_, D_, I_);
    (void)in_sizes; (void)n_in; (void)out_size;
}

// round 7
// speedup vs baseline: 1.8907x; 1.8656x over previous
#include <cuda_runtime.h>
#include <cuda_bf16.h>
#include <cstdint>

// Problem shape (fixed by dataset): E=8, T=2048, D=2048, I=1024
#define E_     8
#define T_     2048
#define D_     2048
#define I_     1024
#define TWOI_  2048
#define EPS_   1e-6f
#define QMAX_  127.0f

// tcgen05 exists only in arch-specific passes (sm_103a/sm_100a). Non-suffixed
// passes (compute_103) compile the FMA fallback. NOTE: sm_103a has NO kind::i8
// (ptxas-verified) — we use kind::f16 with bf16-held integers (exact).
#if defined(__CUDA_ARCH__) && defined(__CUDA_ARCH_HAS_FEATURE__)
#  if __CUDA_ARCH_HAS_FEATURE__(SM103_ALL) || __CUDA_ARCH_HAS_FEATURE__(SM100_ALL) || __CUDA_ARCH_HAS_FEATURE__(SM101_ALL)
#    define USE_TC 1
#  endif
#endif
#ifndef USE_TC
#  define USE_TC 0
#endif

// ---------------- scratch (static device globals; no allocation) -------------
// quantized values held as bf16 (integers in [-127,127], exactly representable)
__device__ __align__(16) __nv_bfloat16 g_xq1[(long)E_ * T_ * D_];
__device__ __align__(16) __nv_bfloat16 g_wq1[(long)E_ * TWOI_ * D_];
__device__ __align__(16) __nv_bfloat16 g_aq [(long)E_ * T_ * I_];
__device__ __align__(16) __nv_bfloat16 g_wq2[(long)E_ * D_ * I_];
__device__ float  g_h  [(long)E_ * T_ * TWOI_];
__device__ float  g_a  [(long)E_ * T_ * I_];
__device__ float  g_amax_x1[E_ * D_];
__device__ float  g_amax_w1[E_ * D_];
__device__ float  g_amax_a [E_ * I_];
__device__ float  g_amax_w2[E_ * I_];
__device__ float  g_s1 [E_ * D_];
__device__ float  g_s2 [E_ * I_];
__device__ float  g_xs1[E_ * T_];
__device__ float  g_ws1[E_ * TWOI_];
__device__ float  g_xs2[E_ * T_];
__device__ float  g_ws2[E_ * D_];

// ================= PTX helpers ================================================
__device__ __forceinline__ uint32_t smem_u32(const void* p) {
    return (uint32_t)__cvta_generic_to_shared(p);
}

#if USE_TC
__device__ __forceinline__ uint32_t elect_one_pred() {
    uint32_t pred;
    asm volatile(
        "{\n\t.reg .pred p;\n\t"
        "elect.sync _|p, 0xFFFFFFFF;\n\t"
        "selp.b32 %0, 1, 0, p;\n\t}"
        : "=r"(pred));
    return pred;
}

#define MBARRIER_INIT(addr, count) \
    asm volatile("mbarrier.init.shared.b64 [%0], %1;" :: "r"((uint32_t)(addr)), "r"((uint32_t)(count)) : "memory")

#define MBARRIER_WAIT_PARITY(mbar_smem_addr, phase_parity) do { \
    uint32_t _mbar = (uint32_t)(mbar_smem_addr); \
    uint32_t _parity = (uint32_t)(phase_parity); \
    uint32_t _done; \
    asm volatile( \
        "{\n\t.reg .pred p;\n\t" \
        "mbarrier.try_wait.parity.acquire.cta.shared::cta.b64 p, [%1], %2;\n\t" \
        "selp.b32 %0, 1, 0, p;\n\t}" \
        : "=r"(_done) : "r"(_mbar), "r"(_parity) : "memory"); \
    if (!_done) { \
        asm volatile( \
            "{\n\t.reg .pred P1;\n\t" \
            "WAIT_LOOP_%=:\n\t" \
            "mbarrier.try_wait.parity.acquire.cta.shared::cta.b64 P1, [%0], %1, 0x989680;\n\t" \
            "@P1 bra.uni WAIT_DONE_%=;\n\t" \
            "bra.uni WAIT_LOOP_%=;\n\t" \
            "WAIT_DONE_%=:\n\t}" \
            :: "r"(_mbar), "r"(_parity) : "memory"); \
    } \
} while(0)

#define TCGEN05_ALLOC(smem_result_addr, nCols) \
    asm volatile("tcgen05.alloc.cta_group::1.sync.aligned.shared::cta.b32 [%0], %1;" \
        :: "r"((uint32_t)(smem_result_addr)), "r"((uint32_t)(nCols)) : "memory")
#define TCGEN05_DEALLOC(tmem_addr, nCols) \
    asm volatile("tcgen05.dealloc.cta_group::1.sync.aligned.b32 %0, %1;" \
        :: "r"(tmem_addr), "r"((uint32_t)(nCols)))
#define TCGEN05_RELINQUISH() \
    asm volatile("tcgen05.relinquish_alloc_permit.cta_group::1.sync.aligned;")
#define TCGEN05_COMMIT(mbar_smem_addr) \
    asm volatile("tcgen05.commit.cta_group::1.mbarrier::arrive::one.shared::cluster.b64 [%0];" \
        :: "r"((uint32_t)(mbar_smem_addr)) : "memory")
#define TCGEN05_FENCE_AFTER()  asm volatile("tcgen05.fence::after_thread_sync;" ::: "memory")
#define TCGEN05_FENCE_BEFORE() asm volatile("tcgen05.fence::before_thread_sync;" ::: "memory")
#define TCGEN05_WAIT_LD()      asm volatile("tcgen05.wait::ld.sync.aligned;" ::: "memory")
#define FENCE_PROXY_ASYNC()    asm volatile("fence.proxy.async.shared::cta;" ::: "memory")

#define TCGEN05_LD_32X32B_X32(r, tmem_addr) \
    asm volatile( \
        "tcgen05.ld.sync.aligned.32x32b.x32.b32 " \
        "{%0, %1, %2, %3, %4, %5, %6, %7, " \
        " %8, %9, %10, %11, %12, %13, %14, %15, " \
        " %16, %17, %18, %19, %20, %21, %22, %23, " \
        " %24, %25, %26, %27, %28, %29, %30, %31}, [%32];" \
        : "=r"((r)[0]),  "=r"((r)[1]),  "=r"((r)[2]),  "=r"((r)[3]), \
          "=r"((r)[4]),  "=r"((r)[5]),  "=r"((r)[6]),  "=r"((r)[7]), \
          "=r"((r)[8]),  "=r"((r)[9]),  "=r"((r)[10]), "=r"((r)[11]), \
          "=r"((r)[12]), "=r"((r)[13]), "=r"((r)[14]), "=r"((r)[15]), \
          "=r"((r)[16]), "=r"((r)[17]), "=r"((r)[18]), "=r"((r)[19]), \
          "=r"((r)[20]), "=r"((r)[21]), "=r"((r)[22]), "=r"((r)[23]), \
          "=r"((r)[24]), "=r"((r)[25]), "=r"((r)[26]), "=r"((r)[27]), \
          "=r"((r)[28]), "=r"((r)[29]), "=r"((r)[30]), "=r"((r)[31]) \
        : "r"(tmem_addr))

// SW128 descriptor (Blackwell, LBO=1, SBO=64; rows are 128 bytes)
static constexpr uint64_t SMEM_DESC_BASE_SW128 =
    (uint64_t(2)  << 61) | (uint64_t(1) << 46) | (uint64_t(64) << 32) | (uint64_t(1) << 16);
#define MAKE_SMEM_DESC(base_addr) \
    (SMEM_DESC_BASE_SW128 | ((uint64_t)((base_addr) >> 4) & 0x3FFF))

// tcgen05 f16 SS MMA (bf16 x bf16 -> f32 TMEM), K=16 per call, cta_group::1
__device__ __forceinline__ void tcgen05_mma_f16_ss(
    uint32_t d_tmem, uint64_t a_desc, uint64_t b_desc, uint32_t idesc, bool accum) {
    uint32_t en = accum ? 1u : 0u;
    asm volatile(
        "{\n\t.reg .pred p;\n\t"
        "setp.ne.u32 p, %5, 0;\n\t"
        "tcgen05.mma.cta_group::1.kind::f16 [%0], %1, %2, %3, {%4, %4, %4, %4}, p;\n\t"
        "}"
        :: "r"(d_tmem), "l"(a_desc), "l"(b_desc), "r"(idesc), "r"(0u), "r"(en)
        : "memory");
}

// idesc (kind::f16): dtype=F32(1)<<4, atype=BF16(1)<<7, btype=BF16(1)<<10,
// N/8<<17, M/16<<24.  (Validated: test_mma.cu idesc 0x8080490 == this formula
// at M=128,N=32; test_2cta_mma_bf16 at M=256,N=64.)
static constexpr uint32_t IDESC_BF16 =
    (1u << 4) | (1u << 7) | (1u << 10) | ((128u / 8) << 17) | ((128u / 16) << 24);
#endif  // USE_TC

#define CP16(dst, src) \
    asm volatile("cp.async.cg.shared.global [%0], [%1], 16;\n" :: "r"(dst), "l"(src))

// ---------------- column abs-max over rows ----------------------------------
__global__ void colmax_kernel(const float* __restrict__ M, float* __restrict__ out,
                              int R, int C, int RCH) {
    int c = blockIdx.x * 256 + threadIdx.x;
    int e = blockIdx.z;
    const float* p = M + (long)e * R * C + (long)blockIdx.y * RCH * C + c;
    float m = 0.f;
#pragma unroll 4
    for (int r = 0; r < RCH; ++r)
        m = fmaxf(m, fabsf(p[(long)r * C]));
    atomicMax((unsigned int*)(out + e * C + c), __float_as_uint(m));
}

// ---------------- smooth scale ----------------------------------------------
__global__ void smooth_scale_kernel(const float* __restrict__ ax,
                                    const float* __restrict__ aw,
                                    float* __restrict__ s, int n) {
    int i = blockIdx.x * 256 + threadIdx.x;
    if (i < n) {
        float v = sqrtf(fmaxf(ax[i], EPS_) / fmaxf(aw[i], EPS_));
        s[i] = fmaxf(v, EPS_);
    }
}

// ---------------- fused per-row quantization (weights + activations) ---------
// Outputs quantized integer values stored as bf16 (exact for |v| <= 127).
__global__ void quant_fused_kernel(const float* __restrict__ W, const float* __restrict__ X,
                                   const float* __restrict__ s,
                                   __nv_bfloat16* __restrict__ qw, __nv_bfloat16* __restrict__ qx,
                                   float* __restrict__ rsw, float* __restrict__ rsx,
                                   int Rw, int Rx, int C) {
    __shared__ float buf[2048];
    __shared__ float red[256];
    int e = blockIdx.y;
    int bx = blockIdx.x;
    int mul = (bx < Rw);
    int r = mul ? bx : bx - Rw;
    int R = mul ? Rw : Rx;
    const float* row = (mul ? W : X) + ((long)e * R + r) * (long)C;
    const float* sv  = s + (long)e * C;
    float m = 0.f;
    for (int c = threadIdx.x; c < C; c += 256) {
        float v = mul ? row[c] * sv[c] : row[c] / sv[c];
        buf[c] = v;
        m = fmaxf(m, fabsf(v));
    }
    red[threadIdx.x] = m;
    __syncthreads();
#pragma unroll
    for (int off = 128; off > 0; off >>= 1) {
        if (threadIdx.x < off)
            red[threadIdx.x] = fmaxf(red[threadIdx.x], red[threadIdx.x + off]);
        __syncthreads();
    }
    float scale = fmaxf(red[0], EPS_) * (1.0f / QMAX_);
    if (threadIdx.x == 0) (mul ? rsw : rsx)[(long)e * R + r] = scale;
    __nv_bfloat16* qr = (mul ? qw : qx) + ((long)e * R + r) * (long)C;
    for (int c = threadIdx.x; c < C; c += 256) {
        float v = rintf(buf[c] / scale);       // round-half-even, matches jnp.round
        v = fminf(fmaxf(v, -QMAX_), QMAX_);
        qr[c] = __float2bfloat16_rn(v);        // exact: integer <= 127
    }
}

// ---------------- bf16-int GEMM (tcgen05 f16 path + FMA fallback) ------------
// C[m,n] = (sum_k A[m,k]*B[n,k]) * as[m] * bs[n]
// A: [E,M,K] bf16 K-major, B: [E,N,K] bf16 K-major. CTA tile 128x128.
// Chunk = 64 K-elements (128 bytes/row); per chunk 4x kind::f16 MMA (K=16).
#define GSTAGES 4
#define STAGE_BYTES 32768     // A tile 16KB + B tile 16KB (128 rows x 128B)
#define GSMEM_BYTES (GSTAGES * STAGE_BYTES + 1024)

__global__ void __launch_bounds__(256, 1)
gemm_bf16_tc(const __nv_bfloat16* __restrict__ A, const __nv_bfloat16* __restrict__ B,
             float* __restrict__ Co, const float* __restrict__ asc_,
             const float* __restrict__ bsc_, int M, int N, int K) {
    extern __shared__ int8_t dynraw[];
#if USE_TC
    __shared__ __align__(16) uint64_t mbar_store[GSTAGES];
    __shared__ uint32_t tmem_addr_sh;

    const uint32_t sbase = (smem_u32(dynraw) + 1023u) & ~1023u;
    const uint32_t mbar0 = smem_u32(&mbar_store[0]);
    const int tid = threadIdx.x;
    const int wid = tid >> 5;
    const int lane = tid & 31;

    const int e = blockIdx.z;
    const int m0 = blockIdx.y * 128, n0 = blockIdx.x * 128;
    const long Kb = (long)K * 2;   // row stride in bytes
    const int8_t* Ae = (const int8_t*)(A + (long)e * M * K + (long)m0 * K);
    const int8_t* Be = (const int8_t*)(B + (long)e * N * K + (long)n0 * K);

    if (wid == 0) {
        TCGEN05_ALLOC(smem_u32(&tmem_addr_sh), 512);
        TCGEN05_RELINQUISH();
    }
    if (tid == 0) {
#pragma unroll
        for (int s = 0; s < GSTAGES; ++s) MBARRIER_INIT(mbar0 + 8 * s, 1);
    }
    __syncthreads();
    const uint32_t tmem = tmem_addr_sh;

    const int nchunks = K >> 6;   // 64 K-elements (=128 bytes) per chunk

    // per stage, each thread loads 4 A + 4 B 16B quads (SW128 swizzled)
    auto load_chunk = [&](int j) {
        uint32_t abase = sbase + (uint32_t)(j & (GSTAGES - 1)) * STAGE_BYTES;
        uint32_t bbase = abase + 16384;
        long koffb = (long)j << 7;   // 128 bytes per chunk
#pragma unroll
        for (int q = 0; q < 4; ++q) {
            int idx = tid * 4 + q;
            int row = idx >> 3, c16 = idx & 7;
            uint32_t off = (uint32_t)(row * 128 + c16 * 16);
            uint32_t sw = off ^ ((off >> 3) & 0x70);
            CP16(abase + sw, Ae + (long)row * Kb + koffb + c16 * 16);
            CP16(bbase + sw, Be + (long)row * Kb + koffb + c16 * 16);
        }
        asm volatile("cp.async.commit_group;\n");
    };

    for (int j = 0; j < GSTAGES - 1 && j < nchunks; ++j) load_chunk(j);

    for (int it = 0; it < nchunks; ++it) {
        if (it + GSTAGES - 1 <= nchunks)
            asm volatile("cp.async.wait_group %0;\n" :: "n"(GSTAGES - 2));
        else
            asm volatile("cp.async.wait_group 0;\n");
        __syncthreads();

        if (wid == 0 && elect_one_pred()) {
            FENCE_PROXY_ASYNC();   // order cp.async writes vs async-proxy MMA reads
            uint32_t st = (uint32_t)(it & (GSTAGES - 1));
            uint64_t ad = MAKE_SMEM_DESC(sbase + st * STAGE_BYTES);
            uint64_t bd = MAKE_SMEM_DESC(sbase + st * STAGE_BYTES + 16384);
#pragma unroll
            for (int ks = 0; ks < 4; ++ks)   // 4 x K=16; +2 desc units = +32B
                tcgen05_mma_f16_ss(tmem, ad + ks * 2, bd + ks * 2, IDESC_BF16,
                                   (it > 0) || (ks > 0));
            TCGEN05_COMMIT(mbar0 + 8 * st);
        }

        int j = it + GSTAGES - 1;
        if (j < nchunks) {
            if (j >= GSTAGES)
                MBARRIER_WAIT_PARITY(mbar0 + 8 * (j & (GSTAGES - 1)),
                                     ((j / GSTAGES) - 1) & 1);
            load_chunk(j);
        }
    }

    MBARRIER_WAIT_PARITY(mbar0 + 8 * ((nchunks - 1) & (GSTAGES - 1)),
                         ((nchunks - 1) / GSTAGES) & 1);
    TCGEN05_FENCE_AFTER();

    // epilogue: warps 0-3 cols 0-63, warps 4-7 cols 64-127; rows by (wid&3)
    {
        int colb = (wid >> 2) * 64;
        uint32_t d0[32], d1[32];
        TCGEN05_LD_32X32B_X32(d0, tmem + colb);
        TCGEN05_LD_32X32B_X32(d1, tmem + colb + 32);
        TCGEN05_WAIT_LD();
        TCGEN05_FENCE_BEFORE();

        int row = (wid & 3) * 32 + lane;
        float as = asc_[(long)e * M + m0 + row];
        const float* bs = bsc_ + (long)e * N + n0 + colb;
        float* dst = Co + (long)e * M * N + (long)(m0 + row) * N + n0 + colb;
#pragma unroll
        for (int c = 0; c < 32; c += 4) {
            float4 v;
            v.x = __uint_as_float(d0[c + 0]) * as * bs[c + 0];
            v.y = __uint_as_float(d0[c + 1]) * as * bs[c + 1];
            v.z = __uint_as_float(d0[c + 2]) * as * bs[c + 2];
            v.w = __uint_as_float(d0[c + 3]) * as * bs[c + 3];
            *(float4*)(dst + c) = v;
        }
#pragma unroll
        for (int c = 0; c < 32; c += 4) {
            float4 v;
            v.x = __uint_as_float(d1[c + 0]) * as * bs[32 + c + 0];
            v.y = __uint_as_float(d1[c + 1]) * as * bs[32 + c + 1];
            v.z = __uint_as_float(d1[c + 2]) * as * bs[32 + c + 2];
            v.w = __uint_as_float(d1[c + 3]) * as * bs[32 + c + 3];
            *(float4*)(dst + 32 + c) = v;
        }
    }
    __syncthreads();
    if (wid == 0) {
        TCGEN05_DEALLOC(tmem, 512);
    }
#else
    // ---------- FMA fallback (non-'a' pass; not selected by the sm_103a driver)
    uint32_t* As = reinterpret_cast<uint32_t*>(dynraw);  // [8][128] bf16x2 words
    uint32_t* Bs = As + 1024;

    int e = blockIdx.z;
    const int8_t* Ae = (const int8_t*)(A + (long)e * M * K);
    const int8_t* Be = (const int8_t*)(B + (long)e * N * K);
    const long Kb = (long)K * 2;

    int tid = threadIdx.x;
    int tx = tid & 15, ty = tid >> 4;
    int m0 = blockIdx.y * 128, n0 = blockIdx.x * 128;

    int lrow = tid >> 1;
    int lw   = (tid & 1) * 4;

    float acc[8][8];
#pragma unroll
    for (int i = 0; i < 8; ++i)
#pragma unroll
        for (int j = 0; j < 8; ++j) acc[i][j] = 0.f;

    int nIter = (int)(Kb >> 5);   // 32 bytes (16 bf16) of K per iter
    for (int it = 0; it < nIter; ++it) {
        const uint4* gA = reinterpret_cast<const uint4*>(Ae + (long)(m0 + lrow) * Kb + it * 32) + (tid & 1);
        const uint4* gB = reinterpret_cast<const uint4*>(Be + (long)(n0 + lrow) * Kb + it * 32) + (tid & 1);
        uint4 pa = *gA, pb = *gB;
        As[(lw + 0) * 128 + lrow] = pa.x; As[(lw + 1) * 128 + lrow] = pa.y;
        As[(lw + 2) * 128 + lrow] = pa.z; As[(lw + 3) * 128 + lrow] = pa.w;
        Bs[(lw + 0) * 128 + lrow] = pb.x; Bs[(lw + 1) * 128 + lrow] = pb.y;
        Bs[(lw + 2) * 128 + lrow] = pb.z; Bs[(lw + 3) * 128 + lrow] = pb.w;
        __syncthreads();
#pragma unroll
        for (int kw = 0; kw < 8; ++kw) {
            float2 af[8], bf[8];
#pragma unroll
            for (int i = 0; i < 8; ++i)
                af[i] = __bfloat1622float2(*(const __nv_bfloat162*)&As[kw * 128 + ty * 8 + i]);
#pragma unroll
            for (int j = 0; j < 8; ++j)
                bf[j] = __bfloat1622float2(*(const __nv_bfloat162*)&Bs[kw * 128 + tx * 8 + j]);
#pragma unroll
            for (int i = 0; i < 8; ++i)
#pragma unroll
                for (int j = 0; j < 8; ++j)
                    acc[i][j] = fmaf(af[i].y, bf[j].y, fmaf(af[i].x, bf[j].x, acc[i][j]));
        }
        __syncthreads();
    }

    const float* asc = asc_ + (long)e * M + m0 + ty * 8;
    const float* bsc = bsc_ + (long)e * N + n0 + tx * 8;
    float bsv[8];
#pragma unroll
    for (int j = 0; j < 8; ++j) bsv[j] = bsc[j];
    float* Ce = Co + (long)e * M * N;
#pragma unroll
    for (int i = 0; i < 8; ++i) {
        float av = asc[i];
        float4 o0, o1;
        o0.x = acc[i][0] * av * bsv[0];
        o0.y = acc[i][1] * av * bsv[1];
        o0.z = acc[i][2] * av * bsv[2];
        o0.w = acc[i][3] * av * bsv[3];
        o1.x = acc[i][4] * av * bsv[4];
        o1.y = acc[i][5] * av * bsv[5];
        o1.z = acc[i][6] * av * bsv[6];
        o1.w = acc[i][7] * av * bsv[7];
        float4* dst = reinterpret_cast<float4*>(Ce + (long)(m0 + ty * 8 + i) * N + n0 + tx * 8);
        dst[0] = o0;
        dst[1] = o1;
    }
#endif
}

// ---------------- SwiGLU + column amax of result -----------------------------
__global__ void swiglu_kernel() {
    int e = blockIdx.z;
    int i = blockIdx.x * 256 + threadIdx.x;
    int t0 = blockIdx.y * 128;
    const float* hb = g_h + ((long)e * T_ + t0) * (long)TWOI_ + i;
    float* ab = g_a + ((long)e * T_ + t0) * (long)I_ + i;
    float m = 0.f;
#pragma unroll 4
    for (int t = 0; t < 128; ++t) {
        float gv = hb[(long)t * TWOI_];
        float uv = hb[(long)t * TWOI_ + I_];
        float v = (gv / (1.0f + expf(-gv))) * uv;   // silu(g) * u
        ab[(long)t * I_] = v;
        m = fmaxf(m, fabsf(v));
    }
    atomicMax((unsigned int*)(g_amax_a + e * I_ + i), __float_as_uint(m));
}

// ---------------- cleanup: zero atomic-max buffers for the next replay -------
__global__ void cleanup_kernel() {
    int i = blockIdx.x * 256 + threadIdx.x;
    if (i < E_ * D_) { g_amax_x1[i] = 0.f; g_amax_w1[i] = 0.f; }
    if (i < E_ * I_) { g_amax_a[i] = 0.f; g_amax_w2[i] = 0.f; }
}

// ---------------- launch ------------------------------------------------------
extern "C" void kernel_launch(void* const* d_in, const int* in_sizes, int n_in,
                              void* d_out, int out_size) {
    const float* x   = (const float*)d_in[0];   // [E, T, D]
    const float* guw = (const float*)d_in[1];   // [E, 2I, D]
    const float* dw  = (const float*)d_in[2];   // [E, D, I]
    float* out = (float*)d_out;                 // [E, T, D]

    __nv_bfloat16 *xq1, *wq1, *aq, *wq2;
    float *h, *a, *ax1, *aw1, *aa, *aw2, *s1, *s2, *xs1, *ws1, *xs2, *ws2;
    cudaGetSymbolAddress((void**)&xq1, g_xq1);
    cudaGetSymbolAddress((void**)&wq1, g_wq1);
    cudaGetSymbolAddress((void**)&aq,  g_aq);
    cudaGetSymbolAddress((void**)&wq2, g_wq2);
    cudaGetSymbolAddress((void**)&h,   g_h);
    cudaGetSymbolAddress((void**)&a,   g_a);
    cudaGetSymbolAddress((void**)&ax1, g_amax_x1);
    cudaGetSymbolAddress((void**)&aw1, g_amax_w1);
    cudaGetSymbolAddress((void**)&aa,  g_amax_a);
    cudaGetSymbolAddress((void**)&aw2, g_amax_w2);
    cudaGetSymbolAddress((void**)&s1,  g_s1);
    cudaGetSymbolAddress((void**)&s2,  g_s2);
    cudaGetSymbolAddress((void**)&xs1, g_xs1);
    cudaGetSymbolAddress((void**)&ws1, g_ws1);
    cudaGetSymbolAddress((void**)&xs2, g_xs2);
    cudaGetSymbolAddress((void**)&ws2, g_ws2);

    cudaFuncSetAttribute(gemm_bf16_tc, cudaFuncAttributeMaxDynamicSharedMemorySize,
                         GSMEM_BYTES);

    // column amaxes for smoothing
    colmax_kernel<<<dim3(D_ / 256, T_ / 256, E_), 256>>>(x,   ax1, T_,    D_, 256);
    colmax_kernel<<<dim3(D_ / 256, TWOI_ / 256, E_), 256>>>(guw, aw1, TWOI_, D_, 256);
    colmax_kernel<<<dim3(I_ / 256, D_ / 256, E_), 256>>>(dw,  aw2, D_,    I_, 256);

    // layer 1
    smooth_scale_kernel<<<(E_ * D_ + 255) / 256, 256>>>(ax1, aw1, s1, E_ * D_);
    quant_fused_kernel<<<dim3(TWOI_ + T_, E_), 256>>>(guw, x, s1, wq1, xq1, ws1, xs1,
                                                      TWOI_, T_, D_);
    gemm_bf16_tc<<<dim3(TWOI_ / 128, T_ / 128, E_), 256, GSMEM_BYTES>>>(xq1, wq1, h, xs1, ws1,
                                                                        T_, TWOI_, D_);
    swiglu_kernel<<<dim3(I_ / 256, T_ / 128, E_), 256>>>();

    // layer 2
    smooth_scale_kernel<<<(E_ * I_ + 255) / 256, 256>>>(aa, aw2, s2, E_ * I_);
    quant_fused_kernel<<<dim3(D_ + T_, E_), 256>>>(dw, a, s2, wq2, aq, ws2, xs2,
                                                   D_, T_, I_);
    gemm_bf16_tc<<<dim3(D_ / 128, T_ / 128, E_), 256, GSMEM_BYTES>>>(aq, wq2, out, xs2, ws2,
                                                                     T_, D_, I_);
    // reset accumulators for next graph replay
    cleanup_kernel<<<(E_ * D_ + 255) / 256, 256>>>();

    (void)in_sizes; (void)n_in; (void)out_size;
}

// round 8
// speedup vs baseline: 2.2037x; 1.1655x over previous
#include <cuda_runtime.h>
#include <cuda_bf16.h>
#include <cstdint>

// Problem shape (fixed by dataset): E=8, T=2048, D=2048, I=1024
#define E_     8
#define T_     2048
#define D_     2048
#define I_     1024
#define TWOI_  2048
#define EPS_   1e-6f
#define QMAX_  127.0f

// tcgen05 exists only in arch-specific passes (sm_103a/sm_100a). Non-suffixed
// passes (compute_103) compile the fallback. sm_103a has NO kind::i8
// (ptxas-verified R6) — we use kind::f16 with bf16-held integers (exact).
#if defined(__CUDA_ARCH__) && defined(__CUDA_ARCH_HAS_FEATURE__)
#  if __CUDA_ARCH_HAS_FEATURE__(SM103_ALL) || __CUDA_ARCH_HAS_FEATURE__(SM100_ALL) || __CUDA_ARCH_HAS_FEATURE__(SM101_ALL)
#    define USE_TC 1
#  endif
#endif
#ifndef USE_TC
#  define USE_TC 0
#endif

// ---------------- scratch (static device globals; no allocation) -------------
__device__ __align__(16) __nv_bfloat16 g_xq1[(long)E_ * T_ * D_];
__device__ __align__(16) __nv_bfloat16 g_wq1[(long)E_ * TWOI_ * D_];
__device__ __align__(16) __nv_bfloat16 g_aq [(long)E_ * T_ * I_];
__device__ __align__(16) __nv_bfloat16 g_wq2[(long)E_ * D_ * I_];
__device__ float  g_a  [(long)E_ * T_ * I_];
__device__ float  g_amax_x1[E_ * D_];
__device__ float  g_amax_w1[E_ * D_];
__device__ float  g_amax_a [E_ * I_];
__device__ float  g_amax_w2[E_ * I_];
__device__ float  g_s1 [E_ * D_];
__device__ float  g_s2 [E_ * I_];
__device__ float  g_xs1[E_ * T_];
__device__ float  g_ws1[E_ * TWOI_];
__device__ float  g_xs2[E_ * T_];
__device__ float  g_ws2[E_ * D_];

// ================= PTX helpers ================================================
__device__ __forceinline__ uint32_t smem_u32(const void* p) {
    return (uint32_t)__cvta_generic_to_shared(p);
}

#if USE_TC
__device__ __forceinline__ uint32_t elect_one_pred() {
    uint32_t pred;
    asm volatile(
        "{\n\t.reg .pred p;\n\t"
        "elect.sync _|p, 0xFFFFFFFF;\n\t"
        "selp.b32 %0, 1, 0, p;\n\t}"
        : "=r"(pred));
    return pred;
}

#define MBARRIER_INIT(addr, count) \
    asm volatile("mbarrier.init.shared.b64 [%0], %1;" :: "r"((uint32_t)(addr)), "r"((uint32_t)(count)) : "memory")

#define MBARRIER_WAIT_PARITY(mbar_smem_addr, phase_parity) do { \
    uint32_t _mbar = (uint32_t)(mbar_smem_addr); \
    uint32_t _parity = (uint32_t)(phase_parity); \
    uint32_t _done; \
    asm volatile( \
        "{\n\t.reg .pred p;\n\t" \
        "mbarrier.try_wait.parity.acquire.cta.shared::cta.b64 p, [%1], %2;\n\t" \
        "selp.b32 %0, 1, 0, p;\n\t}" \
        : "=r"(_done) : "r"(_mbar), "r"(_parity) : "memory"); \
    if (!_done) { \
        asm volatile( \
            "{\n\t.reg .pred P1;\n\t" \
            "WAIT_LOOP_%=:\n\t" \
            "mbarrier.try_wait.parity.acquire.cta.shared::cta.b64 P1, [%0], %1, 0x989680;\n\t" \
            "@P1 bra.uni WAIT_DONE_%=;\n\t" \
            "bra.uni WAIT_LOOP_%=;\n\t" \
            "WAIT_DONE_%=:\n\t}" \
            :: "r"(_mbar), "r"(_parity) : "memory"); \
    } \
} while(0)

#define TCGEN05_ALLOC(smem_result_addr, nCols) \
    asm volatile("tcgen05.alloc.cta_group::1.sync.aligned.shared::cta.b32 [%0], %1;" \
        :: "r"((uint32_t)(smem_result_addr)), "r"((uint32_t)(nCols)) : "memory")
#define TCGEN05_DEALLOC(tmem_addr, nCols) \
    asm volatile("tcgen05.dealloc.cta_group::1.sync.aligned.b32 %0, %1;" \
        :: "r"(tmem_addr), "r"((uint32_t)(nCols)))
#define TCGEN05_RELINQUISH() \
    asm volatile("tcgen05.relinquish_alloc_permit.cta_group::1.sync.aligned;")
#define TCGEN05_COMMIT(mbar_smem_addr) \
    asm volatile("tcgen05.commit.cta_group::1.mbarrier::arrive::one.shared::cluster.b64 [%0];" \
        :: "r"((uint32_t)(mbar_smem_addr)) : "memory")
#define TCGEN05_FENCE_AFTER()  asm volatile("tcgen05.fence::after_thread_sync;" ::: "memory")
#define TCGEN05_FENCE_BEFORE() asm volatile("tcgen05.fence::before_thread_sync;" ::: "memory")
#define TCGEN05_WAIT_LD()      asm volatile("tcgen05.wait::ld.sync.aligned;" ::: "memory")
#define FENCE_PROXY_ASYNC()    asm volatile("fence.proxy.async.shared::cta;" ::: "memory")

#define TCGEN05_LD_32X32B_X32(r, tmem_addr) \
    asm volatile( \
        "tcgen05.ld.sync.aligned.32x32b.x32.b32 " \
        "{%0, %1, %2, %3, %4, %5, %6, %7, " \
        " %8, %9, %10, %11, %12, %13, %14, %15, " \
        " %16, %17, %18, %19, %20, %21, %22, %23, " \
        " %24, %25, %26, %27, %28, %29, %30, %31}, [%32];" \
        : "=r"((r)[0]),  "=r"((r)[1]),  "=r"((r)[2]),  "=r"((r)[3]), \
          "=r"((r)[4]),  "=r"((r)[5]),  "=r"((r)[6]),  "=r"((r)[7]), \
          "=r"((r)[8]),  "=r"((r)[9]),  "=r"((r)[10]), "=r"((r)[11]), \
          "=r"((r)[12]), "=r"((r)[13]), "=r"((r)[14]), "=r"((r)[15]), \
          "=r"((r)[16]), "=r"((r)[17]), "=r"((r)[18]), "=r"((r)[19]), \
          "=r"((r)[20]), "=r"((r)[21]), "=r"((r)[22]), "=r"((r)[23]), \
          "=r"((r)[24]), "=r"((r)[25]), "=r"((r)[26]), "=r"((r)[27]), \
          "=r"((r)[28]), "=r"((r)[29]), "=r"((r)[30]), "=r"((r)[31]) \
        : "r"(tmem_addr))

// SW128 descriptor (Blackwell, LBO=1, SBO=64; rows are 128 bytes)
static constexpr uint64_t SMEM_DESC_BASE_SW128 =
    (uint64_t(2)  << 61) | (uint64_t(1) << 46) | (uint64_t(64) << 32) | (uint64_t(1) << 16);
#define MAKE_SMEM_DESC(base_addr) \
    (SMEM_DESC_BASE_SW128 | ((uint64_t)((base_addr) >> 4) & 0x3FFF))

// tcgen05 f16 SS MMA (bf16 x bf16 -> f32 TMEM), K=16 per call, cta_group::1
__device__ __forceinline__ void tcgen05_mma_f16_ss(
    uint32_t d_tmem, uint64_t a_desc, uint64_t b_desc, uint32_t idesc, bool accum) {
    uint32_t en = accum ? 1u : 0u;
    asm volatile(
        "{\n\t.reg .pred p;\n\t"
        "setp.ne.u32 p, %5, 0;\n\t"
        "tcgen05.mma.cta_group::1.kind::f16 [%0], %1, %2, %3, {%4, %4, %4, %4}, p;\n\t"
        "}"
        :: "r"(d_tmem), "l"(a_desc), "l"(b_desc), "r"(idesc), "r"(0u), "r"(en)
        : "memory");
}

// idesc (kind::f16): dtype=F32(1)<<4, atype=BF16(1)<<7, btype=BF16(1)<<10,
// N/8<<17, M/16<<24.  (Validated vs test_mma.cu 0x8080490, test_2cta_mma_bf16.)
static constexpr uint32_t IDESC_BF16 =
    (1u << 4) | (1u << 7) | (1u << 10) | ((128u / 8) << 17) | ((128u / 16) << 24);
#endif  // USE_TC

#define CP16(dst, src) \
    asm volatile("cp.async.cg.shared.global [%0], [%1], 16;\n" :: "r"(dst), "l"(src))

// ---------------- column abs-max over rows ----------------------------------
__global__ void colmax_kernel(const float* __restrict__ M, float* __restrict__ out,
                              int R, int C, int RCH) {
    int c = blockIdx.x * 256 + threadIdx.x;
    int e = blockIdx.z;
    const float* p = M + (long)e * R * C + (long)blockIdx.y * RCH * C + c;
    float m = 0.f;
#pragma unroll 4
    for (int r = 0; r < RCH; ++r)
        m = fmaxf(m, fabsf(p[(long)r * C]));
    atomicMax((unsigned int*)(out + e * C + c), __float_as_uint(m));
}

// ---------------- smooth scale ----------------------------------------------
__global__ void smooth_scale_kernel(const float* __restrict__ ax,
                                    const float* __restrict__ aw,
                                    float* __restrict__ s, int n) {
    int i = blockIdx.x * 256 + threadIdx.x;
    if (i < n) {
        float v = sqrtf(fmaxf(ax[i], EPS_) / fmaxf(aw[i], EPS_));
        s[i] = fmaxf(v, EPS_);
    }
}

// ---------------- fused per-row quantization (weights + activations) ---------
__global__ void quant_fused_kernel(const float* __restrict__ W, const float* __restrict__ X,
                                   const float* __restrict__ s,
                                   __nv_bfloat16* __restrict__ qw, __nv_bfloat16* __restrict__ qx,
                                   float* __restrict__ rsw, float* __restrict__ rsx,
                                   int Rw, int Rx, int C) {
    __shared__ float buf[2048];
    __shared__ float red[256];
    int e = blockIdx.y;
    int bx = blockIdx.x;
    int mul = (bx < Rw);
    int r = mul ? bx : bx - Rw;
    int R = mul ? Rw : Rx;
    const float* row = (mul ? W : X) + ((long)e * R + r) * (long)C;
    const float* sv  = s + (long)e * C;
    float m = 0.f;
    for (int c = threadIdx.x; c < C; c += 256) {
        float v = mul ? row[c] * sv[c] : row[c] / sv[c];
        buf[c] = v;
        m = fmaxf(m, fabsf(v));
    }
    red[threadIdx.x] = m;
    __syncthreads();
#pragma unroll
    for (int off = 128; off > 0; off >>= 1) {
        if (threadIdx.x < off)
            red[threadIdx.x] = fmaxf(red[threadIdx.x], red[threadIdx.x + off]);
        __syncthreads();
    }
    float scale = fmaxf(red[0], EPS_) * (1.0f / QMAX_);
    if (threadIdx.x == 0) (mul ? rsw : rsx)[(long)e * R + r] = scale;
    __nv_bfloat16* qr = (mul ? qw : qx) + ((long)e * R + r) * (long)C;
    for (int c = threadIdx.x; c < C; c += 256) {
        float v = rintf(buf[c] / scale);       // round-half-even, matches jnp.round
        v = fminf(fmaxf(v, -QMAX_), QMAX_);
        qr[c] = __float2bfloat16_rn(v);        // exact: integer <= 127
    }
}

// ---------------- GEMM1 + SwiGLU fused (tcgen05) ------------------------------
// For each n0-tile (128 of I): gate = X @ Wg^T (Wg rows n0..), up = X @ Wu^T
// (Wu rows n0+I..). Epilogue: a = silu(gate*scales)*(up*scales), written to
// g_a, plus column-amax of a accumulated to g_amax_a.
// Stage = A 16KB + Bg 16KB + Bu 16KB = 48KB. 4 stages. TMEM: gate cols 0-127,
// up cols 128-255.
#define FSTAGES 4
#define FSTAGE_BYTES (3 * 16384)
#define FSMEM_BYTES (FSTAGES * FSTAGE_BYTES + 1024)

__global__ void __launch_bounds__(256, 1)
gemm1_swiglu_tc(const __nv_bfloat16* __restrict__ A, const __nv_bfloat16* __restrict__ B,
                const float* __restrict__ asc_, const float* __restrict__ bsc_) {
    extern __shared__ int8_t dynraw[];
    const int tid = threadIdx.x;
    const int e = blockIdx.z;
    const int m0 = blockIdx.y * 128, n0 = blockIdx.x * 128;
#if USE_TC
    __shared__ __align__(16) uint64_t mbar_store[FSTAGES];
    __shared__ uint32_t tmem_addr_sh;
    __shared__ float cmax[128];

    const uint32_t sbase = (smem_u32(dynraw) + 1023u) & ~1023u;
    const uint32_t mbar0 = smem_u32(&mbar_store[0]);
    const int wid = tid >> 5;
    const int lane = tid & 31;

    const long Kb = (long)D_ * 2;
    const int8_t* Ae = (const int8_t*)(A + (long)e * T_ * D_ + (long)m0 * D_);
    const int8_t* Bg = (const int8_t*)(B + (long)e * TWOI_ * D_ + (long)n0 * D_);
    const int8_t* Bu = (const int8_t*)(B + (long)e * TWOI_ * D_ + (long)(n0 + I_) * D_);

    if (wid == 0) {
        TCGEN05_ALLOC(smem_u32(&tmem_addr_sh), 512);
        TCGEN05_RELINQUISH();
    }
    if (tid == 0) {
#pragma unroll
        for (int s = 0; s < FSTAGES; ++s) MBARRIER_INIT(mbar0 + 8 * s, 1);
    }
    for (int i = tid; i < 128; i += 256) cmax[i] = 0.f;
    __syncthreads();
    const uint32_t tmem = tmem_addr_sh;

    const int nchunks = D_ >> 6;   // 32 chunks of 64 K-elements (128B)

    auto load_chunk = [&](int j) {
        uint32_t abase = sbase + (uint32_t)(j & (FSTAGES - 1)) * FSTAGE_BYTES;
        uint32_t gbase = abase + 16384;
        uint32_t ubase = abase + 32768;
        long koffb = (long)j << 7;
#pragma unroll
        for (int q = 0; q < 4; ++q) {
            int idx = tid * 4 + q;
            int row = idx >> 3, c16 = idx & 7;
            uint32_t off = (uint32_t)(row * 128 + c16 * 16);
            uint32_t sw = off ^ ((off >> 3) & 0x70);
            long goff = (long)row * Kb + koffb + c16 * 16;
            CP16(abase + sw, Ae + goff);
            CP16(gbase + sw, Bg + goff);
            CP16(ubase + sw, Bu + goff);
        }
        asm volatile("cp.async.commit_group;\n");
    };

    for (int j = 0; j < FSTAGES - 1 && j < nchunks; ++j) load_chunk(j);

    for (int it = 0; it < nchunks; ++it) {
        if (it + FSTAGES - 1 <= nchunks)
            asm volatile("cp.async.wait_group %0;\n" :: "n"(FSTAGES - 2));
        else
            asm volatile("cp.async.wait_group 0;\n");
        __syncthreads();

        if (wid == 0 && elect_one_pred()) {
            FENCE_PROXY_ASYNC();
            uint32_t st = (uint32_t)(it & (FSTAGES - 1));
            uint64_t ad = MAKE_SMEM_DESC(sbase + st * FSTAGE_BYTES);
            uint64_t gd = MAKE_SMEM_DESC(sbase + st * FSTAGE_BYTES + 16384);
            uint64_t ud = MAKE_SMEM_DESC(sbase + st * FSTAGE_BYTES + 32768);
            bool acc0 = (it > 0);
#pragma unroll
            for (int ks = 0; ks < 4; ++ks) {
                bool acc = acc0 || (ks > 0);
                tcgen05_mma_f16_ss(tmem,       ad + ks * 2, gd + ks * 2, IDESC_BF16, acc);
                tcgen05_mma_f16_ss(tmem + 128, ad + ks * 2, ud + ks * 2, IDESC_BF16, acc);
            }
            TCGEN05_COMMIT(mbar0 + 8 * st);
        }

        int j = it + FSTAGES - 1;
        if (j < nchunks) {
            if (j >= FSTAGES)
                MBARRIER_WAIT_PARITY(mbar0 + 8 * (j & (FSTAGES - 1)),
                                     ((j / FSTAGES) - 1) & 1);
            load_chunk(j);
        }
    }

    MBARRIER_WAIT_PARITY(mbar0 + 8 * ((nchunks - 1) & (FSTAGES - 1)),
                         ((nchunks - 1) / FSTAGES) & 1);
    TCGEN05_FENCE_AFTER();

    // epilogue: dequant gate & up, swiglu, write a, column amax
    {
        int colb = (wid >> 2) * 64;
        int row = (wid & 3) * 32 + lane;
        long t = m0 + row;
        float as = asc_[(long)e * T_ + t];
        float* dstrow = g_a + ((long)e * T_ + t) * (long)I_ + n0 + colb;
        const float* bsg = bsc_ + (long)e * TWOI_ + n0 + colb;
        const float* bsu = bsc_ + (long)e * TWOI_ + n0 + I_ + colb;
#pragma unroll
        for (int half = 0; half < 2; ++half) {
            uint32_t dg[32], du[32];
            TCGEN05_LD_32X32B_X32(dg, tmem + colb + half * 32);
            TCGEN05_LD_32X32B_X32(du, tmem + 128 + colb + half * 32);
            TCGEN05_WAIT_LD();
            float amx[32];
#pragma unroll
            for (int c = 0; c < 32; c += 4) {
                float4 v;
#pragma unroll
                for (int j2 = 0; j2 < 4; ++j2) {
                    int cc = c + j2;
                    float gv = __uint_as_float(dg[cc]) * as * bsg[half * 32 + cc];
                    float uv = __uint_as_float(du[cc]) * as * bsu[half * 32 + cc];
                    float vv = (gv / (1.0f + expf(-gv))) * uv;
                    ((float*)&v)[j2] = vv;
                    amx[cc] = fabsf(vv);
                }
                *(float4*)(dstrow + half * 32 + c) = v;
            }
            // per-column max over the 32 rows held by this warp
#pragma unroll
            for (int c = 0; c < 32; ++c) {
#pragma unroll
                for (int off = 16; off > 0; off >>= 1)
                    amx[c] = fmaxf(amx[c], __shfl_xor_sync(0xFFFFFFFFu, amx[c], off));
            }
            // lane c owns column c: one smem atomic per column per warp
            atomicMax((unsigned int*)&cmax[colb + half * 32 + lane],
                      __float_as_uint(amx[lane]));
        }
        TCGEN05_FENCE_BEFORE();
    }
    __syncthreads();
    if (tid < 128)
        atomicMax((unsigned int*)(g_amax_a + (long)e * I_ + n0 + tid),
                  __float_as_uint(cmax[tid]));
    if (wid == 0) {
        TCGEN05_DEALLOC(tmem, 512);
    }
#else
    // ---------- naive fallback (non-'a' pass; never selected on sm_103a) -----
    // each thread: 8x8 outputs of the 128x128 a-tile
    int tr = (tid >> 4) * 8, tc = (tid & 15) * 8;
    for (int i = 0; i < 8; ++i) {
        long t = m0 + tr + i;
        float as = asc_[(long)e * T_ + t];
        const __nv_bfloat16* ar = A + (long)e * T_ * D_ + t * (long)D_;
        for (int j = 0; j < 8; ++j) {
            int n = n0 + tc + j;
            const __nv_bfloat16* bg = B + (long)e * TWOI_ * D_ + (long)n * D_;
            const __nv_bfloat16* bu = B + (long)e * TWOI_ * D_ + (long)(n + I_) * D_;
            float sg = 0.f, su = 0.f;
            for (int k = 0; k < D_; ++k) {
                float av = __bfloat162float(ar[k]);
                sg = fmaf(av, __bfloat162float(bg[k]), sg);
                su = fmaf(av, __bfloat162float(bu[k]), su);
            }
            float gv = sg * as * bsc_[(long)e * TWOI_ + n];
            float uv = su * as * bsc_[(long)e * TWOI_ + n + I_];
            float vv = (gv / (1.0f + expf(-gv))) * uv;
            g_a[((long)e * T_ + t) * I_ + n] = vv;
            atomicMax((unsigned int*)(g_amax_a + (long)e * I_ + n),
                      __float_as_uint(fabsf(vv)));
        }
    }
#endif
}

// ---------------- GEMM2 (tcgen05, unchanged R7 structure) ---------------------
#define GSTAGES 4
#define STAGE_BYTES 32768
#define GSMEM_BYTES (GSTAGES * STAGE_BYTES + 1024)

__global__ void __launch_bounds__(256, 1)
gemm_bf16_tc(const __nv_bfloat16* __restrict__ A, const __nv_bfloat16* __restrict__ B,
             float* __restrict__ Co, const float* __restrict__ asc_,
             const float* __restrict__ bsc_, int M, int N, int K) {
    extern __shared__ int8_t dynraw[];
#if USE_TC
    __shared__ __align__(16) uint64_t mbar_store[GSTAGES];
    __shared__ uint32_t tmem_addr_sh;

    const uint32_t sbase = (smem_u32(dynraw) + 1023u) & ~1023u;
    const uint32_t mbar0 = smem_u32(&mbar_store[0]);
    const int tid = threadIdx.x;
    const int wid = tid >> 5;
    const int lane = tid & 31;

    const int e = blockIdx.z;
    const int m0 = blockIdx.y * 128, n0 = blockIdx.x * 128;
    const long Kb = (long)K * 2;
    const int8_t* Ae = (const int8_t*)(A + (long)e * M * K + (long)m0 * K);
    const int8_t* Be = (const int8_t*)(B + (long)e * N * K + (long)n0 * K);

    if (wid == 0) {
        TCGEN05_ALLOC(smem_u32(&tmem_addr_sh), 512);
        TCGEN05_RELINQUISH();
    }
    if (tid == 0) {
#pragma unroll
        for (int s = 0; s < GSTAGES; ++s) MBARRIER_INIT(mbar0 + 8 * s, 1);
    }
    __syncthreads();
    const uint32_t tmem = tmem_addr_sh;

    const int nchunks = K >> 6;

    auto load_chunk = [&](int j) {
        uint32_t abase = sbase + (uint32_t)(j & (GSTAGES - 1)) * STAGE_BYTES;
        uint32_t bbase = abase + 16384;
        long koffb = (long)j << 7;
#pragma unroll
        for (int q = 0; q < 4; ++q) {
            int idx = tid * 4 + q;
            int row = idx >> 3, c16 = idx & 7;
            uint32_t off = (uint32_t)(row * 128 + c16 * 16);
            uint32_t sw = off ^ ((off >> 3) & 0x70);
            CP16(abase + sw, Ae + (long)row * Kb + koffb + c16 * 16);
            CP16(bbase + sw, Be + (long)row * Kb + koffb + c16 * 16);
        }
        asm volatile("cp.async.commit_group;\n");
    };

    for (int j = 0; j < GSTAGES - 1 && j < nchunks; ++j) load_chunk(j);

    for (int it = 0; it < nchunks; ++it) {
        if (it + GSTAGES - 1 <= nchunks)
            asm volatile("cp.async.wait_group %0;\n" :: "n"(GSTAGES - 2));
        else
            asm volatile("cp.async.wait_group 0;\n");
        __syncthreads();

        if (wid == 0 && elect_one_pred()) {
            FENCE_PROXY_ASYNC();
            uint32_t st = (uint32_t)(it & (GSTAGES - 1));
            uint64_t ad = MAKE_SMEM_DESC(sbase + st * STAGE_BYTES);
            uint64_t bd = MAKE_SMEM_DESC(sbase + st * STAGE_BYTES + 16384);
#pragma unroll
            for (int ks = 0; ks < 4; ++ks)
                tcgen05_mma_f16_ss(tmem, ad + ks * 2, bd + ks * 2, IDESC_BF16,
                                   (it > 0) || (ks > 0));
            TCGEN05_COMMIT(mbar0 + 8 * st);
        }

        int j = it + GSTAGES - 1;
        if (j < nchunks) {
            if (j >= GSTAGES)
                MBARRIER_WAIT_PARITY(mbar0 + 8 * (j & (GSTAGES - 1)),
                                     ((j / GSTAGES) - 1) & 1);
            load_chunk(j);
        }
    }

    MBARRIER_WAIT_PARITY(mbar0 + 8 * ((nchunks - 1) & (GSTAGES - 1)),
                         ((nchunks - 1) / GSTAGES) & 1);
    TCGEN05_FENCE_AFTER();

    {
        int colb = (wid >> 2) * 64;
        uint32_t d0[32], d1[32];
        TCGEN05_LD_32X32B_X32(d0, tmem + colb);
        TCGEN05_LD_32X32B_X32(d1, tmem + colb + 32);
        TCGEN05_WAIT_LD();
        TCGEN05_FENCE_BEFORE();

        int row = (wid & 3) * 32 + lane;
        float as = asc_[(long)e * M + m0 + row];
        const float* bs = bsc_ + (long)e * N + n0 + colb;
        float* dst = Co + (long)e * M * N + (long)(m0 + row) * N + n0 + colb;
#pragma unroll
        for (int c = 0; c < 32; c += 4) {
            float4 v;
            v.x = __uint_as_float(d0[c + 0]) * as * bs[c + 0];
            v.y = __uint_as_float(d0[c + 1]) * as * bs[c + 1];
            v.z = __uint_as_float(d0[c + 2]) * as * bs[c + 2];
            v.w = __uint_as_float(d0[c + 3]) * as * bs[c + 3];
            *(float4*)(dst + c) = v;
        }
#pragma unroll
        for (int c = 0; c < 32; c += 4) {
            float4 v;
            v.x = __uint_as_float(d1[c + 0]) * as * bs[32 + c + 0];
            v.y = __uint_as_float(d1[c + 1]) * as * bs[32 + c + 1];
            v.z = __uint_as_float(d1[c + 2]) * as * bs[32 + c + 2];
            v.w = __uint_as_float(d1[c + 3]) * as * bs[32 + c + 3];
            *(float4*)(dst + 32 + c) = v;
        }
    }
    __syncthreads();
    if (wid == 0) {
        TCGEN05_DEALLOC(tmem, 512);
    }
#else
    // ---------- FMA fallback (non-'a' pass; never selected on sm_103a) -------
    uint32_t* As = reinterpret_cast<uint32_t*>(dynraw);
    uint32_t* Bs = As + 1024;

    int e = blockIdx.z;
    const int8_t* Ae = (const int8_t*)(A + (long)e * M * K);
    const int8_t* Be = (const int8_t*)(B + (long)e * N * K);
    const long Kb = (long)K * 2;

    int tid = threadIdx.x;
    int tx = tid & 15, ty = tid >> 4;
    int m0 = blockIdx.y * 128, n0 = blockIdx.x * 128;

    int lrow = tid >> 1;
    int lw   = (tid & 1) * 4;

    float acc[8][8];
#pragma unroll
    for (int i = 0; i < 8; ++i)
#pragma unroll
        for (int j = 0; j < 8; ++j) acc[i][j] = 0.f;

    int nIter = (int)(Kb >> 5);
    for (int it = 0; it < nIter; ++it) {
        const uint4* gA = reinterpret_cast<const uint4*>(Ae + (long)(m0 + lrow) * Kb + it * 32) + (tid & 1);
        const uint4* gB = reinterpret_cast<const uint4*>(Be + (long)(n0 + lrow) * Kb + it * 32) + (tid & 1);
        uint4 pa = *gA, pb = *gB;
        As[(lw + 0) * 128 + lrow] = pa.x; As[(lw + 1) * 128 + lrow] = pa.y;
        As[(lw + 2) * 128 + lrow] = pa.z; As[(lw + 3) * 128 + lrow] = pa.w;
        Bs[(lw + 0) * 128 + lrow] = pb.x; Bs[(lw + 1) * 128 + lrow] = pb.y;
        Bs[(lw + 2) * 128 + lrow] = pb.z; Bs[(lw + 3) * 128 + lrow] = pb.w;
        __syncthreads();
#pragma unroll
        for (int kw = 0; kw < 8; ++kw) {
            float2 af[8], bf[8];
#pragma unroll
            for (int i = 0; i < 8; ++i)
                af[i] = __bfloat1622float2(*(const __nv_bfloat162*)&As[kw * 128 + ty * 8 + i]);
#pragma unroll
            for (int j = 0; j < 8; ++j)
                bf[j] = __bfloat1622float2(*(const __nv_bfloat162*)&Bs[kw * 128 + tx * 8 + j]);
#pragma unroll
            for (int i = 0; i < 8; ++i)
#pragma unroll
                for (int j = 0; j < 8; ++j)
                    acc[i][j] = fmaf(af[i].y, bf[j].y, fmaf(af[i].x, bf[j].x, acc[i][j]));
        }
        __syncthreads();
    }

    const float* asc = asc_ + (long)e * M + m0 + ty * 8;
    const float* bsc = bsc_ + (long)e * N + n0 + tx * 8;
    float bsv[8];
#pragma unroll
    for (int j = 0; j < 8; ++j) bsv[j] = bsc[j];
    float* Ce = Co + (long)e * M * N;
#pragma unroll
    for (int i = 0; i < 8; ++i) {
        float av = asc[i];
        float4 o0, o1;
        o0.x = acc[i][0] * av * bsv[0];
        o0.y = acc[i][1] * av * bsv[1];
        o0.z = acc[i][2] * av * bsv[2];
        o0.w = acc[i][3] * av * bsv[3];
        o1.x = acc[i][4] * av * bsv[4];
        o1.y = acc[i][5] * av * bsv[5];
        o1.z = acc[i][6] * av * bsv[6];
        o1.w = acc[i][7] * av * bsv[7];
        float4* dst = reinterpret_cast<float4*>(Ce + (long)(m0 + ty * 8 + i) * N + n0 + tx * 8);
        dst[0] = o0;
        dst[1] = o1;
    }
#endif
}

// ---------------- cleanup: zero atomic-max buffers for the next replay -------
__global__ void cleanup_kernel() {
    int i = blockIdx.x * 256 + threadIdx.x;
    if (i < E_ * D_) { g_amax_x1[i] = 0.f; g_amax_w1[i] = 0.f; }
    if (i < E_ * I_) { g_amax_a[i] = 0.f; g_amax_w2[i] = 0.f; }
}

// ---------------- launch ------------------------------------------------------
extern "C" void kernel_launch(void* const* d_in, const int* in_sizes, int n_in,
                              void* d_out, int out_size) {
    const float* x   = (const float*)d_in[0];   // [E, T, D]
    const float* guw = (const float*)d_in[1];   // [E, 2I, D]
    const float* dw  = (const float*)d_in[2];   // [E, D, I]
    float* out = (float*)d_out;                 // [E, T, D]

    __nv_bfloat16 *xq1, *wq1, *aq, *wq2;
    float *a, *ax1, *aw1, *aa, *aw2, *s1, *s2, *xs1, *ws1, *xs2, *ws2;
    cudaGetSymbolAddress((void**)&xq1, g_xq1);
    cudaGetSymbolAddress((void**)&wq1, g_wq1);
    cudaGetSymbolAddress((void**)&aq,  g_aq);
    cudaGetSymbolAddress((void**)&wq2, g_wq2);
    cudaGetSymbolAddress((void**)&a,   g_a);
    cudaGetSymbolAddress((void**)&ax1, g_amax_x1);
    cudaGetSymbolAddress((void**)&aw1, g_amax_w1);
    cudaGetSymbolAddress((void**)&aa,  g_amax_a);
    cudaGetSymbolAddress((void**)&aw2, g_amax_w2);
    cudaGetSymbolAddress((void**)&s1,  g_s1);
    cudaGetSymbolAddress((void**)&s2,  g_s2);
    cudaGetSymbolAddress((void**)&xs1, g_xs1);
    cudaGetSymbolAddress((void**)&ws1, g_ws1);
    cudaGetSymbolAddress((void**)&xs2, g_xs2);
    cudaGetSymbolAddress((void**)&ws2, g_ws2);

    cudaFuncSetAttribute(gemm1_swiglu_tc, cudaFuncAttributeMaxDynamicSharedMemorySize,
                         FSMEM_BYTES);
    cudaFuncSetAttribute(gemm_bf16_tc, cudaFuncAttributeMaxDynamicSharedMemorySize,
                         GSMEM_BYTES);

    // column amaxes for smoothing
    colmax_kernel<<<dim3(D_ / 256, T_ / 256, E_), 256>>>(x,   ax1, T_,    D_, 256);
    colmax_kernel<<<dim3(D_ / 256, TWOI_ / 256, E_), 256>>>(guw, aw1, TWOI_, D_, 256);
    colmax_kernel<<<dim3(I_ / 256, D_ / 256, E_), 256>>>(dw,  aw2, D_,    I_, 256);

    // layer 1: smooth, quantize, fused GEMM+SwiGLU (writes g_a + g_amax_a)
    smooth_scale_kernel<<<(E_ * D_ + 255) / 256, 256>>>(ax1, aw1, s1, E_ * D_);
    quant_fused_kernel<<<dim3(TWOI_ + T_, E_), 256>>>(guw, x, s1, wq1, xq1, ws1, xs1,
                                                      TWOI_, T_, D_);
    gemm1_swiglu_tc<<<dim3(I_ / 128, T_ / 128, E_), 256, FSMEM_BYTES>>>(xq1, wq1,
                                                                        xs1, ws1);

    // layer 2: smooth, quantize, GEMM -> out
    smooth_scale_kernel<<<(E_ * I_ + 255) / 256, 256>>>(aa, aw2, s2, E_ * I_);
    quant_fused_kernel<<<dim3(D_ + T_, E_), 256>>>(dw, a, s2, wq2, aq, ws2, xs2,
                                                   D_, T_, I_);
    gemm_bf16_tc<<<dim3(D_ / 128, T_ / 128, E_), 256, GSMEM_BYTES>>>(aq, wq2, out, xs2, ws2,
                                                                     T_, D_, I_);
    // reset accumulators for next graph replay
    cleanup_kernel<<<(E_ * D_ + 255) / 256, 256>>>();

    (void)in_sizes; (void)n_in; (void)out_size;
}

// round 9
// speedup vs baseline: 2.7935x; 1.2677x over previous
#include <cuda_runtime.h>
#include <cuda_bf16.h>
#include <cstdint>

// Problem shape (fixed by dataset): E=8, T=2048, D=2048, I=1024
#define E_     8
#define T_     2048
#define D_     2048
#define I_     1024
#define TWOI_  2048
#define EPS_   1e-6f
#define QMAX_  127.0f

// tcgen05 exists only in arch-specific passes (sm_103a/sm_100a). Non-suffixed
// passes (compute_103) compile the fallback. sm_103a has NO kind::i8
// (ptxas-verified R6) — kind::f16 with bf16-held integers (exact).
#if defined(__CUDA_ARCH__) && defined(__CUDA_ARCH_HAS_FEATURE__)
#  if __CUDA_ARCH_HAS_FEATURE__(SM103_ALL) || __CUDA_ARCH_HAS_FEATURE__(SM100_ALL) || __CUDA_ARCH_HAS_FEATURE__(SM101_ALL)
#    define USE_TC 1
#  endif
#endif
#ifndef USE_TC
#  define USE_TC 0
#endif

// ---------------- scratch (static device globals; no allocation) -------------
__device__ __align__(16) __nv_bfloat16 g_xq1[(long)E_ * T_ * D_];
__device__ __align__(16) __nv_bfloat16 g_wq1[(long)E_ * TWOI_ * D_];
__device__ __align__(16) __nv_bfloat16 g_aq [(long)E_ * T_ * I_];
__device__ __align__(16) __nv_bfloat16 g_wq2[(long)E_ * D_ * I_];
__device__ float  g_a  [(long)E_ * T_ * I_];
__device__ float  g_amax_x1[E_ * D_];
__device__ float  g_amax_w1[E_ * D_];
__device__ float  g_amax_a [E_ * I_];
__device__ float  g_amax_w2[E_ * I_];
__device__ float  g_s1 [E_ * D_];
__device__ float  g_s2 [E_ * I_];
__device__ float  g_xs1[E_ * T_];
__device__ float  g_ws1[E_ * TWOI_];
__device__ float  g_xs2[E_ * T_];
__device__ float  g_ws2[E_ * D_];

// ================= PTX helpers ================================================
__device__ __forceinline__ uint32_t smem_u32(const void* p) {
    return (uint32_t)__cvta_generic_to_shared(p);
}

#if USE_TC
__device__ __forceinline__ uint32_t elect_one_pred() {
    uint32_t pred;
    asm volatile(
        "{\n\t.reg .pred p;\n\t"
        "elect.sync _|p, 0xFFFFFFFF;\n\t"
        "selp.b32 %0, 1, 0, p;\n\t}"
        : "=r"(pred));
    return pred;
}

#define MBARRIER_INIT(addr, count) \
    asm volatile("mbarrier.init.shared.b64 [%0], %1;" :: "r"((uint32_t)(addr)), "r"((uint32_t)(count)) : "memory")

#define MBARRIER_WAIT_PARITY(mbar_smem_addr, phase_parity) do { \
    uint32_t _mbar = (uint32_t)(mbar_smem_addr); \
    uint32_t _parity = (uint32_t)(phase_parity); \
    uint32_t _done; \
    asm volatile( \
        "{\n\t.reg .pred p;\n\t" \
        "mbarrier.try_wait.parity.acquire.cta.shared::cta.b64 p, [%1], %2;\n\t" \
        "selp.b32 %0, 1, 0, p;\n\t}" \
        : "=r"(_done) : "r"(_mbar), "r"(_parity) : "memory"); \
    if (!_done) { \
        asm volatile( \
            "{\n\t.reg .pred P1;\n\t" \
            "WAIT_LOOP_%=:\n\t" \
            "mbarrier.try_wait.parity.acquire.cta.shared::cta.b64 P1, [%0], %1, 0x989680;\n\t" \
            "@P1 bra.uni WAIT_DONE_%=;\n\t" \
            "bra.uni WAIT_LOOP_%=;\n\t" \
            "WAIT_DONE_%=:\n\t}" \
            :: "r"(_mbar), "r"(_parity) : "memory"); \
    } \
} while(0)

#define TCGEN05_ALLOC(smem_result_addr, nCols) \
    asm volatile("tcgen05.alloc.cta_group::1.sync.aligned.shared::cta.b32 [%0], %1;" \
        :: "r"((uint32_t)(smem_result_addr)), "r"((uint32_t)(nCols)) : "memory")
#define TCGEN05_DEALLOC(tmem_addr, nCols) \
    asm volatile("tcgen05.dealloc.cta_group::1.sync.aligned.b32 %0, %1;" \
        :: "r"(tmem_addr), "r"((uint32_t)(nCols)))
#define TCGEN05_RELINQUISH() \
    asm volatile("tcgen05.relinquish_alloc_permit.cta_group::1.sync.aligned;")
#define TCGEN05_COMMIT(mbar_smem_addr) \
    asm volatile("tcgen05.commit.cta_group::1.mbarrier::arrive::one.shared::cluster.b64 [%0];" \
        :: "r"((uint32_t)(mbar_smem_addr)) : "memory")
#define TCGEN05_FENCE_AFTER()  asm volatile("tcgen05.fence::after_thread_sync;" ::: "memory")
#define TCGEN05_FENCE_BEFORE() asm volatile("tcgen05.fence::before_thread_sync;" ::: "memory")
#define TCGEN05_WAIT_LD()      asm volatile("tcgen05.wait::ld.sync.aligned;" ::: "memory")
#define FENCE_PROXY_ASYNC()    asm volatile("fence.proxy.async.shared::cta;" ::: "memory")

#define TCGEN05_LD_32X32B_X32(r, tmem_addr) \
    asm volatile( \
        "tcgen05.ld.sync.aligned.32x32b.x32.b32 " \
        "{%0, %1, %2, %3, %4, %5, %6, %7, " \
        " %8, %9, %10, %11, %12, %13, %14, %15, " \
        " %16, %17, %18, %19, %20, %21, %22, %23, " \
        " %24, %25, %26, %27, %28, %29, %30, %31}, [%32];" \
        : "=r"((r)[0]),  "=r"((r)[1]),  "=r"((r)[2]),  "=r"((r)[3]), \
          "=r"((r)[4]),  "=r"((r)[5]),  "=r"((r)[6]),  "=r"((r)[7]), \
          "=r"((r)[8]),  "=r"((r)[9]),  "=r"((r)[10]), "=r"((r)[11]), \
          "=r"((r)[12]), "=r"((r)[13]), "=r"((r)[14]), "=r"((r)[15]), \
          "=r"((r)[16]), "=r"((r)[17]), "=r"((r)[18]), "=r"((r)[19]), \
          "=r"((r)[20]), "=r"((r)[21]), "=r"((r)[22]), "=r"((r)[23]), \
          "=r"((r)[24]), "=r"((r)[25]), "=r"((r)[26]), "=r"((r)[27]), \
          "=r"((r)[28]), "=r"((r)[29]), "=r"((r)[30]), "=r"((r)[31]) \
        : "r"(tmem_addr))

// SW128 descriptor (Blackwell, LBO=1, SBO=64; rows are 128 bytes)
static constexpr uint64_t SMEM_DESC_BASE_SW128 =
    (uint64_t(2)  << 61) | (uint64_t(1) << 46) | (uint64_t(64) << 32) | (uint64_t(1) << 16);
#define MAKE_SMEM_DESC(base_addr) \
    (SMEM_DESC_BASE_SW128 | ((uint64_t)((base_addr) >> 4) & 0x3FFF))

// tcgen05 f16 SS MMA (bf16 x bf16 -> f32 TMEM), K=16 per call
__device__ __forceinline__ void tcgen05_mma_f16_ss(
    uint32_t d_tmem, uint64_t a_desc, uint64_t b_desc, uint32_t idesc, bool accum) {
    uint32_t en = accum ? 1u : 0u;
    asm volatile(
        "{\n\t.reg .pred p;\n\t"
        "setp.ne.u32 p, %5, 0;\n\t"
        "tcgen05.mma.cta_group::1.kind::f16 [%0], %1, %2, %3, {%4, %4, %4, %4}, p;\n\t"
        "}"
        :: "r"(d_tmem), "l"(a_desc), "l"(b_desc), "r"(idesc), "r"(0u), "r"(en)
        : "memory");
}

// idesc (kind::f16): dtype=F32(1)<<4, atype=BF16(1)<<7, btype=BF16(1)<<10,
// N/8<<17, M/16<<24.  (Validated vs test_mma.cu 0x8080490, test_2cta_mma_bf16.)
static constexpr uint32_t IDESC_BF16 =
    (1u << 4) | (1u << 7) | (1u << 10) | ((128u / 8) << 17) | ((128u / 16) << 24);
#endif  // USE_TC

#define CP16(dst, src) \
    asm volatile("cp.async.cg.shared.global [%0], [%1], 16;\n" :: "r"(dst), "l"(src))

// ---------------- column abs-max over rows (float4 vectorized) ---------------
// thread owns 4 columns: c0 = bx*1024 + tid*4. grid (C/1024, R/256, E).
__global__ void colmax4_kernel(const float* __restrict__ M, float* __restrict__ out,
                               int R, int C) {
    int c0 = blockIdx.x * 1024 + threadIdx.x * 4;
    int e = blockIdx.z;
    const float4* p = (const float4*)(M + (long)e * R * C + (long)blockIdx.y * 256 * C + c0);
    long str = C >> 2;
    float4 m = make_float4(0.f, 0.f, 0.f, 0.f);
#pragma unroll 4
    for (int r = 0; r < 256; ++r) {
        float4 v = p[(long)r * str];
        m.x = fmaxf(m.x, fabsf(v.x)); m.y = fmaxf(m.y, fabsf(v.y));
        m.z = fmaxf(m.z, fabsf(v.z)); m.w = fmaxf(m.w, fabsf(v.w));
    }
    unsigned int* o = (unsigned int*)(out + e * C + c0);
    atomicMax(o + 0, __float_as_uint(m.x));
    atomicMax(o + 1, __float_as_uint(m.y));
    atomicMax(o + 2, __float_as_uint(m.z));
    atomicMax(o + 3, __float_as_uint(m.w));
}

// ---------------- smooth scale ----------------------------------------------
__global__ void smooth_scale_kernel(const float* __restrict__ ax,
                                    const float* __restrict__ aw,
                                    float* __restrict__ s, int n) {
    int i = blockIdx.x * 256 + threadIdx.x;
    if (i < n) {
        float v = sqrtf(fmaxf(ax[i], EPS_) / fmaxf(aw[i], EPS_));
        s[i] = fmaxf(v, EPS_);
    }
}

// ---------------- per-row quantization: warp-per-row, 2-pass, float4 --------
// rows [0,Rw): weights (v = W*s); rows [Rw,Rw+Rx): activations (v = X/s).
// block = 8 warps = 8 rows; grid ((Rw+Rx)/8, E).
__global__ void quant_warp_kernel(const float* __restrict__ W, const float* __restrict__ X,
                                  const float* __restrict__ s,
                                  __nv_bfloat16* __restrict__ qw, __nv_bfloat16* __restrict__ qx,
                                  float* __restrict__ rsw, float* __restrict__ rsx,
                                  int Rw, int Rx, int C) {
    int e = blockIdx.y;
    int wid = threadIdx.x >> 5, lane = threadIdx.x & 31;
    int rg = blockIdx.x * 8 + wid;
    int mul = (rg < Rw);
    int r = mul ? rg : rg - Rw;
    int R = mul ? Rw : Rx;
    const float* row = (mul ? W : X) + ((long)e * R + r) * (long)C;
    const float* sv  = s + (long)e * C;

    // pass 1: row max of |v|
    float m = 0.f;
    for (int c = lane * 4; c < C; c += 128) {
        float4 rv = *(const float4*)(row + c);
        float4 svv = *(const float4*)(sv + c);
        float4 v;
        if (mul) { v.x = rv.x * svv.x; v.y = rv.y * svv.y; v.z = rv.z * svv.z; v.w = rv.w * svv.w; }
        else     { v.x = rv.x / svv.x; v.y = rv.y / svv.y; v.z = rv.z / svv.z; v.w = rv.w / svv.w; }
        m = fmaxf(m, fmaxf(fmaxf(fabsf(v.x), fabsf(v.y)), fmaxf(fabsf(v.z), fabsf(v.w))));
    }
#pragma unroll
    for (int off = 16; off > 0; off >>= 1)
        m = fmaxf(m, __shfl_xor_sync(0xFFFFFFFFu, m, off));
    float scale = fmaxf(m, EPS_) * (1.0f / QMAX_);
    if (lane == 0) (mul ? rsw : rsx)[(long)e * R + r] = scale;

    // pass 2: recompute v (L2-hot reload), quantize, store paired bf16
    __nv_bfloat16* qr = (mul ? qw : qx) + ((long)e * R + r) * (long)C;
    for (int c = lane * 4; c < C; c += 128) {
        float4 rv = *(const float4*)(row + c);
        float4 svv = *(const float4*)(sv + c);
        float4 v;
        if (mul) { v.x = rv.x * svv.x; v.y = rv.y * svv.y; v.z = rv.z * svv.z; v.w = rv.w * svv.w; }
        else     { v.x = rv.x / svv.x; v.y = rv.y / svv.y; v.z = rv.z / svv.z; v.w = rv.w / svv.w; }
        float q0 = fminf(fmaxf(rintf(v.x / scale), -QMAX_), QMAX_);
        float q1 = fminf(fmaxf(rintf(v.y / scale), -QMAX_), QMAX_);
        float q2 = fminf(fmaxf(rintf(v.z / scale), -QMAX_), QMAX_);
        float q3 = fminf(fmaxf(rintf(v.w / scale), -QMAX_), QMAX_);
        __nv_bfloat162 p0 = __floats2bfloat162_rn(q0, q1);
        __nv_bfloat162 p1 = __floats2bfloat162_rn(q2, q3);
        uint2 st;
        st.x = *(uint32_t*)&p0;
        st.y = *(uint32_t*)&p1;
        *(uint2*)(qr + c) = st;
    }
}

// ---------------- GEMM1 + SwiGLU fused (tcgen05, M=256) -----------------------
// CTA: 256 token-rows x 128 I-cols. TMEM 512 cols: gate_m0@0, up_m0@128,
// gate_m1@256, up_m1@384. Stage = A0+A1+Bg+Bu = 64KB, 3-stage ring.
#define F1STAGES 3
#define F1STAGE_BYTES 65536
#define F1SMEM_BYTES (F1STAGES * F1STAGE_BYTES + 1024)

__global__ void __launch_bounds__(256, 1)
gemm1_swiglu_tc(const __nv_bfloat16* __restrict__ A, const __nv_bfloat16* __restrict__ B,
                const float* __restrict__ asc_, const float* __restrict__ bsc_) {
    extern __shared__ int8_t dynraw[];
    const int tid = threadIdx.x;
    const int e = blockIdx.z;
    const int m0 = blockIdx.y * 256, n0 = blockIdx.x * 128;
#if USE_TC
    __shared__ __align__(16) uint64_t mbar_store[F1STAGES];
    __shared__ uint32_t tmem_addr_sh;
    __shared__ float cmax[128];

    const uint32_t sbase = (smem_u32(dynraw) + 1023u) & ~1023u;
    const uint32_t mbar0 = smem_u32(&mbar_store[0]);
    const int wid = tid >> 5;
    const int lane = tid & 31;

    const long Kb = (long)D_ * 2;
    const int8_t* Ae = (const int8_t*)(A + (long)e * T_ * D_ + (long)m0 * D_);
    const int8_t* Bg = (const int8_t*)(B + (long)e * TWOI_ * D_ + (long)n0 * D_);
    const int8_t* Bu = (const int8_t*)(B + (long)e * TWOI_ * D_ + (long)(n0 + I_) * D_);

    if (wid == 0) {
        TCGEN05_ALLOC(smem_u32(&tmem_addr_sh), 512);
        TCGEN05_RELINQUISH();
    }
    if (tid == 0) {
#pragma unroll
        for (int s = 0; s < F1STAGES; ++s) MBARRIER_INIT(mbar0 + 8 * s, 1);
    }
    for (int i = tid; i < 128; i += 256) cmax[i] = 0.f;
    __syncthreads();
    const uint32_t tmem = tmem_addr_sh;

    const int nchunks = D_ >> 6;   // 32 chunks of 64 K-elements (128B)

    auto load_chunk = [&](int j) {
        uint32_t base = sbase + (uint32_t)(j % F1STAGES) * F1STAGE_BYTES;
        long koffb = (long)j << 7;
#pragma unroll
        for (int q = 0; q < 4; ++q) {
            int idx = tid * 4 + q;
            int row = idx >> 3, c16 = idx & 7;
            uint32_t off = (uint32_t)(row * 128 + c16 * 16);
            uint32_t sw = off ^ ((off >> 3) & 0x70);
            long go = (long)row * Kb + koffb + c16 * 16;
            CP16(base + sw,         Ae + go);                    // A0
            CP16(base + 16384 + sw, Ae + 128 * Kb + go);         // A1
            CP16(base + 32768 + sw, Bg + go);                    // Bg
            CP16(base + 49152 + sw, Bu + go);                    // Bu
        }
        asm volatile("cp.async.commit_group;\n");
    };

    for (int j = 0; j < F1STAGES - 1; ++j) load_chunk(j);

    for (int it = 0; it < nchunks; ++it) {
        if (it + 2 <= nchunks)
            asm volatile("cp.async.wait_group 1;\n");
        else
            asm volatile("cp.async.wait_group 0;\n");
        __syncthreads();

        if (wid == 0 && elect_one_pred()) {
            FENCE_PROXY_ASYNC();
            uint32_t base = sbase + (uint32_t)(it % F1STAGES) * F1STAGE_BYTES;
            uint64_t a0 = MAKE_SMEM_DESC(base);
            uint64_t a1 = MAKE_SMEM_DESC(base + 16384);
            uint64_t gd = MAKE_SMEM_DESC(base + 32768);
            uint64_t ud = MAKE_SMEM_DESC(base + 49152);
            bool acc0 = (it > 0);
#pragma unroll
            for (int ks = 0; ks < 4; ++ks) {
                bool acc = acc0 || (ks > 0);
                tcgen05_mma_f16_ss(tmem,       a0 + ks * 2, gd + ks * 2, IDESC_BF16, acc);
                tcgen05_mma_f16_ss(tmem + 128, a0 + ks * 2, ud + ks * 2, IDESC_BF16, acc);
                tcgen05_mma_f16_ss(tmem + 256, a1 + ks * 2, gd + ks * 2, IDESC_BF16, acc);
                tcgen05_mma_f16_ss(tmem + 384, a1 + ks * 2, ud + ks * 2, IDESC_BF16, acc);
            }
            TCGEN05_COMMIT(mbar0 + 8 * (it % F1STAGES));
        }

        int j = it + F1STAGES - 1;
        if (j < nchunks) {
            if (j >= F1STAGES)
                MBARRIER_WAIT_PARITY(mbar0 + 8 * (j % F1STAGES),
                                     ((j - F1STAGES) / F1STAGES) & 1);
            load_chunk(j);
        }
    }

    MBARRIER_WAIT_PARITY(mbar0 + 8 * ((nchunks - 1) % F1STAGES),
                         ((nchunks - 1) / F1STAGES) & 1);
    TCGEN05_FENCE_AFTER();

    // epilogue: warp -> m-tile (wid>>2), subpartition rows (wid&3)*32+lane
    {
        int mt = wid >> 2;
        uint32_t tb = tmem + mt * 256;
        long t = m0 + mt * 128 + (wid & 3) * 32 + lane;
        float as = asc_[(long)e * T_ + t];
        float* dstrow = g_a + ((long)e * T_ + t) * (long)I_ + n0;
        const float* bsg = bsc_ + (long)e * TWOI_ + n0;
        const float* bsu = bsc_ + (long)e * TWOI_ + n0 + I_;
#pragma unroll
        for (int part = 0; part < 4; ++part) {
            uint32_t dg[32], du[32];
            TCGEN05_LD_32X32B_X32(dg, tb + part * 32);
            TCGEN05_LD_32X32B_X32(du, tb + 128 + part * 32);
            TCGEN05_WAIT_LD();
            float amx[32];
#pragma unroll
            for (int c = 0; c < 32; c += 4) {
                float4 v;
#pragma unroll
                for (int j2 = 0; j2 < 4; ++j2) {
                    int cc = c + j2;
                    float gv = __uint_as_float(dg[cc]) * as * bsg[part * 32 + cc];
                    float uv = __uint_as_float(du[cc]) * as * bsu[part * 32 + cc];
                    float vv = (gv / (1.0f + expf(-gv))) * uv;
                    ((float*)&v)[j2] = vv;
                    amx[cc] = fabsf(vv);
                }
                *(float4*)(dstrow + part * 32 + c) = v;
            }
#pragma unroll
            for (int c = 0; c < 32; ++c) {
#pragma unroll
                for (int off = 16; off > 0; off >>= 1)
                    amx[c] = fmaxf(amx[c], __shfl_xor_sync(0xFFFFFFFFu, amx[c], off));
            }
            atomicMax((unsigned int*)&cmax[part * 32 + lane],
                      __float_as_uint(amx[lane]));
        }
        TCGEN05_FENCE_BEFORE();
    }
    __syncthreads();
    if (tid < 128)
        atomicMax((unsigned int*)(g_amax_a + (long)e * I_ + n0 + tid),
                  __float_as_uint(cmax[tid]));
    if (wid == 0) {
        TCGEN05_DEALLOC(tmem, 512);
    }
#else
    // naive fallback (never selected on sm_103a; correctness-preserving)
    for (int idx = tid; idx < 256 * 128; idx += 256) {
        int i = idx >> 7, j = idx & 127;
        long t = m0 + i;
        int n = n0 + j;
        const __nv_bfloat16* ar = A + (long)e * T_ * D_ + t * (long)D_;
        const __nv_bfloat16* bg = B + (long)e * TWOI_ * D_ + (long)n * D_;
        const __nv_bfloat16* bu = B + (long)e * TWOI_ * D_ + (long)(n + I_) * D_;
        float sg = 0.f, su = 0.f;
        for (int k = 0; k < D_; ++k) {
            float av = __bfloat162float(ar[k]);
            sg = fmaf(av, __bfloat162float(bg[k]), sg);
            su = fmaf(av, __bfloat162float(bu[k]), su);
        }
        float as = asc_[(long)e * T_ + t];
        float gv = sg * as * bsc_[(long)e * TWOI_ + n];
        float uv = su * as * bsc_[(long)e * TWOI_ + n + I_];
        float vv = (gv / (1.0f + expf(-gv))) * uv;
        g_a[((long)e * T_ + t) * I_ + n] = vv;
        atomicMax((unsigned int*)(g_amax_a + (long)e * I_ + n),
                  __float_as_uint(fabsf(vv)));
    }
#endif
}

// ---------------- GEMM2 (tcgen05, M=256 x N=256) ------------------------------
// TMEM: D00@0, D01@128, D10@256, D11@384. Stage = A0+A1+B0+B1 = 64KB, 3 stages.
#define G2STAGES 3
#define G2STAGE_BYTES 65536
#define G2SMEM_BYTES (G2STAGES * G2STAGE_BYTES + 1024)

__global__ void __launch_bounds__(256, 1)
gemm2_bf16_tc(const __nv_bfloat16* __restrict__ A, const __nv_bfloat16* __restrict__ B,
              float* __restrict__ Co, const float* __restrict__ asc_,
              const float* __restrict__ bsc_, int M, int N, int K) {
    extern __shared__ int8_t dynraw[];
    const int tid = threadIdx.x;
    const int e = blockIdx.z;
    const int m0 = blockIdx.y * 256, n0 = blockIdx.x * 256;
#if USE_TC
    __shared__ __align__(16) uint64_t mbar_store[G2STAGES];
    __shared__ uint32_t tmem_addr_sh;

    const uint32_t sbase = (smem_u32(dynraw) + 1023u) & ~1023u;
    const uint32_t mbar0 = smem_u32(&mbar_store[0]);
    const int wid = tid >> 5;
    const int lane = tid & 31;

    const long Kb = (long)K * 2;
    const int8_t* Ae = (const int8_t*)(A + (long)e * M * K + (long)m0 * K);
    const int8_t* Be = (const int8_t*)(B + (long)e * N * K + (long)n0 * K);

    if (wid == 0) {
        TCGEN05_ALLOC(smem_u32(&tmem_addr_sh), 512);
        TCGEN05_RELINQUISH();
    }
    if (tid == 0) {
#pragma unroll
        for (int s = 0; s < G2STAGES; ++s) MBARRIER_INIT(mbar0 + 8 * s, 1);
    }
    __syncthreads();
    const uint32_t tmem = tmem_addr_sh;

    const int nchunks = K >> 6;

    auto load_chunk = [&](int j) {
        uint32_t base = sbase + (uint32_t)(j % G2STAGES) * G2STAGE_BYTES;
        long koffb = (long)j << 7;
#pragma unroll
        for (int q = 0; q < 4; ++q) {
            int idx = tid * 4 + q;
            int row = idx >> 3, c16 = idx & 7;
            uint32_t off = (uint32_t)(row * 128 + c16 * 16);
            uint32_t sw = off ^ ((off >> 3) & 0x70);
            long go = (long)row * Kb + koffb + c16 * 16;
            CP16(base + sw,         Ae + go);                    // A0
            CP16(base + 16384 + sw, Ae + 128 * Kb + go);         // A1
            CP16(base + 32768 + sw, Be + go);                    // B0
            CP16(base + 49152 + sw, Be + 128 * Kb + go);         // B1
        }
        asm volatile("cp.async.commit_group;\n");
    };

    for (int j = 0; j < G2STAGES - 1; ++j) load_chunk(j);

    for (int it = 0; it < nchunks; ++it) {
        if (it + 2 <= nchunks)
            asm volatile("cp.async.wait_group 1;\n");
        else
            asm volatile("cp.async.wait_group 0;\n");
        __syncthreads();

        if (wid == 0 && elect_one_pred()) {
            FENCE_PROXY_ASYNC();
            uint32_t base = sbase + (uint32_t)(it % G2STAGES) * G2STAGE_BYTES;
            uint64_t a0 = MAKE_SMEM_DESC(base);
            uint64_t a1 = MAKE_SMEM_DESC(base + 16384);
            uint64_t b0 = MAKE_SMEM_DESC(base + 32768);
            uint64_t b1 = MAKE_SMEM_DESC(base + 49152);
            bool acc0 = (it > 0);
#pragma unroll
            for (int ks = 0; ks < 4; ++ks) {
                bool acc = acc0 || (ks > 0);
                tcgen05_mma_f16_ss(tmem,       a0 + ks * 2, b0 + ks * 2, IDESC_BF16, acc);
                tcgen05_mma_f16_ss(tmem + 128, a0 + ks * 2, b1 + ks * 2, IDESC_BF16, acc);
                tcgen05_mma_f16_ss(tmem + 256, a1 + ks * 2, b0 + ks * 2, IDESC_BF16, acc);
                tcgen05_mma_f16_ss(tmem + 384, a1 + ks * 2, b1 + ks * 2, IDESC_BF16, acc);
            }
            TCGEN05_COMMIT(mbar0 + 8 * (it % G2STAGES));
        }

        int j = it + G2STAGES - 1;
        if (j < nchunks) {
            if (j >= G2STAGES)
                MBARRIER_WAIT_PARITY(mbar0 + 8 * (j % G2STAGES),
                                     ((j - G2STAGES) / G2STAGES) & 1);
            load_chunk(j);
        }
    }

    MBARRIER_WAIT_PARITY(mbar0 + 8 * ((nchunks - 1) % G2STAGES),
                         ((nchunks - 1) / G2STAGES) & 1);
    TCGEN05_FENCE_AFTER();

    // epilogue: warp -> m-tile (wid>>2); 8 parts of 32 cols (n-tiles 0/1)
    {
        int mt = wid >> 2;
        long row = m0 + mt * 128 + (wid & 3) * 32 + lane;
        float as = asc_[(long)e * M + row];
        const float* bs = bsc_ + (long)e * N + n0;
        float* dst = Co + (long)e * M * N + row * N + n0;
#pragma unroll
        for (int part = 0; part < 8; ++part) {
            uint32_t ta = tmem + mt * 256 + ((part >= 4) ? 128 : 0) + (part & 3) * 32;
            uint32_t d0[32];
            TCGEN05_LD_32X32B_X32(d0, ta);
            TCGEN05_WAIT_LD();
#pragma unroll
            for (int c = 0; c < 32; c += 4) {
                float4 v;
                v.x = __uint_as_float(d0[c + 0]) * as * bs[part * 32 + c + 0];
                v.y = __uint_as_float(d0[c + 1]) * as * bs[part * 32 + c + 1];
                v.z = __uint_as_float(d0[c + 2]) * as * bs[part * 32 + c + 2];
                v.w = __uint_as_float(d0[c + 3]) * as * bs[part * 32 + c + 3];
                *(float4*)(dst + part * 32 + c) = v;
            }
        }
        TCGEN05_FENCE_BEFORE();
    }
    __syncthreads();
    if (wid == 0) {
        TCGEN05_DEALLOC(tmem, 512);
    }
#else
    // naive fallback (never selected on sm_103a)
    for (int idx = tid; idx < 256 * 256; idx += 256) {
        int i = idx >> 8, j = idx & 255;
        long r = m0 + i;
        int n = n0 + j;
        const __nv_bfloat16* ar = A + (long)e * M * K + r * (long)K;
        const __nv_bfloat16* br = B + (long)e * N * K + (long)n * K;
        float sum = 0.f;
        for (int k = 0; k < K; ++k)
            sum = fmaf(__bfloat162float(ar[k]), __bfloat162float(br[k]), sum);
        Co[(long)e * M * N + r * N + n] = sum * asc_[(long)e * M + r] * bsc_[(long)e * N + n];
    }
#endif
}

// ---------------- cleanup: zero atomic-max buffers for the next replay -------
__global__ void cleanup_kernel() {
    int i = blockIdx.x * 256 + threadIdx.x;
    if (i < E_ * D_) { g_amax_x1[i] = 0.f; g_amax_w1[i] = 0.f; }
    if (i < E_ * I_) { g_amax_a[i] = 0.f; g_amax_w2[i] = 0.f; }
}

// ---------------- launch ------------------------------------------------------
extern "C" void kernel_launch(void* const* d_in, const int* in_sizes, int n_in,
                              void* d_out, int out_size) {
    const float* x   = (const float*)d_in[0];   // [E, T, D]
    const float* guw = (const float*)d_in[1];   // [E, 2I, D]
    const float* dw  = (const float*)d_in[2];   // [E, D, I]
    float* out = (float*)d_out;                 // [E, T, D]

    __nv_bfloat16 *xq1, *wq1, *aq, *wq2;
    float *a, *ax1, *aw1, *aa, *aw2, *s1, *s2, *xs1, *ws1, *xs2, *ws2;
    cudaGetSymbolAddress((void**)&xq1, g_xq1);
    cudaGetSymbolAddress((void**)&wq1, g_wq1);
    cudaGetSymbolAddress((void**)&aq,  g_aq);
    cudaGetSymbolAddress((void**)&wq2, g_wq2);
    cudaGetSymbolAddress((void**)&a,   g_a);
    cudaGetSymbolAddress((void**)&ax1, g_amax_x1);
    cudaGetSymbolAddress((void**)&aw1, g_amax_w1);
    cudaGetSymbolAddress((void**)&aa,  g_amax_a);
    cudaGetSymbolAddress((void**)&aw2, g_amax_w2);
    cudaGetSymbolAddress((void**)&s1,  g_s1);
    cudaGetSymbolAddress((void**)&s2,  g_s2);
    cudaGetSymbolAddress((void**)&xs1, g_xs1);
    cudaGetSymbolAddress((void**)&ws1, g_ws1);
    cudaGetSymbolAddress((void**)&xs2, g_xs2);
    cudaGetSymbolAddress((void**)&ws2, g_ws2);

    cudaFuncSetAttribute(gemm1_swiglu_tc, cudaFuncAttributeMaxDynamicSharedMemorySize,
                         F1SMEM_BYTES);
    cudaFuncSetAttribute(gemm2_bf16_tc, cudaFuncAttributeMaxDynamicSharedMemorySize,
                         G2SMEM_BYTES);

    // column amaxes for smoothing
    colmax4_kernel<<<dim3(D_ / 1024, T_ / 256, E_), 256>>>(x,   ax1, T_,    D_);
    colmax4_kernel<<<dim3(D_ / 1024, TWOI_ / 256, E_), 256>>>(guw, aw1, TWOI_, D_);
    colmax4_kernel<<<dim3(I_ / 1024, D_ / 256, E_), 256>>>(dw,  aw2, D_,    I_);

    // layer 1: smooth, quantize, fused GEMM+SwiGLU (writes g_a + g_amax_a)
    smooth_scale_kernel<<<(E_ * D_ + 255) / 256, 256>>>(ax1, aw1, s1, E_ * D_);
    quant_warp_kernel<<<dim3((TWOI_ + T_) / 8, E_), 256>>>(guw, x, s1, wq1, xq1,
                                                           ws1, xs1, TWOI_, T_, D_);
    gemm1_swiglu_tc<<<dim3(I_ / 128, T_ / 256, E_), 256, F1SMEM_BYTES>>>(xq1, wq1,
                                                                         xs1, ws1);

    // layer 2: smooth, quantize, GEMM -> out
    smooth_scale_kernel<<<(E_ * I_ + 255) / 256, 256>>>(aa, aw2, s2, E_ * I_);
    quant_warp_kernel<<<dim3((D_ + T_) / 8, E_), 256>>>(dw, a, s2, wq2, aq,
                                                        ws2, xs2, D_, T_, I_);
    gemm2_bf16_tc<<<dim3(D_ / 256, T_ / 256, E_), 256, G2SMEM_BYTES>>>(aq, wq2, out,
                                                                       xs2, ws2,
                                                                       T_, D_, I_);
    // reset accumulators for next graph replay
    cleanup_kernel<<<(E_ * D_ + 255) / 256, 256>>>();

    (void)in_sizes; (void)n_in; (void)out_size;
}

// round 10
// speedup vs baseline: 2.8715x; 1.0279x over previous
#include <cuda_runtime.h>
#include <cuda_bf16.h>
#include <cstdint>

// Problem shape (fixed by dataset): E=8, T=2048, D=2048, I=1024
#define E_     8
#define T_     2048
#define D_     2048
#define I_     1024
#define TWOI_  2048
#define EPS_   1e-6f
#define QMAX_  127.0f

// tcgen05 exists only in arch-specific passes (sm_103a/sm_100a). Non-suffixed
// passes (compute_103) compile the fallback. sm_103a has NO kind::i8
// (ptxas-verified R6) — kind::f16 with bf16-held integers (exact).
#if defined(__CUDA_ARCH__) && defined(__CUDA_ARCH_HAS_FEATURE__)
#  if __CUDA_ARCH_HAS_FEATURE__(SM103_ALL) || __CUDA_ARCH_HAS_FEATURE__(SM100_ALL) || __CUDA_ARCH_HAS_FEATURE__(SM101_ALL)
#    define USE_TC 1
#  endif
#endif
#ifndef USE_TC
#  define USE_TC 0
#endif

// ---------------- scratch (static device globals; no allocation) -------------
__device__ __align__(16) __nv_bfloat16 g_xq1[(long)E_ * T_ * D_];
__device__ __align__(16) __nv_bfloat16 g_wq1[(long)E_ * TWOI_ * D_];
__device__ __align__(16) __nv_bfloat16 g_aq [(long)E_ * T_ * I_];
__device__ __align__(16) __nv_bfloat16 g_wq2[(long)E_ * D_ * I_];
__device__ float  g_a  [(long)E_ * T_ * I_];
__device__ float  g_amax_x1[E_ * D_];
__device__ float  g_amax_w1[E_ * D_];
__device__ float  g_amax_a [E_ * I_];
__device__ float  g_amax_w2[E_ * I_];
__device__ float  g_s1 [E_ * D_];
__device__ float  g_s2 [E_ * I_];
__device__ float  g_xs1[E_ * T_];
__device__ float  g_ws1[E_ * TWOI_];
__device__ float  g_xs2[E_ * T_];
__device__ float  g_ws2[E_ * D_];

// ================= PTX helpers ================================================
__device__ __forceinline__ uint32_t smem_u32(const void* p) {
    return (uint32_t)__cvta_generic_to_shared(p);
}

#if USE_TC
__device__ __forceinline__ uint32_t elect_one_pred() {
    uint32_t pred;
    asm volatile(
        "{\n\t.reg .pred p;\n\t"
        "elect.sync _|p, 0xFFFFFFFF;\n\t"
        "selp.b32 %0, 1, 0, p;\n\t}"
        : "=r"(pred));
    return pred;
}

#define MBARRIER_INIT(addr, count) \
    asm volatile("mbarrier.init.shared.b64 [%0], %1;" :: "r"((uint32_t)(addr)), "r"((uint32_t)(count)) : "memory")

#define MBARRIER_WAIT_PARITY(mbar_smem_addr, phase_parity) do { \
    uint32_t _mbar = (uint32_t)(mbar_smem_addr); \
    uint32_t _parity = (uint32_t)(phase_parity); \
    uint32_t _done; \
    asm volatile( \
        "{\n\t.reg .pred p;\n\t" \
        "mbarrier.try_wait.parity.acquire.cta.shared::cta.b64 p, [%1], %2;\n\t" \
        "selp.b32 %0, 1, 0, p;\n\t}" \
        : "=r"(_done) : "r"(_mbar), "r"(_parity) : "memory"); \
    if (!_done) { \
        asm volatile( \
            "{\n\t.reg .pred P1;\n\t" \
            "WAIT_LOOP_%=:\n\t" \
            "mbarrier.try_wait.parity.acquire.cta.shared::cta.b64 P1, [%0], %1, 0x989680;\n\t" \
            "@P1 bra.uni WAIT_DONE_%=;\n\t" \
            "bra.uni WAIT_LOOP_%=;\n\t" \
            "WAIT_DONE_%=:\n\t}" \
            :: "r"(_mbar), "r"(_parity) : "memory"); \
    } \
} while(0)

#define TCGEN05_ALLOC(smem_result_addr, nCols) \
    asm volatile("tcgen05.alloc.cta_group::1.sync.aligned.shared::cta.b32 [%0], %1;" \
        :: "r"((uint32_t)(smem_result_addr)), "r"((uint32_t)(nCols)) : "memory")
#define TCGEN05_DEALLOC(tmem_addr, nCols) \
    asm volatile("tcgen05.dealloc.cta_group::1.sync.aligned.b32 %0, %1;" \
        :: "r"(tmem_addr), "r"((uint32_t)(nCols)))
#define TCGEN05_RELINQUISH() \
    asm volatile("tcgen05.relinquish_alloc_permit.cta_group::1.sync.aligned;")
#define TCGEN05_COMMIT(mbar_smem_addr) \
    asm volatile("tcgen05.commit.cta_group::1.mbarrier::arrive::one.shared::cluster.b64 [%0];" \
        :: "r"((uint32_t)(mbar_smem_addr)) : "memory")
#define TCGEN05_FENCE_AFTER()  asm volatile("tcgen05.fence::after_thread_sync;" ::: "memory")
#define TCGEN05_FENCE_BEFORE() asm volatile("tcgen05.fence::before_thread_sync;" ::: "memory")
#define TCGEN05_WAIT_LD()      asm volatile("tcgen05.wait::ld.sync.aligned;" ::: "memory")
#define FENCE_PROXY_ASYNC()    asm volatile("fence.proxy.async.shared::cta;" ::: "memory")

#define TCGEN05_LD_32X32B_X32(r, tmem_addr) \
    asm volatile( \
        "tcgen05.ld.sync.aligned.32x32b.x32.b32 " \
        "{%0, %1, %2, %3, %4, %5, %6, %7, " \
        " %8, %9, %10, %11, %12, %13, %14, %15, " \
        " %16, %17, %18, %19, %20, %21, %22, %23, " \
        " %24, %25, %26, %27, %28, %29, %30, %31}, [%32];" \
        : "=r"((r)[0]),  "=r"((r)[1]),  "=r"((r)[2]),  "=r"((r)[3]), \
          "=r"((r)[4]),  "=r"((r)[5]),  "=r"((r)[6]),  "=r"((r)[7]), \
          "=r"((r)[8]),  "=r"((r)[9]),  "=r"((r)[10]), "=r"((r)[11]), \
          "=r"((r)[12]), "=r"((r)[13]), "=r"((r)[14]), "=r"((r)[15]), \
          "=r"((r)[16]), "=r"((r)[17]), "=r"((r)[18]), "=r"((r)[19]), \
          "=r"((r)[20]), "=r"((r)[21]), "=r"((r)[22]), "=r"((r)[23]), \
          "=r"((r)[24]), "=r"((r)[25]), "=r"((r)[26]), "=r"((r)[27]), \
          "=r"((r)[28]), "=r"((r)[29]), "=r"((r)[30]), "=r"((r)[31]) \
        : "r"(tmem_addr))

// SW128 descriptor (Blackwell, LBO=1, SBO=64; rows are 128 bytes)
static constexpr uint64_t SMEM_DESC_BASE_SW128 =
    (uint64_t(2)  << 61) | (uint64_t(1) << 46) | (uint64_t(64) << 32) | (uint64_t(1) << 16);
#define MAKE_SMEM_DESC(base_addr) \
    (SMEM_DESC_BASE_SW128 | ((uint64_t)((base_addr) >> 4) & 0x3FFF))

// tcgen05 f16 SS MMA (bf16 x bf16 -> f32 TMEM), K=16 per call
__device__ __forceinline__ void tcgen05_mma_f16_ss(
    uint32_t d_tmem, uint64_t a_desc, uint64_t b_desc, uint32_t idesc, bool accum) {
    uint32_t en = accum ? 1u : 0u;
    asm volatile(
        "{\n\t.reg .pred p;\n\t"
        "setp.ne.u32 p, %5, 0;\n\t"
        "tcgen05.mma.cta_group::1.kind::f16 [%0], %1, %2, %3, {%4, %4, %4, %4}, p;\n\t"
        "}"
        :: "r"(d_tmem), "l"(a_desc), "l"(b_desc), "r"(idesc), "r"(0u), "r"(en)
        : "memory");
}

// idesc (kind::f16): dtype=F32(1)<<4, atype=BF16(1)<<7, btype=BF16(1)<<10,
// N/8<<17, M/16<<24.  (Validated vs test_mma.cu 0x8080490, test_2cta_mma_bf16.)
static constexpr uint32_t IDESC_BF16 =
    (1u << 4) | (1u << 7) | (1u << 10) | ((128u / 8) << 17) | ((128u / 16) << 24);
#endif  // USE_TC

#define CP16(dst, src) \
    asm volatile("cp.async.cg.shared.global [%0], [%1], 16;\n" :: "r"(dst), "l"(src))

// ---------------- merged column abs-max over rows -----------------------------
// One launch covers x [T,D], guw [2I,D], dw [D,I]. Tile = 64 rows x 1024 cols.
// blockIdx.y in [0,160): [0,64)=x, [64,128)=guw, [128,160)=dw. R=2048 for all.
__global__ void colmax_all_kernel(const float* __restrict__ x,
                                  const float* __restrict__ guw,
                                  const float* __restrict__ dw) {
    int e = blockIdx.z;
    int yy = blockIdx.y;
    const float* M; float* out; int C, tile;
    if (yy < 64)       { M = x;   out = g_amax_x1; C = 2048; tile = yy; }
    else if (yy < 128) { M = guw; out = g_amax_w1; C = 2048; tile = yy - 64; }
    else               { M = dw;  out = g_amax_w2; C = 1024; tile = yy - 128; }
    int cg = (C == 2048) ? (tile & 1) : 0;
    int rg = (C == 2048) ? (tile >> 1) : tile;
    int c0 = cg * 1024 + threadIdx.x * 4;
    const float4* p = (const float4*)(M + (long)e * 2048 * C + (long)rg * 64 * C + c0);
    long str = C >> 2;
    float4 m = make_float4(0.f, 0.f, 0.f, 0.f);
#pragma unroll 8
    for (int r = 0; r < 64; ++r) {
        float4 v = p[(long)r * str];
        m.x = fmaxf(m.x, fabsf(v.x)); m.y = fmaxf(m.y, fabsf(v.y));
        m.z = fmaxf(m.z, fabsf(v.z)); m.w = fmaxf(m.w, fabsf(v.w));
    }
    unsigned int* o = (unsigned int*)(out + e * C + c0);
    atomicMax(o + 0, __float_as_uint(m.x));
    atomicMax(o + 1, __float_as_uint(m.y));
    atomicMax(o + 2, __float_as_uint(m.z));
    atomicMax(o + 3, __float_as_uint(m.w));
}

// ---------------- smooth scale + zero amax for next graph replay -------------
__global__ void smooth_scale_zero_kernel(float* __restrict__ ax,
                                         float* __restrict__ aw,
                                         float* __restrict__ s, int n) {
    int i = blockIdx.x * 256 + threadIdx.x;
    if (i < n) {
        float v = sqrtf(fmaxf(ax[i], EPS_) / fmaxf(aw[i], EPS_));
        s[i] = fmaxf(v, EPS_);
        ax[i] = 0.f;   // reset for next replay (producers re-run before readers)
        aw[i] = 0.f;
    }
}

// ---------------- per-row quantization: warp-per-row, single-pass, registers --
// rows [0,Rw): weights (v = W*s); rows [Rw,Rw+Rx): activations (v = X/s).
// block = 8 warps = 8 rows; grid ((Rw+Rx)/8, E). C compile-time.
template <int C>
__global__ void quant_warp_kernel(const float* __restrict__ W, const float* __restrict__ X,
                                  const float* __restrict__ s,
                                  __nv_bfloat16* __restrict__ qw, __nv_bfloat16* __restrict__ qx,
                                  float* __restrict__ rsw, float* __restrict__ rsx,
                                  int Rw, int Rx) {
    constexpr int NV = C / 128;   // float4 quads per lane
    int e = blockIdx.y;
    int wid = threadIdx.x >> 5, lane = threadIdx.x & 31;
    int rg = blockIdx.x * 8 + wid;
    int mul = (rg < Rw);
    int r = mul ? rg : rg - Rw;
    int R = mul ? Rw : Rx;
    const float* row = (mul ? W : X) + ((long)e * R + r) * (long)C;
    const float* sv  = s + (long)e * C;

    float4 v[NV];
    float m = 0.f;
#pragma unroll
    for (int i = 0; i < NV; ++i) {
        int c = lane * 4 + i * 128;
        float4 rv = *(const float4*)(row + c);
        float4 svv = *(const float4*)(sv + c);
        float4 vv;
        if (mul) { vv.x = rv.x * svv.x; vv.y = rv.y * svv.y; vv.z = rv.z * svv.z; vv.w = rv.w * svv.w; }
        else     { vv.x = rv.x / svv.x; vv.y = rv.y / svv.y; vv.z = rv.z / svv.z; vv.w = rv.w / svv.w; }
        v[i] = vv;
        m = fmaxf(m, fmaxf(fmaxf(fabsf(vv.x), fabsf(vv.y)), fmaxf(fabsf(vv.z), fabsf(vv.w))));
    }
#pragma unroll
    for (int off = 16; off > 0; off >>= 1)
        m = fmaxf(m, __shfl_xor_sync(0xFFFFFFFFu, m, off));
    float scale = fmaxf(m, EPS_) * (1.0f / QMAX_);
    if (lane == 0) (mul ? rsw : rsx)[(long)e * R + r] = scale;

    __nv_bfloat16* qr = (mul ? qw : qx) + ((long)e * R + r) * (long)C;
#pragma unroll
    for (int i = 0; i < NV; ++i) {
        int c = lane * 4 + i * 128;
        float q0 = fminf(fmaxf(rintf(v[i].x / scale), -QMAX_), QMAX_);
        float q1 = fminf(fmaxf(rintf(v[i].y / scale), -QMAX_), QMAX_);
        float q2 = fminf(fmaxf(rintf(v[i].z / scale), -QMAX_), QMAX_);
        float q3 = fminf(fmaxf(rintf(v[i].w / scale), -QMAX_), QMAX_);
        __nv_bfloat162 p0 = __floats2bfloat162_rn(q0, q1);
        __nv_bfloat162 p1 = __floats2bfloat162_rn(q2, q3);
        uint2 st;
        st.x = *(uint32_t*)&p0;
        st.y = *(uint32_t*)&p1;
        *(uint2*)(qr + c) = st;
    }
}

// ---------------- GEMM1 + SwiGLU fused (tcgen05, M=256) -----------------------
// CTA: 256 token-rows x 128 I-cols. TMEM 512 cols: gate_m0@0, up_m0@128,
// gate_m1@256, up_m1@384. Stage = A0+A1+Bg+Bu = 64KB, 3-stage ring.
#define F1STAGES 3
#define F1STAGE_BYTES 65536
#define F1SMEM_BYTES (F1STAGES * F1STAGE_BYTES + 1024)

__global__ void __launch_bounds__(256, 1)
gemm1_swiglu_tc(const __nv_bfloat16* __restrict__ A, const __nv_bfloat16* __restrict__ B,
                const float* __restrict__ asc_, const float* __restrict__ bsc_) {
    extern __shared__ int8_t dynraw[];
    const int tid = threadIdx.x;
    const int e = blockIdx.z;
    const int m0 = blockIdx.y * 256, n0 = blockIdx.x * 128;
#if USE_TC
    __shared__ __align__(16) uint64_t mbar_store[F1STAGES];
    __shared__ uint32_t tmem_addr_sh;
    __shared__ float cmax[128];

    const uint32_t sbase = (smem_u32(dynraw) + 1023u) & ~1023u;
    const uint32_t mbar0 = smem_u32(&mbar_store[0]);
    const int wid = tid >> 5;
    const int lane = tid & 31;

    const long Kb = (long)D_ * 2;
    const int8_t* Ae = (const int8_t*)(A + (long)e * T_ * D_ + (long)m0 * D_);
    const int8_t* Bg = (const int8_t*)(B + (long)e * TWOI_ * D_ + (long)n0 * D_);
    const int8_t* Bu = (const int8_t*)(B + (long)e * TWOI_ * D_ + (long)(n0 + I_) * D_);

    if (wid == 0) {
        TCGEN05_ALLOC(smem_u32(&tmem_addr_sh), 512);
        TCGEN05_RELINQUISH();
    }
    if (tid == 0) {
#pragma unroll
        for (int s = 0; s < F1STAGES; ++s) MBARRIER_INIT(mbar0 + 8 * s, 1);
    }
    for (int i = tid; i < 128; i += 256) cmax[i] = 0.f;
    __syncthreads();
    const uint32_t tmem = tmem_addr_sh;

    const int nchunks = D_ >> 6;   // 32 chunks of 64 K-elements (128B)

    auto load_chunk = [&](int j) {
        uint32_t base = sbase + (uint32_t)(j % F1STAGES) * F1STAGE_BYTES;
        long koffb = (long)j << 7;
#pragma unroll
        for (int q = 0; q < 4; ++q) {
            int idx = tid * 4 + q;
            int row = idx >> 3, c16 = idx & 7;
            uint32_t off = (uint32_t)(row * 128 + c16 * 16);
            uint32_t sw = off ^ ((off >> 3) & 0x70);
            long go = (long)row * Kb + koffb + c16 * 16;
            CP16(base + sw,         Ae + go);                    // A0
            CP16(base + 16384 + sw, Ae + 128 * Kb + go);         // A1
            CP16(base + 32768 + sw, Bg + go);                    // Bg
            CP16(base + 49152 + sw, Bu + go);                    // Bu
        }
        asm volatile("cp.async.commit_group;\n");
    };

    for (int j = 0; j < F1STAGES - 1; ++j) load_chunk(j);

    for (int it = 0; it < nchunks; ++it) {
        if (it + 2 <= nchunks)
            asm volatile("cp.async.wait_group 1;\n");
        else
            asm volatile("cp.async.wait_group 0;\n");
        __syncthreads();

        if (wid == 0 && elect_one_pred()) {
            FENCE_PROXY_ASYNC();
            uint32_t base = sbase + (uint32_t)(it % F1STAGES) * F1STAGE_BYTES;
            uint64_t a0 = MAKE_SMEM_DESC(base);
            uint64_t a1 = MAKE_SMEM_DESC(base + 16384);
            uint64_t gd = MAKE_SMEM_DESC(base + 32768);
            uint64_t ud = MAKE_SMEM_DESC(base + 49152);
            bool acc0 = (it > 0);
#pragma unroll
            for (int ks = 0; ks < 4; ++ks) {
                bool acc = acc0 || (ks > 0);
                tcgen05_mma_f16_ss(tmem,       a0 + ks * 2, gd + ks * 2, IDESC_BF16, acc);
                tcgen05_mma_f16_ss(tmem + 128, a0 + ks * 2, ud + ks * 2, IDESC_BF16, acc);
                tcgen05_mma_f16_ss(tmem + 256, a1 + ks * 2, gd + ks * 2, IDESC_BF16, acc);
                tcgen05_mma_f16_ss(tmem + 384, a1 + ks * 2, ud + ks * 2, IDESC_BF16, acc);
            }
            TCGEN05_COMMIT(mbar0 + 8 * (it % F1STAGES));
        }

        int j = it + F1STAGES - 1;
        if (j < nchunks) {
            if (j >= F1STAGES)
                MBARRIER_WAIT_PARITY(mbar0 + 8 * (j % F1STAGES),
                                     ((j - F1STAGES) / F1STAGES) & 1);
            load_chunk(j);
        }
    }

    MBARRIER_WAIT_PARITY(mbar0 + 8 * ((nchunks - 1) % F1STAGES),
                         ((nchunks - 1) / F1STAGES) & 1);
    TCGEN05_FENCE_AFTER();

    // epilogue: warp -> m-tile (wid>>2), subpartition rows (wid&3)*32+lane
    {
        int mt = wid >> 2;
        uint32_t tb = tmem + mt * 256;
        long t = m0 + mt * 128 + (wid & 3) * 32 + lane;
        float as = asc_[(long)e * T_ + t];
        float* dstrow = g_a + ((long)e * T_ + t) * (long)I_ + n0;
        const float* bsg = bsc_ + (long)e * TWOI_ + n0;
        const float* bsu = bsc_ + (long)e * TWOI_ + n0 + I_;
#pragma unroll
        for (int part = 0; part < 4; ++part) {
            uint32_t dg[32], du[32];
            TCGEN05_LD_32X32B_X32(dg, tb + part * 32);
            TCGEN05_LD_32X32B_X32(du, tb + 128 + part * 32);
            TCGEN05_WAIT_LD();
            float amx[32];
#pragma unroll
            for (int c = 0; c < 32; c += 4) {
                float4 v;
#pragma unroll
                for (int j2 = 0; j2 < 4; ++j2) {
                    int cc = c + j2;
                    float gv = __uint_as_float(dg[cc]) * as * bsg[part * 32 + cc];
                    float uv = __uint_as_float(du[cc]) * as * bsu[part * 32 + cc];
                    float vv = (gv / (1.0f + expf(-gv))) * uv;
                    ((float*)&v)[j2] = vv;
                    amx[cc] = fabsf(vv);
                }
                *(float4*)(dstrow + part * 32 + c) = v;
            }
#pragma unroll
            for (int c = 0; c < 32; ++c) {
#pragma unroll
                for (int off = 16; off > 0; off >>= 1)
                    amx[c] = fmaxf(amx[c], __shfl_xor_sync(0xFFFFFFFFu, amx[c], off));
            }
            atomicMax((unsigned int*)&cmax[part * 32 + lane],
                      __float_as_uint(amx[lane]));
        }
        TCGEN05_FENCE_BEFORE();
    }
    __syncthreads();
    if (tid < 128)
        atomicMax((unsigned int*)(g_amax_a + (long)e * I_ + n0 + tid),
                  __float_as_uint(cmax[tid]));
    if (wid == 0) {
        TCGEN05_DEALLOC(tmem, 512);
    }
#else
    // naive fallback (never selected on sm_103a; correctness-preserving)
    for (int idx = tid; idx < 256 * 128; idx += 256) {
        int i = idx >> 7, j = idx & 127;
        long t = m0 + i;
        int n = n0 + j;
        const __nv_bfloat16* ar = A + (long)e * T_ * D_ + t * (long)D_;
        const __nv_bfloat16* bg = B + (long)e * TWOI_ * D_ + (long)n * D_;
        const __nv_bfloat16* bu = B + (long)e * TWOI_ * D_ + (long)(n + I_) * D_;
        float sg = 0.f, su = 0.f;
        for (int k = 0; k < D_; ++k) {
            float av = __bfloat162float(ar[k]);
            sg = fmaf(av, __bfloat162float(bg[k]), sg);
            su = fmaf(av, __bfloat162float(bu[k]), su);
        }
        float as = asc_[(long)e * T_ + t];
        float gv = sg * as * bsc_[(long)e * TWOI_ + n];
        float uv = su * as * bsc_[(long)e * TWOI_ + n + I_];
        float vv = (gv / (1.0f + expf(-gv))) * uv;
        g_a[((long)e * T_ + t) * I_ + n] = vv;
        atomicMax((unsigned int*)(g_amax_a + (long)e * I_ + n),
                  __float_as_uint(fabsf(vv)));
    }
#endif
}

// ---------------- GEMM2 (tcgen05, M=256 x N=256) ------------------------------
// TMEM: D00@0, D01@128, D10@256, D11@384. Stage = A0+A1+B0+B1 = 64KB, 3 stages.
#define G2STAGES 3
#define G2STAGE_BYTES 65536
#define G2SMEM_BYTES (G2STAGES * G2STAGE_BYTES + 1024)

__global__ void __launch_bounds__(256, 1)
gemm2_bf16_tc(const __nv_bfloat16* __restrict__ A, const __nv_bfloat16* __restrict__ B,
              float* __restrict__ Co, const float* __restrict__ asc_,
              const float* __restrict__ bsc_, int M, int N, int K) {
    extern __shared__ int8_t dynraw[];
    const int tid = threadIdx.x;
    const int e = blockIdx.z;
    const int m0 = blockIdx.y * 256, n0 = blockIdx.x * 256;
#if USE_TC
    __shared__ __align__(16) uint64_t mbar_store[G2STAGES];
    __shared__ uint32_t tmem_addr_sh;

    const uint32_t sbase = (smem_u32(dynraw) + 1023u) & ~1023u;
    const uint32_t mbar0 = smem_u32(&mbar_store[0]);
    const int wid = tid >> 5;
    const int lane = tid & 31;

    const long Kb = (long)K * 2;
    const int8_t* Ae = (const int8_t*)(A + (long)e * M * K + (long)m0 * K);
    const int8_t* Be = (const int8_t*)(B + (long)e * N * K + (long)n0 * K);

    if (wid == 0) {
        TCGEN05_ALLOC(smem_u32(&tmem_addr_sh), 512);
        TCGEN05_RELINQUISH();
    }
    if (tid == 0) {
#pragma unroll
        for (int s = 0; s < G2STAGES; ++s) MBARRIER_INIT(mbar0 + 8 * s, 1);
    }
    __syncthreads();
    const uint32_t tmem = tmem_addr_sh;

    const int nchunks = K >> 6;

    auto load_chunk = [&](int j) {
        uint32_t base = sbase + (uint32_t)(j % G2STAGES) * G2STAGE_BYTES;
        long koffb = (long)j << 7;
#pragma unroll
        for (int q = 0; q < 4; ++q) {
            int idx = tid * 4 + q;
            int row = idx >> 3, c16 = idx & 7;
            uint32_t off = (uint32_t)(row * 128 + c16 * 16);
            uint32_t sw = off ^ ((off >> 3) & 0x70);
            long go = (long)row * Kb + koffb + c16 * 16;
            CP16(base + sw,         Ae + go);                    // A0
            CP16(base + 16384 + sw, Ae + 128 * Kb + go);         // A1
            CP16(base + 32768 + sw, Be + go);                    // B0
            CP16(base + 49152 + sw, Be + 128 * Kb + go);         // B1
        }
        asm volatile("cp.async.commit_group;\n");
    };

    for (int j = 0; j < G2STAGES - 1; ++j) load_chunk(j);

    for (int it = 0; it < nchunks; ++it) {
        if (it + 2 <= nchunks)
            asm volatile("cp.async.wait_group 1;\n");
        else
            asm volatile("cp.async.wait_group 0;\n");
        __syncthreads();

        if (wid == 0 && elect_one_pred()) {
            FENCE_PROXY_ASYNC();
            uint32_t base = sbase + (uint32_t)(it % G2STAGES) * G2STAGE_BYTES;
            uint64_t a0 = MAKE_SMEM_DESC(base);
            uint64_t a1 = MAKE_SMEM_DESC(base + 16384);
            uint64_t b0 = MAKE_SMEM_DESC(base + 32768);
            uint64_t b1 = MAKE_SMEM_DESC(base + 49152);
            bool acc0 = (it > 0);
#pragma unroll
            for (int ks = 0; ks < 4; ++ks) {
                bool acc = acc0 || (ks > 0);
                tcgen05_mma_f16_ss(tmem,       a0 + ks * 2, b0 + ks * 2, IDESC_BF16, acc);
                tcgen05_mma_f16_ss(tmem + 128, a0 + ks * 2, b1 + ks * 2, IDESC_BF16, acc);
                tcgen05_mma_f16_ss(tmem + 256, a1 + ks * 2, b0 + ks * 2, IDESC_BF16, acc);
                tcgen05_mma_f16_ss(tmem + 384, a1 + ks * 2, b1 + ks * 2, IDESC_BF16, acc);
            }
            TCGEN05_COMMIT(mbar0 + 8 * (it % G2STAGES));
        }

        int j = it + G2STAGES - 1;
        if (j < nchunks) {
            if (j >= G2STAGES)
                MBARRIER_WAIT_PARITY(mbar0 + 8 * (j % G2STAGES),
                                     ((j - G2STAGES) / G2STAGES) & 1);
            load_chunk(j);
        }
    }

    MBARRIER_WAIT_PARITY(mbar0 + 8 * ((nchunks - 1) % G2STAGES),
                         ((nchunks - 1) / G2STAGES) & 1);
    TCGEN05_FENCE_AFTER();

    // epilogue: warp -> m-tile (wid>>2); 8 parts of 32 cols (n-tiles 0/1)
    {
        int mt = wid >> 2;
        long row = m0 + mt * 128 + (wid & 3) * 32 + lane;
        float as = asc_[(long)e * M + row];
        const float* bs = bsc_ + (long)e * N + n0;
        float* dst = Co + (long)e * M * N + row * N + n0;
#pragma unroll
        for (int part = 0; part < 8; ++part) {
            uint32_t ta = tmem + mt * 256 + ((part >= 4) ? 128 : 0) + (part & 3) * 32;
            uint32_t d0[32];
            TCGEN05_LD_32X32B_X32(d0, ta);
            TCGEN05_WAIT_LD();
#pragma unroll
            for (int c = 0; c < 32; c += 4) {
                float4 v;
                v.x = __uint_as_float(d0[c + 0]) * as * bs[part * 32 + c + 0];
                v.y = __uint_as_float(d0[c + 1]) * as * bs[part * 32 + c + 1];
                v.z = __uint_as_float(d0[c + 2]) * as * bs[part * 32 + c + 2];
                v.w = __uint_as_float(d0[c + 3]) * as * bs[part * 32 + c + 3];
                *(float4*)(dst + part * 32 + c) = v;
            }
        }
        TCGEN05_FENCE_BEFORE();
    }
    __syncthreads();
    if (wid == 0) {
        TCGEN05_DEALLOC(tmem, 512);
    }
#else
    // naive fallback (never selected on sm_103a)
    for (int idx = tid; idx < 256 * 256; idx += 256) {
        int i = idx >> 8, j = idx & 255;
        long r = m0 + i;
        int n = n0 + j;
        const __nv_bfloat16* ar = A + (long)e * M * K + r * (long)K;
        const __nv_bfloat16* br = B + (long)e * N * K + (long)n * K;
        float sum = 0.f;
        for (int k = 0; k < K; ++k)
            sum = fmaf(__bfloat162float(ar[k]), __bfloat162float(br[k]), sum);
        Co[(long)e * M * N + r * N + n] = sum * asc_[(long)e * M + r] * bsc_[(long)e * N + n];
    }
#endif
}

// ---------------- launch ------------------------------------------------------
extern "C" void kernel_launch(void* const* d_in, const int* in_sizes, int n_in,
                              void* d_out, int out_size) {
    const float* x   = (const float*)d_in[0];   // [E, T, D]
    const float* guw = (const float*)d_in[1];   // [E, 2I, D]
    const float* dw  = (const float*)d_in[2];   // [E, D, I]
    float* out = (float*)d_out;                 // [E, T, D]

    __nv_bfloat16 *xq1, *wq1, *aq, *wq2;
    float *a, *ax1, *aw1, *aa, *aw2, *s1, *s2, *xs1, *ws1, *xs2, *ws2;
    cudaGetSymbolAddress((void**)&xq1, g_xq1);
    cudaGetSymbolAddress((void**)&wq1, g_wq1);
    cudaGetSymbolAddress((void**)&aq,  g_aq);
    cudaGetSymbolAddress((void**)&wq2, g_wq2);
    cudaGetSymbolAddress((void**)&a,   g_a);
    cudaGetSymbolAddress((void**)&ax1, g_amax_x1);
    cudaGetSymbolAddress((void**)&aw1, g_amax_w1);
    cudaGetSymbolAddress((void**)&aa,  g_amax_a);
    cudaGetSymbolAddress((void**)&aw2, g_amax_w2);
    cudaGetSymbolAddress((void**)&s1,  g_s1);
    cudaGetSymbolAddress((void**)&s2,  g_s2);
    cudaGetSymbolAddress((void**)&xs1, g_xs1);
    cudaGetSymbolAddress((void**)&ws1, g_ws1);
    cudaGetSymbolAddress((void**)&xs2, g_xs2);
    cudaGetSymbolAddress((void**)&ws2, g_ws2);

    cudaFuncSetAttribute(gemm1_swiglu_tc, cudaFuncAttributeMaxDynamicSharedMemorySize,
                         F1SMEM_BYTES);
    cudaFuncSetAttribute(gemm2_bf16_tc, cudaFuncAttributeMaxDynamicSharedMemorySize,
                         G2SMEM_BYTES);

    // [0] all three column-amax reductions in one concurrent launch
    colmax_all_kernel<<<dim3(1, 160, E_), 256>>>(x, guw, dw);

    // [1] smooth scale s1 (+ zero amax_x1/amax_w1 for next replay)
    smooth_scale_zero_kernel<<<(E_ * D_ + 255) / 256, 256>>>(ax1, aw1, s1, E_ * D_);
    // [2] quantize guw + x (bf16-held integers)
    quant_warp_kernel<D_><<<dim3((TWOI_ + T_) / 8, E_), 256>>>(guw, x, s1, wq1, xq1,
                                                               ws1, xs1, TWOI_, T_);
    // [3] fused GEMM1 + SwiGLU (writes g_a + g_amax_a)  <- ncu-profiled slot
    gemm1_swiglu_tc<<<dim3(I_ / 128, T_ / 256, E_), 256, F1SMEM_BYTES>>>(xq1, wq1,
                                                                         xs1, ws1);

    // [4] smooth scale s2 (+ zero amax_a/amax_w2)
    smooth_scale_zero_kernel<<<(E_ * I_ + 255) / 256, 256>>>(aa, aw2, s2, E_ * I_);
    // [5] quantize dw + a
    quant_warp_kernel<I_><<<dim3((D_ + T_) / 8, E_), 256>>>(dw, a, s2, wq2, aq,
                                                            ws2, xs2, D_, T_);
    // [6] GEMM2 -> out
    gemm2_bf16_tc<<<dim3(D_ / 256, T_ / 256, E_), 256, G2SMEM_BYTES>>>(aq, wq2, out,
                                                                       xs2, ws2,
                                                                       T_, D_, I_);
    (void)in_sizes; (void)n_in; (void)out_size;
}

// round 14
// speedup vs baseline: 3.1288x; 1.0896x over previous
#include <cuda_runtime.h>
#include <cuda.h>
#include <cuda_bf16.h>
#include <cstdint>

// Problem shape (fixed by dataset): E=8, T=2048, D=2048, I=1024
#define E_     8
#define T_     2048
#define D_     2048
#define I_     1024
#define TWOI_  2048
#define EPS_   1e-6f
#define QMAX_  127.0f

// tcgen05/TMA fast path exists only in arch-specific passes (sm_103a/sm_100a).
// sm_103a has NO kind::i8 (ptxas-verified R6) — kind::f16 with bf16-held
// integers (exact for |v|<=127).
#if defined(__CUDA_ARCH__) && defined(__CUDA_ARCH_HAS_FEATURE__)
#  if __CUDA_ARCH_HAS_FEATURE__(SM103_ALL) || __CUDA_ARCH_HAS_FEATURE__(SM100_ALL) || __CUDA_ARCH_HAS_FEATURE__(SM101_ALL)
#    define USE_TC 1
#  endif
#endif
#ifndef USE_TC
#  define USE_TC 0
#endif

// ---------------- scratch (static device globals; no allocation) -------------
__device__ __align__(16) __nv_bfloat16 g_xq1[(long)E_ * T_ * D_];
__device__ __align__(16) __nv_bfloat16 g_wq1[(long)E_ * TWOI_ * D_];
__device__ __align__(16) __nv_bfloat16 g_aq [(long)E_ * T_ * I_];
__device__ __align__(16) __nv_bfloat16 g_wq2[(long)E_ * D_ * I_];
__device__ float  g_a  [(long)E_ * T_ * I_];
__device__ float  g_amax_x1[E_ * D_];
__device__ float  g_amax_w1[E_ * D_];
__device__ float  g_amax_a [E_ * I_];
__device__ float  g_amax_w2[E_ * I_];
__device__ float  g_s1 [E_ * D_];
__device__ float  g_s2 [E_ * I_];
__device__ float  g_xs1[E_ * T_];
__device__ float  g_ws1[E_ * TWOI_];
__device__ float  g_xs2[E_ * T_];
__device__ float  g_ws2[E_ * D_];

// ================= PTX helpers ================================================
__device__ __forceinline__ uint32_t smem_u32(const void* p) {
    return (uint32_t)__cvta_generic_to_shared(p);
}

#if USE_TC
#define MBARRIER_INIT(addr, count) \
    asm volatile("mbarrier.init.shared.b64 [%0], %1;" :: "r"((uint32_t)(addr)), "r"((uint32_t)(count)) : "memory")

#define MBARRIER_EXPECT_TX(addr, bytes) \
    asm volatile("mbarrier.arrive.expect_tx.shared.b64 _, [%0], %1;" \
        :: "r"((uint32_t)(addr)), "r"((uint32_t)(bytes)) : "memory")

#define MBARRIER_WAIT_PARITY(mbar_smem_addr, phase_parity) do { \
    uint32_t _mbar = (uint32_t)(mbar_smem_addr); \
    uint32_t _parity = (uint32_t)(phase_parity); \
    uint32_t _done; \
    asm volatile( \
        "{\n\t.reg .pred p;\n\t" \
        "mbarrier.try_wait.parity.acquire.cta.shared::cta.b64 p, [%1], %2;\n\t" \
        "selp.b32 %0, 1, 0, p;\n\t}" \
        : "=r"(_done) : "r"(_mbar), "r"(_parity) : "memory"); \
    if (!_done) { \
        asm volatile( \
            "{\n\t.reg .pred P1;\n\t" \
            "WAIT_LOOP_%=:\n\t" \
            "mbarrier.try_wait.parity.acquire.cta.shared::cta.b64 P1, [%0], %1, 0x989680;\n\t" \
            "@P1 bra.uni WAIT_DONE_%=;\n\t" \
            "bra.uni WAIT_LOOP_%=;\n\t" \
            "WAIT_DONE_%=:\n\t}" \
            :: "r"(_mbar), "r"(_parity) : "memory"); \
    } \
} while(0)

#define TCGEN05_ALLOC(smem_result_addr, nCols) \
    asm volatile("tcgen05.alloc.cta_group::1.sync.aligned.shared::cta.b32 [%0], %1;" \
        :: "r"((uint32_t)(smem_result_addr)), "r"((uint32_t)(nCols)) : "memory")
#define TCGEN05_DEALLOC(tmem_addr, nCols) \
    asm volatile("tcgen05.dealloc.cta_group::1.sync.aligned.b32 %0, %1;" \
        :: "r"(tmem_addr), "r"((uint32_t)(nCols)))
#define TCGEN05_RELINQUISH() \
    asm volatile("tcgen05.relinquish_alloc_permit.cta_group::1.sync.aligned;")
#define TCGEN05_COMMIT(mbar_smem_addr) \
    asm volatile("tcgen05.commit.cta_group::1.mbarrier::arrive::one.shared::cluster.b64 [%0];" \
        :: "r"((uint32_t)(mbar_smem_addr)) : "memory")
#define TCGEN05_FENCE_AFTER()  asm volatile("tcgen05.fence::after_thread_sync;" ::: "memory")
#define TCGEN05_FENCE_BEFORE() asm volatile("tcgen05.fence::before_thread_sync;" ::: "memory")
#define TCGEN05_WAIT_LD()      asm volatile("tcgen05.wait::ld.sync.aligned;" ::: "memory")

#define TMA_LOAD_2D(smem_addr, tmap, cx, cy, mbar) \
    asm volatile("cp.async.bulk.tensor.2d.shared::cta.global.tile.mbarrier::complete_tx::bytes " \
        "[%0], [%1, {%2, %3}], [%4];" \
        :: "r"((uint32_t)(smem_addr)), "l"(tmap), "r"((int)(cx)), "r"((int)(cy)), \
           "r"((uint32_t)(mbar)) : "memory")

#define TCGEN05_LD_32X32B_X32(r, tmem_addr) \
    asm volatile( \
        "tcgen05.ld.sync.aligned.32x32b.x32.b32 " \
        "{%0, %1, %2, %3, %4, %5, %6, %7, " \
        " %8, %9, %10, %11, %12, %13, %14, %15, " \
        " %16, %17, %18, %19, %20, %21, %22, %23, " \
        " %24, %25, %26, %27, %28, %29, %30, %31}, [%32];" \
        : "=r"((r)[0]),  "=r"((r)[1]),  "=r"((r)[2]),  "=r"((r)[3]), \
          "=r"((r)[4]),  "=r"((r)[5]),  "=r"((r)[6]),  "=r"((r)[7]), \
          "=r"((r)[8]),  "=r"((r)[9]),  "=r"((r)[10]), "=r"((r)[11]), \
          "=r"((r)[12]), "=r"((r)[13]), "=r"((r)[14]), "=r"((r)[15]), \
          "=r"((r)[16]), "=r"((r)[17]), "=r"((r)[18]), "=r"((r)[19]), \
          "=r"((r)[20]), "=r"((r)[21]), "=r"((r)[22]), "=r"((r)[23]), \
          "=r"((r)[24]), "=r"((r)[25]), "=r"((r)[26]), "=r"((r)[27]), \
          "=r"((r)[28]), "=r"((r)[29]), "=r"((r)[30]), "=r"((r)[31]) \
        : "r"(tmem_addr))

// SW128 descriptor (Blackwell, LBO=1, SBO=64; rows are 128 bytes)
static constexpr uint64_t SMEM_DESC_BASE_SW128 =
    (uint64_t(2)  << 61) | (uint64_t(1) << 46) | (uint64_t(64) << 32) | (uint64_t(1) << 16);
#define MAKE_SMEM_DESC(base_addr) \
    (SMEM_DESC_BASE_SW128 | ((uint64_t)((base_addr) >> 4) & 0x3FFF))

// tcgen05 f16 SS MMA (bf16 x bf16 -> f32 TMEM), K=16 per call
__device__ __forceinline__ void tcgen05_mma_f16_ss(
    uint32_t d_tmem, uint64_t a_desc, uint64_t b_desc, uint32_t idesc, bool accum) {
    uint32_t en = accum ? 1u : 0u;
    asm volatile(
        "{\n\t.reg .pred p;\n\t"
        "setp.ne.u32 p, %5, 0;\n\t"
        "tcgen05.mma.cta_group::1.kind::f16 [%0], %1, %2, %3, {%4, %4, %4, %4}, p;\n\t"
        "}"
        :: "r"(d_tmem), "l"(a_desc), "l"(b_desc), "r"(idesc), "r"(0u), "r"(en)
        : "memory");
}

// idesc (kind::f16): dtype=F32(1)<<4, atype=BF16(1)<<7, btype=BF16(1)<<10,
// N/8<<17, M/16<<24.  (Validated vs test_mma.cu 0x8080490, test_2cta_mma_bf16.)
static constexpr uint32_t IDESC_BF16 =
    (1u << 4) | (1u << 7) | (1u << 10) | ((128u / 8) << 17) | ((128u / 16) << 24);
#endif  // USE_TC

// ---------------- merged column abs-max over rows -----------------------------
__global__ void colmax_all_kernel(const float* __restrict__ x,
                                  const float* __restrict__ guw,
                                  const float* __restrict__ dw) {
    int e = blockIdx.z;
    int yy = blockIdx.y;
    const float* M; float* out; int C, tile;
    if (yy < 64)       { M = x;   out = g_amax_x1; C = 2048; tile = yy; }
    else if (yy < 128) { M = guw; out = g_amax_w1; C = 2048; tile = yy - 64; }
    else               { M = dw;  out = g_amax_w2; C = 1024; tile = yy - 128; }
    int cg = (C == 2048) ? (tile & 1) : 0;
    int rg = (C == 2048) ? (tile >> 1) : tile;
    int c0 = cg * 1024 + threadIdx.x * 4;
    const float4* p = (const float4*)(M + (long)e * 2048 * C + (long)rg * 64 * C + c0);
    long str = C >> 2;
    float4 m = make_float4(0.f, 0.f, 0.f, 0.f);
#pragma unroll 8
    for (int r = 0; r < 64; ++r) {
        float4 v = p[(long)r * str];
        m.x = fmaxf(m.x, fabsf(v.x)); m.y = fmaxf(m.y, fabsf(v.y));
        m.z = fmaxf(m.z, fabsf(v.z)); m.w = fmaxf(m.w, fabsf(v.w));
    }
    unsigned int* o = (unsigned int*)(out + e * C + c0);
    atomicMax(o + 0, __float_as_uint(m.x));
    atomicMax(o + 1, __float_as_uint(m.y));
    atomicMax(o + 2, __float_as_uint(m.z));
    atomicMax(o + 3, __float_as_uint(m.w));
}

// ---------------- smooth scale + zero amax for next graph replay -------------
__global__ void smooth_scale_zero_kernel(float* __restrict__ ax,
                                         float* __restrict__ aw,
                                         float* __restrict__ s, int n) {
    int i = blockIdx.x * 256 + threadIdx.x;
    if (i < n) {
        float v = sqrtf(fmaxf(ax[i], EPS_) / fmaxf(aw[i], EPS_));
        s[i] = fmaxf(v, EPS_);
        ax[i] = 0.f;
        aw[i] = 0.f;
    }
}

// ---------------- per-row quantization: warp-per-row, single-pass, registers --
template <int C>
__global__ void quant_warp_kernel(const float* __restrict__ W, const float* __restrict__ X,
                                  const float* __restrict__ s,
                                  __nv_bfloat16* __restrict__ qw, __nv_bfloat16* __restrict__ qx,
                                  float* __restrict__ rsw, float* __restrict__ rsx,
                                  int Rw, int Rx) {
    constexpr int NV = C / 128;
    int e = blockIdx.y;
    int wid = threadIdx.x >> 5, lane = threadIdx.x & 31;
    int rg = blockIdx.x * 8 + wid;
    int mul = (rg < Rw);
    int r = mul ? rg : rg - Rw;
    int R = mul ? Rw : Rx;
    const float* row = (mul ? W : X) + ((long)e * R + r) * (long)C;
    const float* sv  = s + (long)e * C;

    float4 v[NV];
    float m = 0.f;
#pragma unroll
    for (int i = 0; i < NV; ++i) {
        int c = lane * 4 + i * 128;
        float4 rv = *(const float4*)(row + c);
        float4 svv = *(const float4*)(sv + c);
        float4 vv;
        if (mul) { vv.x = rv.x * svv.x; vv.y = rv.y * svv.y; vv.z = rv.z * svv.z; vv.w = rv.w * svv.w; }
        else     { vv.x = rv.x / svv.x; vv.y = rv.y / svv.y; vv.z = rv.z / svv.z; vv.w = rv.w / svv.w; }
        v[i] = vv;
        m = fmaxf(m, fmaxf(fmaxf(fabsf(vv.x), fabsf(vv.y)), fmaxf(fabsf(vv.z), fabsf(vv.w))));
    }
#pragma unroll
    for (int off = 16; off > 0; off >>= 1)
        m = fmaxf(m, __shfl_xor_sync(0xFFFFFFFFu, m, off));
    float scale = fmaxf(m, EPS_) * (1.0f / QMAX_);
    if (lane == 0) (mul ? rsw : rsx)[(long)e * R + r] = scale;

    __nv_bfloat16* qr = (mul ? qw : qx) + ((long)e * R + r) * (long)C;
#pragma unroll
    for (int i = 0; i < NV; ++i) {
        int c = lane * 4 + i * 128;
        float q0 = fminf(fmaxf(rintf(v[i].x / scale), -QMAX_), QMAX_);
        float q1 = fminf(fmaxf(rintf(v[i].y / scale), -QMAX_), QMAX_);
        float q2 = fminf(fmaxf(rintf(v[i].z / scale), -QMAX_), QMAX_);
        float q3 = fminf(fmaxf(rintf(v[i].w / scale), -QMAX_), QMAX_);
        __nv_bfloat162 p0 = __floats2bfloat162_rn(q0, q1);
        __nv_bfloat162 p1 = __floats2bfloat162_rn(q2, q3);
        uint2 st;
        st.x = *(uint32_t*)&p0;
        st.y = *(uint32_t*)&p1;
        *(uint2*)(qr + c) = st;
    }
}

// ---------------- GEMM1 + SwiGLU fused (tcgen05 + TMA, M=256) -----------------
// TMA fills (box 64 bf16 x 128 rows = 16KB, SW128). Stage = A0+A1+Bg+Bu = 64KB,
// 3-stage ring. Single-thread control (tid0): expect_tx + 4 TMA loads, wait
// full parity, 16 MMAs, commit done-barrier. IMPORTANT: only tid0 — which has
// tracked every barrier phase — may wait the FINAL done parity (parity waits
// cannot skip phases); everyone else meets at __syncthreads().
// TMEM 512 cols: gate_m0@0, up_m0@128, gate_m1@256, up_m1@384.
#define F1STAGES 3
#define F1STAGE_BYTES 65536
#define F1SMEM_BYTES (F1STAGES * F1STAGE_BYTES + 1024)

__global__ void __launch_bounds__(256, 1)
gemm1_swiglu_tc(const __grid_constant__ CUtensorMap tmA,
                const __grid_constant__ CUtensorMap tmB,
                const __nv_bfloat16* __restrict__ A, const __nv_bfloat16* __restrict__ B,
                const float* __restrict__ asc_, const float* __restrict__ bsc_) {
    extern __shared__ int8_t dynraw[];
    const int tid = threadIdx.x;
    const int e = blockIdx.z;
    const int m0 = blockIdx.y * 256, n0 = blockIdx.x * 128;
#if USE_TC
    __shared__ __align__(16) uint64_t mbar_store[2 * F1STAGES];   // full 0..2, done 3..5
    __shared__ uint32_t tmem_addr_sh;
    __shared__ float cmax[128];

    const uint32_t sbase = (smem_u32(dynraw) + 1023u) & ~1023u;
    const uint32_t mbar0 = smem_u32(&mbar_store[0]);
    const int wid = tid >> 5;
    const int lane = tid & 31;
    const int nchunks = D_ >> 6;   // 32

    if (wid == 0) {
        TCGEN05_ALLOC(smem_u32(&tmem_addr_sh), 512);
        TCGEN05_RELINQUISH();
    }
    if (tid == 0) {
#pragma unroll
        for (int s = 0; s < 2 * F1STAGES; ++s) MBARRIER_INIT(mbar0 + 8 * s, 1);
    }
    for (int i = tid; i < 128; i += 256) cmax[i] = 0.f;
    __syncthreads();
    const uint32_t tmem = tmem_addr_sh;

    if (tid == 0) {
        const int rowA = e * T_ + m0;
        const int rowG = e * TWOI_ + n0;
        const int rowU = rowG + I_;
        auto issue = [&](int j) {
            int s = j % F1STAGES;
            uint32_t base = sbase + (uint32_t)s * F1STAGE_BYTES;
            uint32_t fb = mbar0 + 8 * s;
            MBARRIER_EXPECT_TX(fb, F1STAGE_BYTES);
            int cx = j * 64;
            TMA_LOAD_2D(base,         &tmA, cx, rowA,       fb);
            TMA_LOAD_2D(base + 16384, &tmA, cx, rowA + 128, fb);
            TMA_LOAD_2D(base + 32768, &tmB, cx, rowG,       fb);
            TMA_LOAD_2D(base + 49152, &tmB, cx, rowU,       fb);
        };
        for (int j = 0; j < F1STAGES - 1; ++j) issue(j);
        for (int it = 0; it < nchunks; ++it) {
            int s = it % F1STAGES;
            MBARRIER_WAIT_PARITY(mbar0 + 8 * s, (it / F1STAGES) & 1);
            uint32_t base = sbase + (uint32_t)s * F1STAGE_BYTES;
            uint64_t a0 = MAKE_SMEM_DESC(base);
            uint64_t a1 = MAKE_SMEM_DESC(base + 16384);
            uint64_t gd = MAKE_SMEM_DESC(base + 32768);
            uint64_t ud = MAKE_SMEM_DESC(base + 49152);
            bool acc0 = (it > 0);
#pragma unroll
            for (int ks = 0; ks < 4; ++ks) {
                bool acc = acc0 || (ks > 0);
                tcgen05_mma_f16_ss(tmem,       a0 + ks * 2, gd + ks * 2, IDESC_BF16, acc);
                tcgen05_mma_f16_ss(tmem + 128, a0 + ks * 2, ud + ks * 2, IDESC_BF16, acc);
                tcgen05_mma_f16_ss(tmem + 256, a1 + ks * 2, gd + ks * 2, IDESC_BF16, acc);
                tcgen05_mma_f16_ss(tmem + 384, a1 + ks * 2, ud + ks * 2, IDESC_BF16, acc);
            }
            TCGEN05_COMMIT(mbar0 + 8 * (F1STAGES + s));
            int j = it + F1STAGES - 1;
            if (j < nchunks) {
                if (j >= F1STAGES)
                    MBARRIER_WAIT_PARITY(mbar0 + 8 * (F1STAGES + j % F1STAGES),
                                         ((j - F1STAGES) / F1STAGES) & 1);
                issue(j);
            }
        }
        // FINAL done wait by tid0 only — for tid0 this is the immediate next
        // phase of this barrier (it last waited n=9, final commit is n=10).
        MBARRIER_WAIT_PARITY(mbar0 + 8 * (F1STAGES + (nchunks - 1) % F1STAGES),
                             ((nchunks - 1) / F1STAGES) & 1);
    }
    // block-wide rendezvous: everyone else parks here until tid0 confirms
    // the last MMA completed; then the fence publishes TMEM to all threads.
    __syncthreads();
    TCGEN05_FENCE_AFTER();

    // epilogue: warp -> m-tile (wid>>2), subpartition rows (wid&3)*32+lane
    {
        int mt = wid >> 2;
        uint32_t tb = tmem + mt * 256;
        long t = m0 + mt * 128 + (wid & 3) * 32 + lane;
        float as = asc_[(long)e * T_ + t];
        float* dstrow = g_a + ((long)e * T_ + t) * (long)I_ + n0;
        const float* bsg = bsc_ + (long)e * TWOI_ + n0;
        const float* bsu = bsc_ + (long)e * TWOI_ + n0 + I_;
#pragma unroll
        for (int part = 0; part < 4; ++part) {
            uint32_t dg[32], du[32];
            TCGEN05_LD_32X32B_X32(dg, tb + part * 32);
            TCGEN05_LD_32X32B_X32(du, tb + 128 + part * 32);
            TCGEN05_WAIT_LD();
            float amx[32];
#pragma unroll
            for (int c = 0; c < 32; c += 4) {
                float4 v;
#pragma unroll
                for (int j2 = 0; j2 < 4; ++j2) {
                    int cc = c + j2;
                    float gv = __uint_as_float(dg[cc]) * as * bsg[part * 32 + cc];
                    float uv = __uint_as_float(du[cc]) * as * bsu[part * 32 + cc];
                    float vv = (gv / (1.0f + expf(-gv))) * uv;
                    ((float*)&v)[j2] = vv;
                    amx[cc] = fabsf(vv);
                }
                *(float4*)(dstrow + part * 32 + c) = v;
            }
#pragma unroll
            for (int c = 0; c < 32; ++c) {
#pragma unroll
                for (int off = 16; off > 0; off >>= 1)
                    amx[c] = fmaxf(amx[c], __shfl_xor_sync(0xFFFFFFFFu, amx[c], off));
            }
            atomicMax((unsigned int*)&cmax[part * 32 + lane],
                      __float_as_uint(amx[lane]));
        }
        TCGEN05_FENCE_BEFORE();
    }
    __syncthreads();
    if (tid < 128)
        atomicMax((unsigned int*)(g_amax_a + (long)e * I_ + n0 + tid),
                  __float_as_uint(cmax[tid]));
    if (wid == 0) {
        TCGEN05_DEALLOC(tmem, 512);
    }
#else
    // naive fallback (never selected on sm_103a; correctness-preserving)
    for (int idx = tid; idx < 256 * 128; idx += 256) {
        int i = idx >> 7, j = idx & 127;
        long t = m0 + i;
        int n = n0 + j;
        const __nv_bfloat16* ar = A + (long)e * T_ * D_ + t * (long)D_;
        const __nv_bfloat16* bg = B + (long)e * TWOI_ * D_ + (long)n * D_;
        const __nv_bfloat16* bu = B + (long)e * TWOI_ * D_ + (long)(n + I_) * D_;
        float sg = 0.f, su = 0.f;
        for (int k = 0; k < D_; ++k) {
            float av = __bfloat162float(ar[k]);
            sg = fmaf(av, __bfloat162float(bg[k]), sg);
            su = fmaf(av, __bfloat162float(bu[k]), su);
        }
        float as = asc_[(long)e * T_ + t];
        float gv = sg * as * bsc_[(long)e * TWOI_ + n];
        float uv = su * as * bsc_[(long)e * TWOI_ + n + I_];
        float vv = (gv / (1.0f + expf(-gv))) * uv;
        g_a[((long)e * T_ + t) * I_ + n] = vv;
        atomicMax((unsigned int*)(g_amax_a + (long)e * I_ + n),
                  __float_as_uint(fabsf(vv)));
    }
#endif
}

// ---------------- GEMM2 (tcgen05 + TMA, M=256 x N=256) ------------------------
#define G2STAGES 3
#define G2STAGE_BYTES 65536
#define G2SMEM_BYTES (G2STAGES * G2STAGE_BYTES + 1024)

__global__ void __launch_bounds__(256, 1)
gemm2_bf16_tc(const __grid_constant__ CUtensorMap tmA,
              const __grid_constant__ CUtensorMap tmB,
              const __nv_bfloat16* __restrict__ A, const __nv_bfloat16* __restrict__ B,
              float* __restrict__ Co, const float* __restrict__ asc_,
              const float* __restrict__ bsc_) {
    extern __shared__ int8_t dynraw[];
    const int tid = threadIdx.x;
    const int e = blockIdx.z;
    const int m0 = blockIdx.y * 256, n0 = blockIdx.x * 256;
    const int M = T_, N = D_, K = I_;
#if USE_TC
    __shared__ __align__(16) uint64_t mbar_store[2 * G2STAGES];
    __shared__ uint32_t tmem_addr_sh;

    const uint32_t sbase = (smem_u32(dynraw) + 1023u) & ~1023u;
    const uint32_t mbar0 = smem_u32(&mbar_store[0]);
    const int wid = tid >> 5;
    const int lane = tid & 31;
    const int nchunks = K >> 6;   // 16

    if (wid == 0) {
        TCGEN05_ALLOC(smem_u32(&tmem_addr_sh), 512);
        TCGEN05_RELINQUISH();
    }
    if (tid == 0) {
#pragma unroll
        for (int s = 0; s < 2 * G2STAGES; ++s) MBARRIER_INIT(mbar0 + 8 * s, 1);
    }
    __syncthreads();
    const uint32_t tmem = tmem_addr_sh;

    if (tid == 0) {
        const int rowA = e * M + m0;
        const int rowB = e * N + n0;
        auto issue = [&](int j) {
            int s = j % G2STAGES;
            uint32_t base = sbase + (uint32_t)s * G2STAGE_BYTES;
            uint32_t fb = mbar0 + 8 * s;
            MBARRIER_EXPECT_TX(fb, G2STAGE_BYTES);
            int cx = j * 64;
            TMA_LOAD_2D(base,         &tmA, cx, rowA,       fb);
            TMA_LOAD_2D(base + 16384, &tmA, cx, rowA + 128, fb);
            TMA_LOAD_2D(base + 32768, &tmB, cx, rowB,       fb);
            TMA_LOAD_2D(base + 49152, &tmB, cx, rowB + 128, fb);
        };
        for (int j = 0; j < G2STAGES - 1; ++j) issue(j);
        for (int it = 0; it < nchunks; ++it) {
            int s = it % G2STAGES;
            MBARRIER_WAIT_PARITY(mbar0 + 8 * s, (it / G2STAGES) & 1);
            uint32_t base = sbase + (uint32_t)s * G2STAGE_BYTES;
            uint64_t a0 = MAKE_SMEM_DESC(base);
            uint64_t a1 = MAKE_SMEM_DESC(base + 16384);
            uint64_t b0 = MAKE_SMEM_DESC(base + 32768);
            uint64_t b1 = MAKE_SMEM_DESC(base + 49152);
            bool acc0 = (it > 0);
#pragma unroll
            for (int ks = 0; ks < 4; ++ks) {
                bool acc = acc0 || (ks > 0);
                tcgen05_mma_f16_ss(tmem,       a0 + ks * 2, b0 + ks * 2, IDESC_BF16, acc);
                tcgen05_mma_f16_ss(tmem + 128, a0 + ks * 2, b1 + ks * 2, IDESC_BF16, acc);
                tcgen05_mma_f16_ss(tmem + 256, a1 + ks * 2, b0 + ks * 2, IDESC_BF16, acc);
                tcgen05_mma_f16_ss(tmem + 384, a1 + ks * 2, b1 + ks * 2, IDESC_BF16, acc);
            }
            TCGEN05_COMMIT(mbar0 + 8 * (G2STAGES + s));
            int j = it + G2STAGES - 1;
            if (j < nchunks) {
                if (j >= G2STAGES)
                    MBARRIER_WAIT_PARITY(mbar0 + 8 * (G2STAGES + j % G2STAGES),
                                         ((j - G2STAGES) / G2STAGES) & 1);
                issue(j);
            }
        }
        // FINAL done wait by tid0 only (immediate next phase for tid0).
        MBARRIER_WAIT_PARITY(mbar0 + 8 * (G2STAGES + (nchunks - 1) % G2STAGES),
                             ((nchunks - 1) / G2STAGES) & 1);
    }
    __syncthreads();
    TCGEN05_FENCE_AFTER();

    // epilogue: warp -> m-tile (wid>>2); 8 parts of 32 cols (n-tiles 0/1)
    {
        int mt = wid >> 2;
        long row = m0 + mt * 128 + (wid & 3) * 32 + lane;
        float as = asc_[(long)e * M + row];
        const float* bs = bsc_ + (long)e * N + n0;
        float* dst = Co + (long)e * M * N + row * N + n0;
#pragma unroll
        for (int part = 0; part < 8; ++part) {
            uint32_t ta = tmem + mt * 256 + ((part >= 4) ? 128 : 0) + (part & 3) * 32;
            uint32_t d0[32];
            TCGEN05_LD_32X32B_X32(d0, ta);
            TCGEN05_WAIT_LD();
#pragma unroll
            for (int c = 0; c < 32; c += 4) {
                float4 v;
                v.x = __uint_as_float(d0[c + 0]) * as * bs[part * 32 + c + 0];
                v.y = __uint_as_float(d0[c + 1]) * as * bs[part * 32 + c + 1];
                v.z = __uint_as_float(d0[c + 2]) * as * bs[part * 32 + c + 2];
                v.w = __uint_as_float(d0[c + 3]) * as * bs[part * 32 + c + 3];
                *(float4*)(dst + part * 32 + c) = v;
            }
        }
        TCGEN05_FENCE_BEFORE();
    }
    __syncthreads();
    if (wid == 0) {
        TCGEN05_DEALLOC(tmem, 512);
    }
#else
    // naive fallback (never selected on sm_103a)
    for (int idx = tid; idx < 256 * 256; idx += 256) {
        int i = idx >> 8, j = idx & 255;
        long r = m0 + i;
        int n = n0 + j;
        const __nv_bfloat16* ar = A + (long)e * M * K + r * (long)K;
        const __nv_bfloat16* br = B + (long)e * N * K + (long)n * K;
        float sum = 0.f;
        for (int k = 0; k < K; ++k)
            sum = fmaf(__bfloat162float(ar[k]), __bfloat162float(br[k]), sum);
        Co[(long)e * M * N + r * N + n] = sum * asc_[(long)e * M + r] * bsc_[(long)e * N + n];
    }
#endif
}

// ---------------- host: tensor-map encode via runtime entry point ------------
typedef CUresult (*TmEncodeFn)(CUtensorMap*, CUtensorMapDataType, cuuint32_t,
    void*, const cuuint64_t*, const cuuint64_t*, const cuuint32_t*, const cuuint32_t*,
    CUtensorMapInterleave, CUtensorMapSwizzle, CUtensorMapL2promotion,
    CUtensorMapFloatOOBfill);

static void make_tm_bf16(TmEncodeFn enc, CUtensorMap* tm, void* base,
                         unsigned dim0, unsigned long long rows) {
    cuuint64_t dims[2] = {(cuuint64_t)dim0, (cuuint64_t)rows};
    cuuint64_t strides[1] = {(cuuint64_t)dim0 * 2};
    cuuint32_t box[2] = {64, 128};        // 64 bf16 = 128B (SW128 span) x 128 rows
    cuuint32_t estr[2] = {1, 1};
    enc(tm, CU_TENSOR_MAP_DATA_TYPE_BFLOAT16, 2, base, dims, strides, box, estr,
        CU_TENSOR_MAP_INTERLEAVE_NONE, CU_TENSOR_MAP_SWIZZLE_128B,
        CU_TENSOR_MAP_L2_PROMOTION_L2_128B, CU_TENSOR_MAP_FLOAT_OOB_FILL_NONE);
}

// ---------------- launch ------------------------------------------------------
extern "C" void kernel_launch(void* const* d_in, const int* in_sizes, int n_in,
                              void* d_out, int out_size) {
    const float* x   = (const float*)d_in[0];   // [E, T, D]
    const float* guw = (const float*)d_in[1];   // [E, 2I, D]
    const float* dw  = (const float*)d_in[2];   // [E, D, I]
    float* out = (float*)d_out;                 // [E, T, D]

    __nv_bfloat16 *xq1, *wq1, *aq, *wq2;
    float *a, *ax1, *aw1, *aa, *aw2, *s1, *s2, *xs1, *ws1, *xs2, *ws2;
    cudaGetSymbolAddress((void**)&xq1, g_xq1);
    cudaGetSymbolAddress((void**)&wq1, g_wq1);
    cudaGetSymbolAddress((void**)&aq,  g_aq);
    cudaGetSymbolAddress((void**)&wq2, g_wq2);
    cudaGetSymbolAddress((void**)&a,   g_a);
    cudaGetSymbolAddress((void**)&ax1, g_amax_x1);
    cudaGetSymbolAddress((void**)&aw1, g_amax_w1);
    cudaGetSymbolAddress((void**)&aa,  g_amax_a);
    cudaGetSymbolAddress((void**)&aw2, g_amax_w2);
    cudaGetSymbolAddress((void**)&s1,  g_s1);
    cudaGetSymbolAddress((void**)&s2,  g_s2);
    cudaGetSymbolAddress((void**)&xs1, g_xs1);
    cudaGetSymbolAddress((void**)&ws1, g_ws1);
    cudaGetSymbolAddress((void**)&xs2, g_xs2);
    cudaGetSymbolAddress((void**)&ws2, g_ws2);

    // driver tensor-map encoder via runtime (no -lcuda needed)
    void* fp = nullptr;
    cudaGetDriverEntryPoint("cuTensorMapEncodeTiled", &fp, cudaEnableDefault);
    TmEncodeFn enc = (TmEncodeFn)fp;
    CUtensorMap tmX1{}, tmW1{}, tmA2{}, tmW2{};
    make_tm_bf16(enc, &tmX1, xq1, D_, (unsigned long long)E_ * T_);
    make_tm_bf16(enc, &tmW1, wq1, D_, (unsigned long long)E_ * TWOI_);
    make_tm_bf16(enc, &tmA2, aq,  I_, (unsigned long long)E_ * T_);
    make_tm_bf16(enc, &tmW2, wq2, I_, (unsigned long long)E_ * D_);

    cudaFuncSetAttribute(gemm1_swiglu_tc, cudaFuncAttributeMaxDynamicSharedMemorySize,
                         F1SMEM_BYTES);
    cudaFuncSetAttribute(gemm2_bf16_tc, cudaFuncAttributeMaxDynamicSharedMemorySize,
                         G2SMEM_BYTES);

    // [0] all three column-amax reductions in one concurrent launch
    colmax_all_kernel<<<dim3(1, 160, E_), 256>>>(x, guw, dw);
    // [1] smooth scale s1 (+ zero amax_x1/amax_w1 for next replay)
    smooth_scale_zero_kernel<<<(E_ * D_ + 255) / 256, 256>>>(ax1, aw1, s1, E_ * D_);
    // [2] quantize guw + x (bf16-held integers)
    quant_warp_kernel<D_><<<dim3((TWOI_ + T_) / 8, E_), 256>>>(guw, x, s1, wq1, xq1,
                                                               ws1, xs1, TWOI_, T_);
    // [3] fused GEMM1 + SwiGLU  <- ncu-profiled slot
    gemm1_swiglu_tc<<<dim3(I_ / 128, T_ / 256, E_), 256, F1SMEM_BYTES>>>(
        tmX1, tmW1, xq1, wq1, xs1, ws1);
    // [4] smooth scale s2 (+ zero amax_a/amax_w2)
    smooth_scale_zero_kernel<<<(E_ * I_ + 255) / 256, 256>>>(aa, aw2, s2, E_ * I_);
    // [5] quantize dw + a
    quant_warp_kernel<I_><<<dim3((D_ + T_) / 8, E_), 256>>>(dw, a, s2, wq2, aq,
                                                            ws2, xs2, D_, T_);
    // [6] GEMM2 -> out
    gemm2_bf16_tc<<<dim3(D_ / 256, T_ / 256, E_), 256, G2SMEM_BYTES>>>(
        tmA2, tmW2, aq, wq2, out, xs2, ws2);
    (void)in_sizes; (void)n_in; (void)out_size;
}

// round 15
// speedup vs baseline: 3.9501x; 1.2625x over previous
#include <cuda_runtime.h>
#include <cuda.h>
#include <cuda_bf16.h>
#include <cstdint>

// Problem shape (fixed by dataset): E=8, T=2048, D=2048, I=1024
#define E_     8
#define T_     2048
#define D_     2048
#define I_     1024
#define TWOI_  2048
#define EPS_   1e-6f
#define QMAX_  127.0f

// tcgen05/TMA fast path exists only in arch-specific passes (sm_103a/sm_100a).
// sm_103a has NO kind::i8 (ptxas-verified R6) — kind::f16 with bf16-held
// integers (exact for |v|<=127).
#if defined(__CUDA_ARCH__) && defined(__CUDA_ARCH_HAS_FEATURE__)
#  if __CUDA_ARCH_HAS_FEATURE__(SM103_ALL) || __CUDA_ARCH_HAS_FEATURE__(SM100_ALL) || __CUDA_ARCH_HAS_FEATURE__(SM101_ALL)
#    define USE_TC 1
#  endif
#endif
#ifndef USE_TC
#  define USE_TC 0
#endif

// ---------------- scratch (static device globals; no allocation) -------------
__device__ __align__(16) __nv_bfloat16 g_xq1[(long)E_ * T_ * D_];
__device__ __align__(16) __nv_bfloat16 g_wq1[(long)E_ * TWOI_ * D_];
__device__ __align__(16) __nv_bfloat16 g_aq [(long)E_ * T_ * I_];
__device__ __align__(16) __nv_bfloat16 g_wq2[(long)E_ * D_ * I_];
__device__ float  g_a  [(long)E_ * T_ * I_];
__device__ float  g_amax_x1[E_ * D_];
__device__ float  g_amax_w1[E_ * D_];
__device__ float  g_amax_a [E_ * I_];
__device__ float  g_amax_w2[E_ * I_];
__device__ float  g_s1   [E_ * D_];
__device__ float  g_sinv1[E_ * D_];
__device__ float  g_s2   [E_ * I_];
__device__ float  g_sinv2[E_ * I_];
__device__ float  g_xs1[E_ * T_];
__device__ float  g_ws1[E_ * TWOI_];
__device__ float  g_xs2[E_ * T_];
__device__ float  g_ws2[E_ * D_];

// ================= PTX helpers ================================================
__device__ __forceinline__ uint32_t smem_u32(const void* p) {
    return (uint32_t)__cvta_generic_to_shared(p);
}

#if USE_TC
#define MBARRIER_INIT(addr, count) \
    asm volatile("mbarrier.init.shared.b64 [%0], %1;" :: "r"((uint32_t)(addr)), "r"((uint32_t)(count)) : "memory")

#define MBARRIER_EXPECT_TX(addr, bytes) \
    asm volatile("mbarrier.arrive.expect_tx.shared.b64 _, [%0], %1;" \
        :: "r"((uint32_t)(addr)), "r"((uint32_t)(bytes)) : "memory")

#define MBARRIER_WAIT_PARITY(mbar_smem_addr, phase_parity) do { \
    uint32_t _mbar = (uint32_t)(mbar_smem_addr); \
    uint32_t _parity = (uint32_t)(phase_parity); \
    uint32_t _done; \
    asm volatile( \
        "{\n\t.reg .pred p;\n\t" \
        "mbarrier.try_wait.parity.acquire.cta.shared::cta.b64 p, [%1], %2;\n\t" \
        "selp.b32 %0, 1, 0, p;\n\t}" \
        : "=r"(_done) : "r"(_mbar), "r"(_parity) : "memory"); \
    if (!_done) { \
        asm volatile( \
            "{\n\t.reg .pred P1;\n\t" \
            "WAIT_LOOP_%=:\n\t" \
            "mbarrier.try_wait.parity.acquire.cta.shared::cta.b64 P1, [%0], %1, 0x989680;\n\t" \
            "@P1 bra.uni WAIT_DONE_%=;\n\t" \
            "bra.uni WAIT_LOOP_%=;\n\t" \
            "WAIT_DONE_%=:\n\t}" \
            :: "r"(_mbar), "r"(_parity) : "memory"); \
    } \
} while(0)

#define TCGEN05_ALLOC(smem_result_addr, nCols) \
    asm volatile("tcgen05.alloc.cta_group::1.sync.aligned.shared::cta.b32 [%0], %1;" \
        :: "r"((uint32_t)(smem_result_addr)), "r"((uint32_t)(nCols)) : "memory")
#define TCGEN05_DEALLOC(tmem_addr, nCols) \
    asm volatile("tcgen05.dealloc.cta_group::1.sync.aligned.b32 %0, %1;" \
        :: "r"(tmem_addr), "r"((uint32_t)(nCols)))
#define TCGEN05_RELINQUISH() \
    asm volatile("tcgen05.relinquish_alloc_permit.cta_group::1.sync.aligned;")
#define TCGEN05_COMMIT(mbar_smem_addr) \
    asm volatile("tcgen05.commit.cta_group::1.mbarrier::arrive::one.shared::cluster.b64 [%0];" \
        :: "r"((uint32_t)(mbar_smem_addr)) : "memory")
#define TCGEN05_FENCE_AFTER()  asm volatile("tcgen05.fence::after_thread_sync;" ::: "memory")
#define TCGEN05_FENCE_BEFORE() asm volatile("tcgen05.fence::before_thread_sync;" ::: "memory")
#define TCGEN05_WAIT_LD()      asm volatile("tcgen05.wait::ld.sync.aligned;" ::: "memory")

#define TMA_LOAD_2D(smem_addr, tmap, cx, cy, mbar) \
    asm volatile("cp.async.bulk.tensor.2d.shared::cta.global.tile.mbarrier::complete_tx::bytes " \
        "[%0], [%1, {%2, %3}], [%4];" \
        :: "r"((uint32_t)(smem_addr)), "l"(tmap), "r"((int)(cx)), "r"((int)(cy)), \
           "r"((uint32_t)(mbar)) : "memory")

#define TCGEN05_LD_32X32B_X32(r, tmem_addr) \
    asm volatile( \
        "tcgen05.ld.sync.aligned.32x32b.x32.b32 " \
        "{%0, %1, %2, %3, %4, %5, %6, %7, " \
        " %8, %9, %10, %11, %12, %13, %14, %15, " \
        " %16, %17, %18, %19, %20, %21, %22, %23, " \
        " %24, %25, %26, %27, %28, %29, %30, %31}, [%32];" \
        : "=r"((r)[0]),  "=r"((r)[1]),  "=r"((r)[2]),  "=r"((r)[3]), \
          "=r"((r)[4]),  "=r"((r)[5]),  "=r"((r)[6]),  "=r"((r)[7]), \
          "=r"((r)[8]),  "=r"((r)[9]),  "=r"((r)[10]), "=r"((r)[11]), \
          "=r"((r)[12]), "=r"((r)[13]), "=r"((r)[14]), "=r"((r)[15]), \
          "=r"((r)[16]), "=r"((r)[17]), "=r"((r)[18]), "=r"((r)[19]), \
          "=r"((r)[20]), "=r"((r)[21]), "=r"((r)[22]), "=r"((r)[23]), \
          "=r"((r)[24]), "=r"((r)[25]), "=r"((r)[26]), "=r"((r)[27]), \
          "=r"((r)[28]), "=r"((r)[29]), "=r"((r)[30]), "=r"((r)[31]) \
        : "r"(tmem_addr))

// SW128 descriptor (Blackwell, LBO=1, SBO=64; rows are 128 bytes)
static constexpr uint64_t SMEM_DESC_BASE_SW128 =
    (uint64_t(2)  << 61) | (uint64_t(1) << 46) | (uint64_t(64) << 32) | (uint64_t(1) << 16);
#define MAKE_SMEM_DESC(base_addr) \
    (SMEM_DESC_BASE_SW128 | ((uint64_t)((base_addr) >> 4) & 0x3FFF))

// tcgen05 f16 SS MMA (bf16 x bf16 -> f32 TMEM), K=16 per call
__device__ __forceinline__ void tcgen05_mma_f16_ss(
    uint32_t d_tmem, uint64_t a_desc, uint64_t b_desc, uint32_t idesc, bool accum) {
    uint32_t en = accum ? 1u : 0u;
    asm volatile(
        "{\n\t.reg .pred p;\n\t"
        "setp.ne.u32 p, %5, 0;\n\t"
        "tcgen05.mma.cta_group::1.kind::f16 [%0], %1, %2, %3, {%4, %4, %4, %4}, p;\n\t"
        "}"
        :: "r"(d_tmem), "l"(a_desc), "l"(b_desc), "r"(idesc), "r"(0u), "r"(en)
        : "memory");
}

// idesc (kind::f16): dtype=F32(1)<<4, atype=BF16(1)<<7, btype=BF16(1)<<10,
// N/8<<17, M/16<<24.  (Validated vs test_mma.cu 0x8080490, test_2cta_mma_bf16.)
static constexpr uint32_t IDESC_BF16 =
    (1u << 4) | (1u << 7) | (1u << 10) | ((128u / 8) << 17) | ((128u / 16) << 24);
#endif  // USE_TC

// ---------------- merged column abs-max over rows -----------------------------
__global__ void colmax_all_kernel(const float* __restrict__ x,
                                  const float* __restrict__ guw,
                                  const float* __restrict__ dw) {
    int e = blockIdx.z;
    int yy = blockIdx.y;
    const float* M; float* out; int C, tile;
    if (yy < 64)       { M = x;   out = g_amax_x1; C = 2048; tile = yy; }
    else if (yy < 128) { M = guw; out = g_amax_w1; C = 2048; tile = yy - 64; }
    else               { M = dw;  out = g_amax_w2; C = 1024; tile = yy - 128; }
    int cg = (C == 2048) ? (tile & 1) : 0;
    int rg = (C == 2048) ? (tile >> 1) : tile;
    int c0 = cg * 1024 + threadIdx.x * 4;
    const float4* p = (const float4*)(M + (long)e * 2048 * C + (long)rg * 64 * C + c0);
    long str = C >> 2;
    float4 m = make_float4(0.f, 0.f, 0.f, 0.f);
#pragma unroll 8
    for (int r = 0; r < 64; ++r) {
        float4 v = p[(long)r * str];
        m.x = fmaxf(m.x, fabsf(v.x)); m.y = fmaxf(m.y, fabsf(v.y));
        m.z = fmaxf(m.z, fabsf(v.z)); m.w = fmaxf(m.w, fabsf(v.w));
    }
    unsigned int* o = (unsigned int*)(out + e * C + c0);
    atomicMax(o + 0, __float_as_uint(m.x));
    atomicMax(o + 1, __float_as_uint(m.y));
    atomicMax(o + 2, __float_as_uint(m.z));
    atomicMax(o + 3, __float_as_uint(m.w));
}

// ---------------- smooth scale (+ 1/s) + zero amax for next graph replay -----
__global__ void smooth_scale_zero_kernel(float* __restrict__ ax,
                                         float* __restrict__ aw,
                                         float* __restrict__ s,
                                         float* __restrict__ sinv, int n) {
    int i = blockIdx.x * 256 + threadIdx.x;
    if (i < n) {
        float v = sqrtf(fmaxf(ax[i], EPS_) / fmaxf(aw[i], EPS_));
        v = fmaxf(v, EPS_);
        s[i] = v;
        sinv[i] = 1.0f / v;   // activations multiply by 1/s (<=1ulp vs divide)
        ax[i] = 0.f;
        aw[i] = 0.f;
    }
}

// ---------------- per-row quantization: warp-per-row, single-pass, registers --
// rows [0,Rw): weights (v = W*s); rows [Rw,Rw+Rx): activations (v = X*(1/s)).
template <int C>
__global__ void quant_warp_kernel(const float* __restrict__ W, const float* __restrict__ X,
                                  const float* __restrict__ s, const float* __restrict__ sinv,
                                  __nv_bfloat16* __restrict__ qw, __nv_bfloat16* __restrict__ qx,
                                  float* __restrict__ rsw, float* __restrict__ rsx,
                                  int Rw, int Rx) {
    constexpr int NV = C / 128;
    int e = blockIdx.y;
    int wid = threadIdx.x >> 5, lane = threadIdx.x & 31;
    int rg = blockIdx.x * 8 + wid;
    int mul = (rg < Rw);
    int r = mul ? rg : rg - Rw;
    int R = mul ? Rw : Rx;
    const float* row = (mul ? W : X) + ((long)e * R + r) * (long)C;
    const float* sv  = (mul ? s : sinv) + (long)e * C;

    float4 v[NV];
    float m = 0.f;
#pragma unroll
    for (int i = 0; i < NV; ++i) {
        int c = lane * 4 + i * 128;
        float4 rv = *(const float4*)(row + c);
        float4 svv = *(const float4*)(sv + c);
        float4 vv;
        vv.x = rv.x * svv.x; vv.y = rv.y * svv.y;
        vv.z = rv.z * svv.z; vv.w = rv.w * svv.w;
        v[i] = vv;
        m = fmaxf(m, fmaxf(fmaxf(fabsf(vv.x), fabsf(vv.y)), fmaxf(fabsf(vv.z), fabsf(vv.w))));
    }
#pragma unroll
    for (int off = 16; off > 0; off >>= 1)
        m = fmaxf(m, __shfl_xor_sync(0xFFFFFFFFu, m, off));
    float scale = fmaxf(m, EPS_) * (1.0f / QMAX_);
    if (lane == 0) (mul ? rsw : rsx)[(long)e * R + r] = scale;

    __nv_bfloat16* qr = (mul ? qw : qx) + ((long)e * R + r) * (long)C;
#pragma unroll
    for (int i = 0; i < NV; ++i) {
        int c = lane * 4 + i * 128;
        float q0 = fminf(fmaxf(rintf(v[i].x / scale), -QMAX_), QMAX_);
        float q1 = fminf(fmaxf(rintf(v[i].y / scale), -QMAX_), QMAX_);
        float q2 = fminf(fmaxf(rintf(v[i].z / scale), -QMAX_), QMAX_);
        float q3 = fminf(fmaxf(rintf(v[i].w / scale), -QMAX_), QMAX_);
        __nv_bfloat162 p0 = __floats2bfloat162_rn(q0, q1);
        __nv_bfloat162 p1 = __floats2bfloat162_rn(q2, q3);
        uint2 st;
        st.x = *(uint32_t*)&p0;
        st.y = *(uint32_t*)&p1;
        *(uint2*)(qr + c) = st;
    }
}

// ---------------- GEMM1 + SwiGLU fused (tcgen05 + TMA, M=256) -----------------
// Warp-specialized control: tid0 (warp 0) = MMA consumer (wait full -> 16 MMA
// -> commit done); tid32 (warp 1) = TMA producer (wait done(j-S) -> expect_tx
// -> 4 TMA). Producer tracks every done phase, so IT performs the final drain
// (parity waits cannot skip phases). Epilogue gated by __syncthreads().
// TMEM 512 cols: gate_m0@0, up_m0@128, gate_m1@256, up_m1@384.
#define F1STAGES 3
#define F1STAGE_BYTES 65536
#define F1SMEM_BYTES (F1STAGES * F1STAGE_BYTES + 1024)

__global__ void __launch_bounds__(256, 1)
gemm1_swiglu_tc(const __grid_constant__ CUtensorMap tmA,
                const __grid_constant__ CUtensorMap tmB,
                const __nv_bfloat16* __restrict__ A, const __nv_bfloat16* __restrict__ B,
                const float* __restrict__ asc_, const float* __restrict__ bsc_) {
    extern __shared__ int8_t dynraw[];
    const int tid = threadIdx.x;
    const int e = blockIdx.z;
    const int m0 = blockIdx.y * 256, n0 = blockIdx.x * 128;
#if USE_TC
    __shared__ __align__(16) uint64_t mbar_store[2 * F1STAGES];   // full 0..2, done 3..5
    __shared__ uint32_t tmem_addr_sh;
    __shared__ float cmax[128];

    const uint32_t sbase = (smem_u32(dynraw) + 1023u) & ~1023u;
    const uint32_t mbar0 = smem_u32(&mbar_store[0]);
    const int wid = tid >> 5;
    const int lane = tid & 31;
    const int nchunks = D_ >> 6;   // 32

    if (wid == 0) {
        TCGEN05_ALLOC(smem_u32(&tmem_addr_sh), 512);
        TCGEN05_RELINQUISH();
    }
    if (tid == 0) {
#pragma unroll
        for (int s = 0; s < 2 * F1STAGES; ++s) MBARRIER_INIT(mbar0 + 8 * s, 1);
    }
    for (int i = tid; i < 128; i += 256) cmax[i] = 0.f;
    __syncthreads();
    const uint32_t tmem = tmem_addr_sh;

    if (tid == 0) {
        // -------- MMA consumer --------
        for (int it = 0; it < nchunks; ++it) {
            int s = it % F1STAGES;
            MBARRIER_WAIT_PARITY(mbar0 + 8 * s, (it / F1STAGES) & 1);
            uint32_t base = sbase + (uint32_t)s * F1STAGE_BYTES;
            uint64_t a0 = MAKE_SMEM_DESC(base);
            uint64_t a1 = MAKE_SMEM_DESC(base + 16384);
            uint64_t gd = MAKE_SMEM_DESC(base + 32768);
            uint64_t ud = MAKE_SMEM_DESC(base + 49152);
            bool acc0 = (it > 0);
#pragma unroll
            for (int ks = 0; ks < 4; ++ks) {
                bool acc = acc0 || (ks > 0);
                tcgen05_mma_f16_ss(tmem,       a0 + ks * 2, gd + ks * 2, IDESC_BF16, acc);
                tcgen05_mma_f16_ss(tmem + 128, a0 + ks * 2, ud + ks * 2, IDESC_BF16, acc);
                tcgen05_mma_f16_ss(tmem + 256, a1 + ks * 2, gd + ks * 2, IDESC_BF16, acc);
                tcgen05_mma_f16_ss(tmem + 384, a1 + ks * 2, ud + ks * 2, IDESC_BF16, acc);
            }
            TCGEN05_COMMIT(mbar0 + 8 * (F1STAGES + s));
        }
    } else if (tid == 32) {
        // -------- TMA producer (separate warp; independent phase tracking) ----
        const int rowA = e * T_ + m0;
        const int rowG = e * TWOI_ + n0;
        const int rowU = rowG + I_;
        for (int j = 0; j < nchunks; ++j) {
            if (j >= F1STAGES) {
                int c = j - F1STAGES;
                MBARRIER_WAIT_PARITY(mbar0 + 8 * (F1STAGES + c % F1STAGES),
                                     (c / F1STAGES) & 1);
            }
            int s = j % F1STAGES;
            uint32_t base = sbase + (uint32_t)s * F1STAGE_BYTES;
            uint32_t fb = mbar0 + 8 * s;
            MBARRIER_EXPECT_TX(fb, F1STAGE_BYTES);
            int cx = j * 64;
            TMA_LOAD_2D(base,         &tmA, cx, rowA,       fb);
            TMA_LOAD_2D(base + 16384, &tmA, cx, rowA + 128, fb);
            TMA_LOAD_2D(base + 32768, &tmB, cx, rowG,       fb);
            TMA_LOAD_2D(base + 49152, &tmB, cx, rowU,       fb);
        }
        // drain: wait remaining done phases (chunks nchunks-S .. nchunks-1)
        for (int c = nchunks - F1STAGES; c < nchunks; ++c)
            if (c >= 0)
                MBARRIER_WAIT_PARITY(mbar0 + 8 * (F1STAGES + c % F1STAGES),
                                     (c / F1STAGES) & 1);
    }
    // rendezvous: producer has confirmed ALL MMAs complete
    __syncthreads();
    TCGEN05_FENCE_AFTER();

    // epilogue: warp -> m-tile (wid>>2), subpartition rows (wid&3)*32+lane
    {
        int mt = wid >> 2;
        uint32_t tb = tmem + mt * 256;
        long t = m0 + mt * 128 + (wid & 3) * 32 + lane;
        float as = asc_[(long)e * T_ + t];
        float* dstrow = g_a + ((long)e * T_ + t) * (long)I_ + n0;
        const float* bsg = bsc_ + (long)e * TWOI_ + n0;
        const float* bsu = bsc_ + (long)e * TWOI_ + n0 + I_;
#pragma unroll
        for (int part = 0; part < 4; ++part) {
            uint32_t dg[32], du[32];
            TCGEN05_LD_32X32B_X32(dg, tb + part * 32);
            TCGEN05_LD_32X32B_X32(du, tb + 128 + part * 32);
            TCGEN05_WAIT_LD();
            float amx[32];
#pragma unroll
            for (int c = 0; c < 32; c += 4) {
                float4 v;
#pragma unroll
                for (int j2 = 0; j2 < 4; ++j2) {
                    int cc = c + j2;
                    float gv = __uint_as_float(dg[cc]) * as * bsg[part * 32 + cc];
                    float uv = __uint_as_float(du[cc]) * as * bsu[part * 32 + cc];
                    float vv = (gv / (1.0f + expf(-gv))) * uv;
                    ((float*)&v)[j2] = vv;
                    amx[cc] = fabsf(vv);
                }
                *(float4*)(dstrow + part * 32 + c) = v;
            }
#pragma unroll
            for (int c = 0; c < 32; ++c) {
#pragma unroll
                for (int off = 16; off > 0; off >>= 1)
                    amx[c] = fmaxf(amx[c], __shfl_xor_sync(0xFFFFFFFFu, amx[c], off));
            }
            atomicMax((unsigned int*)&cmax[part * 32 + lane],
                      __float_as_uint(amx[lane]));
        }
        TCGEN05_FENCE_BEFORE();
    }
    __syncthreads();
    if (tid < 128)
        atomicMax((unsigned int*)(g_amax_a + (long)e * I_ + n0 + tid),
                  __float_as_uint(cmax[tid]));
    if (wid == 0) {
        TCGEN05_DEALLOC(tmem, 512);
    }
#else
    // naive fallback (never selected on sm_103a; correctness-preserving)
    for (int idx = tid; idx < 256 * 128; idx += 256) {
        int i = idx >> 7, j = idx & 127;
        long t = m0 + i;
        int n = n0 + j;
        const __nv_bfloat16* ar = A + (long)e * T_ * D_ + t * (long)D_;
        const __nv_bfloat16* bg = B + (long)e * TWOI_ * D_ + (long)n * D_;
        const __nv_bfloat16* bu = B + (long)e * TWOI_ * D_ + (long)(n + I_) * D_;
        float sg = 0.f, su = 0.f;
        for (int k = 0; k < D_; ++k) {
            float av = __bfloat162float(ar[k]);
            sg = fmaf(av, __bfloat162float(bg[k]), sg);
            su = fmaf(av, __bfloat162float(bu[k]), su);
        }
        float as = asc_[(long)e * T_ + t];
        float gv = sg * as * bsc_[(long)e * TWOI_ + n];
        float uv = su * as * bsc_[(long)e * TWOI_ + n + I_];
        float vv = (gv / (1.0f + expf(-gv))) * uv;
        g_a[((long)e * T_ + t) * I_ + n] = vv;
        atomicMax((unsigned int*)(g_amax_a + (long)e * I_ + n),
                  __float_as_uint(fabsf(vv)));
    }
#endif
}

// ---------------- GEMM2 (tcgen05 + TMA, M=256 x N=256) ------------------------
#define G2STAGES 3
#define G2STAGE_BYTES 65536
#define G2SMEM_BYTES (G2STAGES * G2STAGE_BYTES + 1024)

__global__ void __launch_bounds__(256, 1)
gemm2_bf16_tc(const __grid_constant__ CUtensorMap tmA,
              const __grid_constant__ CUtensorMap tmB,
              const __nv_bfloat16* __restrict__ A, const __nv_bfloat16* __restrict__ B,
              float* __restrict__ Co, const float* __restrict__ asc_,
              const float* __restrict__ bsc_) {
    extern __shared__ int8_t dynraw[];
    const int tid = threadIdx.x;
    const int e = blockIdx.z;
    const int m0 = blockIdx.y * 256, n0 = blockIdx.x * 256;
    const int M = T_, N = D_, K = I_;
#if USE_TC
    __shared__ __align__(16) uint64_t mbar_store[2 * G2STAGES];
    __shared__ uint32_t tmem_addr_sh;

    const uint32_t sbase = (smem_u32(dynraw) + 1023u) & ~1023u;
    const uint32_t mbar0 = smem_u32(&mbar_store[0]);
    const int wid = tid >> 5;
    const int lane = tid & 31;
    const int nchunks = K >> 6;   // 16

    if (wid == 0) {
        TCGEN05_ALLOC(smem_u32(&tmem_addr_sh), 512);
        TCGEN05_RELINQUISH();
    }
    if (tid == 0) {
#pragma unroll
        for (int s = 0; s < 2 * G2STAGES; ++s) MBARRIER_INIT(mbar0 + 8 * s, 1);
    }
    __syncthreads();
    const uint32_t tmem = tmem_addr_sh;

    if (tid == 0) {
        // -------- MMA consumer --------
        for (int it = 0; it < nchunks; ++it) {
            int s = it % G2STAGES;
            MBARRIER_WAIT_PARITY(mbar0 + 8 * s, (it / G2STAGES) & 1);
            uint32_t base = sbase + (uint32_t)s * G2STAGE_BYTES;
            uint64_t a0 = MAKE_SMEM_DESC(base);
            uint64_t a1 = MAKE_SMEM_DESC(base + 16384);
            uint64_t b0 = MAKE_SMEM_DESC(base + 32768);
            uint64_t b1 = MAKE_SMEM_DESC(base + 49152);
            bool acc0 = (it > 0);
#pragma unroll
            for (int ks = 0; ks < 4; ++ks) {
                bool acc = acc0 || (ks > 0);
                tcgen05_mma_f16_ss(tmem,       a0 + ks * 2, b0 + ks * 2, IDESC_BF16, acc);
                tcgen05_mma_f16_ss(tmem + 128, a0 + ks * 2, b1 + ks * 2, IDESC_BF16, acc);
                tcgen05_mma_f16_ss(tmem + 256, a1 + ks * 2, b0 + ks * 2, IDESC_BF16, acc);
                tcgen05_mma_f16_ss(tmem + 384, a1 + ks * 2, b1 + ks * 2, IDESC_BF16, acc);
            }
            TCGEN05_COMMIT(mbar0 + 8 * (G2STAGES + s));
        }
    } else if (tid == 32) {
        // -------- TMA producer --------
        const int rowA = e * M + m0;
        const int rowB = e * N + n0;
        for (int j = 0; j < nchunks; ++j) {
            if (j >= G2STAGES) {
                int c = j - G2STAGES;
                MBARRIER_WAIT_PARITY(mbar0 + 8 * (G2STAGES + c % G2STAGES),
                                     (c / G2STAGES) & 1);
            }
            int s = j % G2STAGES;
            uint32_t base = sbase + (uint32_t)s * G2STAGE_BYTES;
            uint32_t fb = mbar0 + 8 * s;
            MBARRIER_EXPECT_TX(fb, G2STAGE_BYTES);
            int cx = j * 64;
            TMA_LOAD_2D(base,         &tmA, cx, rowA,       fb);
            TMA_LOAD_2D(base + 16384, &tmA, cx, rowA + 128, fb);
            TMA_LOAD_2D(base + 32768, &tmB, cx, rowB,       fb);
            TMA_LOAD_2D(base + 49152, &tmB, cx, rowB + 128, fb);
        }
        for (int c = nchunks - G2STAGES; c < nchunks; ++c)
            if (c >= 0)
                MBARRIER_WAIT_PARITY(mbar0 + 8 * (G2STAGES + c % G2STAGES),
                                     (c / G2STAGES) & 1);
    }
    __syncthreads();
    TCGEN05_FENCE_AFTER();

    // epilogue: warp -> m-tile (wid>>2); 8 parts of 32 cols, 2 LDTMs per wait
    {
        int mt = wid >> 2;
        long row = m0 + mt * 128 + (wid & 3) * 32 + lane;
        float as = asc_[(long)e * M + row];
        const float* bs = bsc_ + (long)e * N + n0;
        float* dst = Co + (long)e * M * N + row * N + n0;
#pragma unroll
        for (int pp = 0; pp < 4; ++pp) {
            int p0 = 2 * pp, p1 = 2 * pp + 1;
            uint32_t ta0 = tmem + mt * 256 + ((p0 >= 4) ? 128 : 0) + (p0 & 3) * 32;
            uint32_t ta1 = tmem + mt * 256 + ((p1 >= 4) ? 128 : 0) + (p1 & 3) * 32;
            uint32_t d0[32], d1[32];
            TCGEN05_LD_32X32B_X32(d0, ta0);
            TCGEN05_LD_32X32B_X32(d1, ta1);
            TCGEN05_WAIT_LD();
#pragma unroll
            for (int c = 0; c < 32; c += 4) {
                float4 v;
                v.x = __uint_as_float(d0[c + 0]) * as * bs[p0 * 32 + c + 0];
                v.y = __uint_as_float(d0[c + 1]) * as * bs[p0 * 32 + c + 1];
                v.z = __uint_as_float(d0[c + 2]) * as * bs[p0 * 32 + c + 2];
                v.w = __uint_as_float(d0[c + 3]) * as * bs[p0 * 32 + c + 3];
                *(float4*)(dst + p0 * 32 + c) = v;
            }
#pragma unroll
            for (int c = 0; c < 32; c += 4) {
                float4 v;
                v.x = __uint_as_float(d1[c + 0]) * as * bs[p1 * 32 + c + 0];
                v.y = __uint_as_float(d1[c + 1]) * as * bs[p1 * 32 + c + 1];
                v.z = __uint_as_float(d1[c + 2]) * as * bs[p1 * 32 + c + 2];
                v.w = __uint_as_float(d1[c + 3]) * as * bs[p1 * 32 + c + 3];
                *(float4*)(dst + p1 * 32 + c) = v;
            }
        }
        TCGEN05_FENCE_BEFORE();
    }
    __syncthreads();
    if (wid == 0) {
        TCGEN05_DEALLOC(tmem, 512);
    }
#else
    // naive fallback (never selected on sm_103a)
    for (int idx = tid; idx < 256 * 256; idx += 256) {
        int i = idx >> 8, j = idx & 255;
        long r = m0 + i;
        int n = n0 + j;
        const __nv_bfloat16* ar = A + (long)e * M * K + r * (long)K;
        const __nv_bfloat16* br = B + (long)e * N * K + (long)n * K;
        float sum = 0.f;
        for (int k = 0; k < K; ++k)
            sum = fmaf(__bfloat162float(ar[k]), __bfloat162float(br[k]), sum);
        Co[(long)e * M * N + r * N + n] = sum * asc_[(long)e * M + r] * bsc_[(long)e * N + n];
    }
#endif
}

// ---------------- host: tensor-map encode via runtime entry point ------------
typedef CUresult (*TmEncodeFn)(CUtensorMap*, CUtensorMapDataType, cuuint32_t,
    void*, const cuuint64_t*, const cuuint64_t*, const cuuint32_t*, const cuuint32_t*,
    CUtensorMapInterleave, CUtensorMapSwizzle, CUtensorMapL2promotion,
    CUtensorMapFloatOOBfill);

static void make_tm_bf16(TmEncodeFn enc, CUtensorMap* tm, void* base,
                         unsigned dim0, unsigned long long rows) {
    cuuint64_t dims[2] = {(cuuint64_t)dim0, (cuuint64_t)rows};
    cuuint64_t strides[1] = {(cuuint64_t)dim0 * 2};
    cuuint32_t box[2] = {64, 128};        // 64 bf16 = 128B (SW128 span) x 128 rows
    cuuint32_t estr[2] = {1, 1};
    enc(tm, CU_TENSOR_MAP_DATA_TYPE_BFLOAT16, 2, base, dims, strides, box, estr,
        CU_TENSOR_MAP_INTERLEAVE_NONE, CU_TENSOR_MAP_SWIZZLE_128B,
        CU_TENSOR_MAP_L2_PROMOTION_L2_128B, CU_TENSOR_MAP_FLOAT_OOB_FILL_NONE);
}

// ---------------- launch ------------------------------------------------------
extern "C" void kernel_launch(void* const* d_in, const int* in_sizes, int n_in,
                              void* d_out, int out_size) {
    const float* x   = (const float*)d_in[0];   // [E, T, D]
    const float* guw = (const float*)d_in[1];   // [E, 2I, D]
    const float* dw  = (const float*)d_in[2];   // [E, D, I]
    float* out = (float*)d_out;                 // [E, T, D]

    __nv_bfloat16 *xq1, *wq1, *aq, *wq2;
    float *a, *ax1, *aw1, *aa, *aw2, *s1, *si1, *s2, *si2, *xs1, *ws1, *xs2, *ws2;
    cudaGetSymbolAddress((void**)&xq1, g_xq1);
    cudaGetSymbolAddress((void**)&wq1, g_wq1);
    cudaGetSymbolAddress((void**)&aq,  g_aq);
    cudaGetSymbolAddress((void**)&wq2, g_wq2);
    cudaGetSymbolAddress((void**)&a,   g_a);
    cudaGetSymbolAddress((void**)&ax1, g_amax_x1);
    cudaGetSymbolAddress((void**)&aw1, g_amax_w1);
    cudaGetSymbolAddress((void**)&aa,  g_amax_a);
    cudaGetSymbolAddress((void**)&aw2, g_amax_w2);
    cudaGetSymbolAddress((void**)&s1,  g_s1);
    cudaGetSymbolAddress((void**)&si1, g_sinv1);
    cudaGetSymbolAddress((void**)&s2,  g_s2);
    cudaGetSymbolAddress((void**)&si2, g_sinv2);
    cudaGetSymbolAddress((void**)&xs1, g_xs1);
    cudaGetSymbolAddress((void**)&ws1, g_ws1);
    cudaGetSymbolAddress((void**)&xs2, g_xs2);
    cudaGetSymbolAddress((void**)&ws2, g_ws2);

    // driver tensor-map encoder via runtime (no -lcuda needed)
    void* fp = nullptr;
    cudaGetDriverEntryPoint("cuTensorMapEncodeTiled", &fp, cudaEnableDefault);
    TmEncodeFn enc = (TmEncodeFn)fp;
    CUtensorMap tmX1{}, tmW1{}, tmA2{}, tmW2{};
    make_tm_bf16(enc, &tmX1, xq1, D_, (unsigned long long)E_ * T_);
    make_tm_bf16(enc, &tmW1, wq1, D_, (unsigned long long)E_ * TWOI_);
    make_tm_bf16(enc, &tmA2, aq,  I_, (unsigned long long)E_ * T_);
    make_tm_bf16(enc, &tmW2, wq2, I_, (unsigned long long)E_ * D_);

    cudaFuncSetAttribute(gemm1_swiglu_tc, cudaFuncAttributeMaxDynamicSharedMemorySize,
                         F1SMEM_BYTES);
    cudaFuncSetAttribute(gemm2_bf16_tc, cudaFuncAttributeMaxDynamicSharedMemorySize,
                         G2SMEM_BYTES);

    // [0] all three column-amax reductions in one concurrent launch
    colmax_all_kernel<<<dim3(1, 160, E_), 256>>>(x, guw, dw);
    // [1] smooth scale s1 + 1/s1 (+ zero amax_x1/amax_w1 for next replay)
    smooth_scale_zero_kernel<<<(E_ * D_ + 255) / 256, 256>>>(ax1, aw1, s1, si1, E_ * D_);
    // [2] quantize guw + x (bf16-held integers)
    quant_warp_kernel<D_><<<dim3((TWOI_ + T_) / 8, E_), 256>>>(guw, x, s1, si1, wq1, xq1,
                                                               ws1, xs1, TWOI_, T_);
    // [3] fused GEMM1 + SwiGLU  <- ncu-profiled slot
    gemm1_swiglu_tc<<<dim3(I_ / 128, T_ / 256, E_), 256, F1SMEM_BYTES>>>(
        tmX1, tmW1, xq1, wq1, xs1, ws1);
    // [4] smooth scale s2 + 1/s2 (+ zero amax_a/amax_w2)
    smooth_scale_zero_kernel<<<(E_ * I_ + 255) / 256, 256>>>(aa, aw2, s2, si2, E_ * I_);
    // [5] quantize dw + a
    quant_warp_kernel<I_><<<dim3((D_ + T_) / 8, E_), 256>>>(dw, a, s2, si2, wq2, aq,
                                                            ws2, xs2, D_, T_);
    // [6] GEMM2 -> out
    gemm2_bf16_tc<<<dim3(D_ / 256, T_ / 256, E_), 256, G2SMEM_BYTES>>>(
        tmA2, tmW2, aq, wq2, out, xs2, ws2);
    (void)in_sizes; (void)n_in; (void)out_size;
}

// round 16
// speedup vs baseline: 3.9963x; 1.0117x over previous
#include <cuda_runtime.h>
#include <cuda.h>
#include <cuda_bf16.h>
#include <cstdint>

// Problem shape (fixed by dataset): E=8, T=2048, D=2048, I=1024
#define E_     8
#define T_     2048
#define D_     2048
#define I_     1024
#define TWOI_  2048
#define EPS_   1e-6f
#define QMAX_  127.0f

// tcgen05/TMA fast path exists only in arch-specific passes (sm_103a/sm_100a).
// sm_103a has NO kind::i8 (ptxas-verified R6) — kind::f16 with bf16-held
// integers (exact for |v|<=127).
#if defined(__CUDA_ARCH__) && defined(__CUDA_ARCH_HAS_FEATURE__)
#  if __CUDA_ARCH_HAS_FEATURE__(SM103_ALL) || __CUDA_ARCH_HAS_FEATURE__(SM100_ALL) || __CUDA_ARCH_HAS_FEATURE__(SM101_ALL)
#    define USE_TC 1
#  endif
#endif
#ifndef USE_TC
#  define USE_TC 0
#endif

// ---------------- scratch (static device globals; no allocation) -------------
__device__ __align__(16) __nv_bfloat16 g_xq1[(long)E_ * T_ * D_];
__device__ __align__(16) __nv_bfloat16 g_wq1[(long)E_ * TWOI_ * D_];
__device__ __align__(16) __nv_bfloat16 g_aq [(long)E_ * T_ * I_];
__device__ __align__(16) __nv_bfloat16 g_wq2[(long)E_ * D_ * I_];
__device__ float  g_a  [(long)E_ * T_ * I_];
__device__ float  g_amax_x1[E_ * D_];
__device__ float  g_amax_w1[E_ * D_];
__device__ float  g_amax_a [E_ * I_];
__device__ float  g_amax_w2[E_ * I_];
__device__ float  g_s1   [E_ * D_];
__device__ float  g_sinv1[E_ * D_];
__device__ float  g_s2   [E_ * I_];
__device__ float  g_sinv2[E_ * I_];
__device__ float  g_xs1[E_ * T_];
__device__ float  g_ws1[E_ * TWOI_];
__device__ float  g_xs2[E_ * T_];
__device__ float  g_ws2[E_ * D_];

// ================= PTX helpers ================================================
__device__ __forceinline__ uint32_t smem_u32(const void* p) {
    return (uint32_t)__cvta_generic_to_shared(p);
}

#if USE_TC
__device__ __forceinline__ uint32_t cluster_rank() {
    uint32_t r;
    asm("mov.u32 %0, %%cluster_ctarank;" : "=r"(r));
    return r;
}

#define CLUSTER_SYNC() do { \
    asm volatile("barrier.cluster.arrive.aligned;" ::: "memory"); \
    asm volatile("barrier.cluster.wait.aligned;" ::: "memory"); \
} while (0)

#define MBARRIER_INIT(addr, count) \
    asm volatile("mbarrier.init.shared.b64 [%0], %1;" :: "r"((uint32_t)(addr)), "r"((uint32_t)(count)) : "memory")

#define MBARRIER_EXPECT_TX(addr, bytes) \
    asm volatile("mbarrier.arrive.expect_tx.shared.b64 _, [%0], %1;" \
        :: "r"((uint32_t)(addr)), "r"((uint32_t)(bytes)) : "memory")

#define MBARRIER_WAIT_PARITY(mbar_smem_addr, phase_parity) do { \
    uint32_t _mbar = (uint32_t)(mbar_smem_addr); \
    uint32_t _parity = (uint32_t)(phase_parity); \
    uint32_t _done; \
    asm volatile( \
        "{\n\t.reg .pred p;\n\t" \
        "mbarrier.try_wait.parity.acquire.cta.shared::cta.b64 p, [%1], %2;\n\t" \
        "selp.b32 %0, 1, 0, p;\n\t}" \
        : "=r"(_done) : "r"(_mbar), "r"(_parity) : "memory"); \
    if (!_done) { \
        asm volatile( \
            "{\n\t.reg .pred P1;\n\t" \
            "WAIT_LOOP_%=:\n\t" \
            "mbarrier.try_wait.parity.acquire.cta.shared::cta.b64 P1, [%0], %1, 0x989680;\n\t" \
            "@P1 bra.uni WAIT_DONE_%=;\n\t" \
            "bra.uni WAIT_LOOP_%=;\n\t" \
            "WAIT_DONE_%=:\n\t}" \
            :: "r"(_mbar), "r"(_parity) : "memory"); \
    } \
} while(0)

#define TCGEN05_ALLOC(smem_result_addr, nCols) \
    asm volatile("tcgen05.alloc.cta_group::1.sync.aligned.shared::cta.b32 [%0], %1;" \
        :: "r"((uint32_t)(smem_result_addr)), "r"((uint32_t)(nCols)) : "memory")
#define TCGEN05_DEALLOC(tmem_addr, nCols) \
    asm volatile("tcgen05.dealloc.cta_group::1.sync.aligned.b32 %0, %1;" \
        :: "r"(tmem_addr), "r"((uint32_t)(nCols)))
#define TCGEN05_RELINQUISH() \
    asm volatile("tcgen05.relinquish_alloc_permit.cta_group::1.sync.aligned;")
// commit with multicast: arrive at done-barrier (same smem offset) in every
// CTA whose bit is set in mask.
#define TCGEN05_COMMIT_MC(mbar_smem_addr, mask) \
    asm volatile("tcgen05.commit.cta_group::1.mbarrier::arrive::one.shared::cluster.multicast::cluster.b64 [%0], %1;" \
        :: "r"((uint32_t)(mbar_smem_addr)), "h"((uint16_t)(mask)) : "memory")
#define TCGEN05_FENCE_AFTER()  asm volatile("tcgen05.fence::after_thread_sync;" ::: "memory")
#define TCGEN05_FENCE_BEFORE() asm volatile("tcgen05.fence::before_thread_sync;" ::: "memory")
#define TCGEN05_WAIT_LD()      asm volatile("tcgen05.wait::ld.sync.aligned;" ::: "memory")

// multicast TMA: data + complete_tx delivered to the same smem offset in every
// CTA in mask (validated pattern: test_tma_multicast.cu)
#define TMA_LOAD_2D_MC(smem_addr, tmap, cx, cy, mbar, mask) \
    asm volatile("cp.async.bulk.tensor.2d.shared::cluster.global.tile.mbarrier::complete_tx::bytes.multicast::cluster " \
        "[%0], [%1, {%2, %3}], [%4], %5;" \
        :: "r"((uint32_t)(smem_addr)), "l"(tmap), "r"((int)(cx)), "r"((int)(cy)), \
           "r"((uint32_t)(mbar)), "h"((uint16_t)(mask)) : "memory")

#define TCGEN05_LD_32X32B_X32(r, tmem_addr) \
    asm volatile( \
        "tcgen05.ld.sync.aligned.32x32b.x32.b32 " \
        "{%0, %1, %2, %3, %4, %5, %6, %7, " \
        " %8, %9, %10, %11, %12, %13, %14, %15, " \
        " %16, %17, %18, %19, %20, %21, %22, %23, " \
        " %24, %25, %26, %27, %28, %29, %30, %31}, [%32];" \
        : "=r"((r)[0]),  "=r"((r)[1]),  "=r"((r)[2]),  "=r"((r)[3]), \
          "=r"((r)[4]),  "=r"((r)[5]),  "=r"((r)[6]),  "=r"((r)[7]), \
          "=r"((r)[8]),  "=r"((r)[9]),  "=r"((r)[10]), "=r"((r)[11]), \
          "=r"((r)[12]), "=r"((r)[13]), "=r"((r)[14]), "=r"((r)[15]), \
          "=r"((r)[16]), "=r"((r)[17]), "=r"((r)[18]), "=r"((r)[19]), \
          "=r"((r)[20]), "=r"((r)[21]), "=r"((r)[22]), "=r"((r)[23]), \
          "=r"((r)[24]), "=r"((r)[25]), "=r"((r)[26]), "=r"((r)[27]), \
          "=r"((r)[28]), "=r"((r)[29]), "=r"((r)[30]), "=r"((r)[31]) \
        : "r"(tmem_addr))

// SW128 descriptor (Blackwell, LBO=1, SBO=64; rows are 128 bytes)
static constexpr uint64_t SMEM_DESC_BASE_SW128 =
    (uint64_t(2)  << 61) | (uint64_t(1) << 46) | (uint64_t(64) << 32) | (uint64_t(1) << 16);
#define MAKE_SMEM_DESC(base_addr) \
    (SMEM_DESC_BASE_SW128 | ((uint64_t)((base_addr) >> 4) & 0x3FFF))

// tcgen05 f16 SS MMA (bf16 x bf16 -> f32 TMEM), K=16 per call
__device__ __forceinline__ void tcgen05_mma_f16_ss(
    uint32_t d_tmem, uint64_t a_desc, uint64_t b_desc, uint32_t idesc, bool accum) {
    uint32_t en = accum ? 1u : 0u;
    asm volatile(
        "{\n\t.reg .pred p;\n\t"
        "setp.ne.u32 p, %5, 0;\n\t"
        "tcgen05.mma.cta_group::1.kind::f16 [%0], %1, %2, %3, {%4, %4, %4, %4}, p;\n\t"
        "}"
        :: "r"(d_tmem), "l"(a_desc), "l"(b_desc), "r"(idesc), "r"(0u), "r"(en)
        : "memory");
}

// idesc (kind::f16): dtype=F32(1)<<4, atype=BF16(1)<<7, btype=BF16(1)<<10,
// N/8<<17, M/16<<24.  (Validated vs test_mma.cu 0x8080490, test_2cta_mma_bf16.)
static constexpr uint32_t IDESC_BF16 =
    (1u << 4) | (1u << 7) | (1u << 10) | ((128u / 8) << 17) | ((128u / 16) << 24);
#endif  // USE_TC

// ---------------- merged column abs-max over rows -----------------------------
__global__ void colmax_all_kernel(const float* __restrict__ x,
                                  const float* __restrict__ guw,
                                  const float* __restrict__ dw) {
    int e = blockIdx.z;
    int yy = blockIdx.y;
    const float* M; float* out; int C, tile;
    if (yy < 64)       { M = x;   out = g_amax_x1; C = 2048; tile = yy; }
    else if (yy < 128) { M = guw; out = g_amax_w1; C = 2048; tile = yy - 64; }
    else               { M = dw;  out = g_amax_w2; C = 1024; tile = yy - 128; }
    int cg = (C == 2048) ? (tile & 1) : 0;
    int rg = (C == 2048) ? (tile >> 1) : tile;
    int c0 = cg * 1024 + threadIdx.x * 4;
    const float4* p = (const float4*)(M + (long)e * 2048 * C + (long)rg * 64 * C + c0);
    long str = C >> 2;
    float4 m = make_float4(0.f, 0.f, 0.f, 0.f);
#pragma unroll 8
    for (int r = 0; r < 64; ++r) {
        float4 v = p[(long)r * str];
        m.x = fmaxf(m.x, fabsf(v.x)); m.y = fmaxf(m.y, fabsf(v.y));
        m.z = fmaxf(m.z, fabsf(v.z)); m.w = fmaxf(m.w, fabsf(v.w));
    }
    unsigned int* o = (unsigned int*)(out + e * C + c0);
    atomicMax(o + 0, __float_as_uint(m.x));
    atomicMax(o + 1, __float_as_uint(m.y));
    atomicMax(o + 2, __float_as_uint(m.z));
    atomicMax(o + 3, __float_as_uint(m.w));
}

// ---------------- smooth scale (+ 1/s) + zero amax for next graph replay -----
__global__ void smooth_scale_zero_kernel(float* __restrict__ ax,
                                         float* __restrict__ aw,
                                         float* __restrict__ s,
                                         float* __restrict__ sinv, int n) {
    int i = blockIdx.x * 256 + threadIdx.x;
    if (i < n) {
        float v = sqrtf(fmaxf(ax[i], EPS_) / fmaxf(aw[i], EPS_));
        v = fmaxf(v, EPS_);
        s[i] = v;
        sinv[i] = 1.0f / v;   // activations multiply by 1/s (<=1ulp vs divide)
        ax[i] = 0.f;
        aw[i] = 0.f;
    }
}

// ---------------- per-row quantization: warp-per-row, single-pass, registers --
// rows [0,Rw): weights (v = W*s); rows [Rw,Rw+Rx): activations (v = X*(1/s)).
template <int C>
__global__ void quant_warp_kernel(const float* __restrict__ W, const float* __restrict__ X,
                                  const float* __restrict__ s, const float* __restrict__ sinv,
                                  __nv_bfloat16* __restrict__ qw, __nv_bfloat16* __restrict__ qx,
                                  float* __restrict__ rsw, float* __restrict__ rsx,
                                  int Rw, int Rx) {
    constexpr int NV = C / 128;
    int e = blockIdx.y;
    int wid = threadIdx.x >> 5, lane = threadIdx.x & 31;
    int rg = blockIdx.x * 8 + wid;
    int mul = (rg < Rw);
    int r = mul ? rg : rg - Rw;
    int R = mul ? Rw : Rx;
    const float* row = (mul ? W : X) + ((long)e * R + r) * (long)C;
    const float* sv  = (mul ? s : sinv) + (long)e * C;

    float4 v[NV];
    float m = 0.f;
#pragma unroll
    for (int i = 0; i < NV; ++i) {
        int c = lane * 4 + i * 128;
        float4 rv = *(const float4*)(row + c);
        float4 svv = *(const float4*)(sv + c);
        float4 vv;
        vv.x = rv.x * svv.x; vv.y = rv.y * svv.y;
        vv.z = rv.z * svv.z; vv.w = rv.w * svv.w;
        v[i] = vv;
        m = fmaxf(m, fmaxf(fmaxf(fabsf(vv.x), fabsf(vv.y)), fmaxf(fabsf(vv.z), fabsf(vv.w))));
    }
#pragma unroll
    for (int off = 16; off > 0; off >>= 1)
        m = fmaxf(m, __shfl_xor_sync(0xFFFFFFFFu, m, off));
    float scale = fmaxf(m, EPS_) * (1.0f / QMAX_);
    if (lane == 0) (mul ? rsw : rsx)[(long)e * R + r] = scale;

    __nv_bfloat16* qr = (mul ? qw : qx) + ((long)e * R + r) * (long)C;
#pragma unroll
    for (int i = 0; i < NV; ++i) {
        int c = lane * 4 + i * 128;
        float q0 = fminf(fmaxf(rintf(v[i].x / scale), -QMAX_), QMAX_);
        float q1 = fminf(fmaxf(rintf(v[i].y / scale), -QMAX_), QMAX_);
        float q2 = fminf(fmaxf(rintf(v[i].z / scale), -QMAX_), QMAX_);
        float q3 = fminf(fmaxf(rintf(v[i].w / scale), -QMAX_), QMAX_);
        __nv_bfloat162 p0 = __floats2bfloat162_rn(q0, q1);
        __nv_bfloat162 p1 = __floats2bfloat162_rn(q2, q3);
        uint2 st;
        st.x = *(uint32_t*)&p0;
        st.y = *(uint32_t*)&p1;
        *(uint2*)(qr + c) = st;
    }
}

// ---------------- GEMM1 + SwiGLU fused (tcgen05 + TMA multicast, M=256) -------
// Cluster (2,2,1): x-pair (adjacent n0) shares A; y-pair (adjacent m0-supertile)
// shares B. Cooperative slicing: rx picks which A half this CTA issues (mcast
// to x-pair), ry picks gate-vs-up B half (mcast to y-pair). Per-CTA issued
// bytes halve (64KB -> 32KB/chunk); received bytes unchanged.
// done barrier count=3: each consumer commits multicast to {self, x-, y-partner}.
// MMA loop / TMEM / epilogue identical to R15.
#define F1STAGES 3
#define F1STAGE_BYTES 65536
#define F1SMEM_BYTES (F1STAGES * F1STAGE_BYTES + 1024)

__global__ void __launch_bounds__(256, 1) __cluster_dims__(2, 2, 1)
gemm1_swiglu_tc(const __grid_constant__ CUtensorMap tmA,
                const __grid_constant__ CUtensorMap tmB,
                const __nv_bfloat16* __restrict__ A, const __nv_bfloat16* __restrict__ B,
                const float* __restrict__ asc_, const float* __restrict__ bsc_) {
    extern __shared__ int8_t dynraw[];
    const int tid = threadIdx.x;
    const int e = blockIdx.z;
    const int m0 = blockIdx.y * 256, n0 = blockIdx.x * 128;
#if USE_TC
    __shared__ __align__(16) uint64_t mbar_store[2 * F1STAGES];   // full 0..2, done 3..5
    __shared__ uint32_t tmem_addr_sh;
    __shared__ float cmax[128];

    const uint32_t sbase = (smem_u32(dynraw) + 1023u) & ~1023u;
    const uint32_t mbar0 = smem_u32(&mbar_store[0]);
    const int wid = tid >> 5;
    const int lane = tid & 31;
    const int nchunks = D_ >> 6;   // 32

    const uint32_t rank = cluster_rank();          // rx = rank&1 (n), ry = rank>>1 (m)
    const uint32_t rx = rank & 1, ry = rank >> 1;
    const uint16_t xmask = (uint16_t)((1u << rank) | (1u << (rank ^ 1)));
    const uint16_t ymask = (uint16_t)((1u << rank) | (1u << (rank ^ 2)));
    const uint16_t cmask = (uint16_t)((1u << rank) | (1u << (rank ^ 1)) | (1u << (rank ^ 2)));

    if (wid == 0) {
        TCGEN05_ALLOC(smem_u32(&tmem_addr_sh), 512);
        TCGEN05_RELINQUISH();
    }
    if (tid == 0) {
#pragma unroll
        for (int s = 0; s < F1STAGES; ++s) {
            MBARRIER_INIT(mbar0 + 8 * s, 1);                    // full: 1 arrive (expect_tx)
            MBARRIER_INIT(mbar0 + 8 * (F1STAGES + s), 3);       // done: self + x + y commits
        }
    }
    for (int i = tid; i < 128; i += 256) cmax[i] = 0.f;
    __syncthreads();
    CLUSTER_SYNC();   // all barriers visible before any multicast targets them
    const uint32_t tmem = tmem_addr_sh;

    if (tid == 0) {
        // -------- MMA consumer --------
        for (int it = 0; it < nchunks; ++it) {
            int s = it % F1STAGES;
            MBARRIER_WAIT_PARITY(mbar0 + 8 * s, (it / F1STAGES) & 1);
            uint32_t base = sbase + (uint32_t)s * F1STAGE_BYTES;
            uint64_t a0 = MAKE_SMEM_DESC(base);
            uint64_t a1 = MAKE_SMEM_DESC(base + 16384);
            uint64_t gd = MAKE_SMEM_DESC(base + 32768);
            uint64_t ud = MAKE_SMEM_DESC(base + 49152);
            bool acc0 = (it > 0);
#pragma unroll
            for (int ks = 0; ks < 4; ++ks) {
                bool acc = acc0 || (ks > 0);
                tcgen05_mma_f16_ss(tmem,       a0 + ks * 2, gd + ks * 2, IDESC_BF16, acc);
                tcgen05_mma_f16_ss(tmem + 128, a0 + ks * 2, ud + ks * 2, IDESC_BF16, acc);
                tcgen05_mma_f16_ss(tmem + 256, a1 + ks * 2, gd + ks * 2, IDESC_BF16, acc);
                tcgen05_mma_f16_ss(tmem + 384, a1 + ks * 2, ud + ks * 2, IDESC_BF16, acc);
            }
            TCGEN05_COMMIT_MC(mbar0 + 8 * (F1STAGES + s), cmask);
        }
    } else if (tid == 32) {
        // -------- TMA producer: issue only this CTA's slices, multicast -------
        const int rowA = e * T_ + m0;                  // shared across x-pair
        const int rowG = e * TWOI_ + n0;               // shared across y-pair
        const int rowU = rowG + I_;
        const int aRow = rowA + (int)rx * 128;         // my A half
        const uint32_t aDst = (rx ? 16384u : 0u);
        const int bRow = ry ? rowU : rowG;             // my B half (gate or up)
        const uint32_t bDst = (ry ? 49152u : 32768u);
        for (int j = 0; j < nchunks; ++j) {
            if (j >= F1STAGES) {
                int c = j - F1STAGES;
                MBARRIER_WAIT_PARITY(mbar0 + 8 * (F1STAGES + c % F1STAGES),
                                     (c / F1STAGES) & 1);
            }
            int s = j % F1STAGES;
            uint32_t base = sbase + (uint32_t)s * F1STAGE_BYTES;
            uint32_t fb = mbar0 + 8 * s;
            MBARRIER_EXPECT_TX(fb, F1STAGE_BYTES);   // 64KB arrives (4 x 16KB mcast)
            int cx = j * 64;
            TMA_LOAD_2D_MC(base + aDst, &tmA, cx, aRow, fb, xmask);
            TMA_LOAD_2D_MC(base + bDst, &tmB, cx, bRow, fb, ymask);
        }
        // drain: wait remaining done phases
        for (int c = nchunks - F1STAGES; c < nchunks; ++c)
            if (c >= 0)
                MBARRIER_WAIT_PARITY(mbar0 + 8 * (F1STAGES + c % F1STAGES),
                                     (c / F1STAGES) & 1);
    }
    __syncthreads();
    TCGEN05_FENCE_AFTER();

    // epilogue: warp -> m-tile (wid>>2), subpartition rows (wid&3)*32+lane
    {
        int mt = wid >> 2;
        uint32_t tb = tmem + mt * 256;
        long t = m0 + mt * 128 + (wid & 3) * 32 + lane;
        float as = asc_[(long)e * T_ + t];
        float* dstrow = g_a + ((long)e * T_ + t) * (long)I_ + n0;
        const float* bsg = bsc_ + (long)e * TWOI_ + n0;
        const float* bsu = bsc_ + (long)e * TWOI_ + n0 + I_;
#pragma unroll
        for (int part = 0; part < 4; ++part) {
            uint32_t dg[32], du[32];
            TCGEN05_LD_32X32B_X32(dg, tb + part * 32);
            TCGEN05_LD_32X32B_X32(du, tb + 128 + part * 32);
            TCGEN05_WAIT_LD();
            float amx[32];
#pragma unroll
            for (int c = 0; c < 32; c += 4) {
                float4 v;
#pragma unroll
                for (int j2 = 0; j2 < 4; ++j2) {
                    int cc = c + j2;
                    float gv = __uint_as_float(dg[cc]) * as * bsg[part * 32 + cc];
                    float uv = __uint_as_float(du[cc]) * as * bsu[part * 32 + cc];
                    float vv = (gv / (1.0f + expf(-gv))) * uv;
                    ((float*)&v)[j2] = vv;
                    amx[cc] = fabsf(vv);
                }
                *(float4*)(dstrow + part * 32 + c) = v;
            }
#pragma unroll
            for (int c = 0; c < 32; ++c) {
#pragma unroll
                for (int off = 16; off > 0; off >>= 1)
                    amx[c] = fmaxf(amx[c], __shfl_xor_sync(0xFFFFFFFFu, amx[c], off));
            }
            atomicMax((unsigned int*)&cmax[part * 32 + lane],
                      __float_as_uint(amx[lane]));
        }
        TCGEN05_FENCE_BEFORE();
    }
    __syncthreads();
    if (tid < 128)
        atomicMax((unsigned int*)(g_amax_a + (long)e * I_ + n0 + tid),
                  __float_as_uint(cmax[tid]));
    if (wid == 0) {
        TCGEN05_DEALLOC(tmem, 512);
    }
    CLUSTER_SYNC();   // no CTA exits while peers may still target its smem
#else
    // naive fallback (never selected on sm_103a; correctness-preserving)
    for (int idx = tid; idx < 256 * 128; idx += 256) {
        int i = idx >> 7, j = idx & 127;
        long t = m0 + i;
        int n = n0 + j;
        const __nv_bfloat16* ar = A + (long)e * T_ * D_ + t * (long)D_;
        const __nv_bfloat16* bg = B + (long)e * TWOI_ * D_ + (long)n * D_;
        const __nv_bfloat16* bu = B + (long)e * TWOI_ * D_ + (long)(n + I_) * D_;
        float sg = 0.f, su = 0.f;
        for (int k = 0; k < D_; ++k) {
            float av = __bfloat162float(ar[k]);
            sg = fmaf(av, __bfloat162float(bg[k]), sg);
            su = fmaf(av, __bfloat162float(bu[k]), su);
        }
        float as = asc_[(long)e * T_ + t];
        float gv = sg * as * bsc_[(long)e * TWOI_ + n];
        float uv = su * as * bsc_[(long)e * TWOI_ + n + I_];
        float vv = (gv / (1.0f + expf(-gv))) * uv;
        g_a[((long)e * T_ + t) * I_ + n] = vv;
        atomicMax((unsigned int*)(g_amax_a + (long)e * I_ + n),
                  __float_as_uint(fabsf(vv)));
    }
#endif
}

// ---------------- GEMM2 (tcgen05 + TMA multicast, M=256 x N=256) --------------
// Same cluster (2,2,1) slicing: x-pair shares A (rx picks half), y-pair shares
// B (ry picks half).
#define G2STAGES 3
#define G2STAGE_BYTES 65536
#define G2SMEM_BYTES (G2STAGES * G2STAGE_BYTES + 1024)

__global__ void __launch_bounds__(256, 1) __cluster_dims__(2, 2, 1)
gemm2_bf16_tc(const __grid_constant__ CUtensorMap tmA,
              const __grid_constant__ CUtensorMap tmB,
              const __nv_bfloat16* __restrict__ A, const __nv_bfloat16* __restrict__ B,
              float* __restrict__ Co, const float* __restrict__ asc_,
              const float* __restrict__ bsc_) {
    extern __shared__ int8_t dynraw[];
    const int tid = threadIdx.x;
    const int e = blockIdx.z;
    const int m0 = blockIdx.y * 256, n0 = blockIdx.x * 256;
    const int M = T_, N = D_, K = I_;
#if USE_TC
    __shared__ __align__(16) uint64_t mbar_store[2 * G2STAGES];
    __shared__ uint32_t tmem_addr_sh;

    const uint32_t sbase = (smem_u32(dynraw) + 1023u) & ~1023u;
    const uint32_t mbar0 = smem_u32(&mbar_store[0]);
    const int wid = tid >> 5;
    const int lane = tid & 31;
    const int nchunks = K >> 6;   // 16

    const uint32_t rank = cluster_rank();
    const uint32_t rx = rank & 1, ry = rank >> 1;
    const uint16_t xmask = (uint16_t)((1u << rank) | (1u << (rank ^ 1)));
    const uint16_t ymask = (uint16_t)((1u << rank) | (1u << (rank ^ 2)));
    const uint16_t cmask = (uint16_t)((1u << rank) | (1u << (rank ^ 1)) | (1u << (rank ^ 2)));

    if (wid == 0) {
        TCGEN05_ALLOC(smem_u32(&tmem_addr_sh), 512);
        TCGEN05_RELINQUISH();
    }
    if (tid == 0) {
#pragma unroll
        for (int s = 0; s < G2STAGES; ++s) {
            MBARRIER_INIT(mbar0 + 8 * s, 1);
            MBARRIER_INIT(mbar0 + 8 * (G2STAGES + s), 3);
        }
    }
    __syncthreads();
    CLUSTER_SYNC();
    const uint32_t tmem = tmem_addr_sh;

    if (tid == 0) {
        // -------- MMA consumer --------
        for (int it = 0; it < nchunks; ++it) {
            int s = it % G2STAGES;
            MBARRIER_WAIT_PARITY(mbar0 + 8 * s, (it / G2STAGES) & 1);
            uint32_t base = sbase + (uint32_t)s * G2STAGE_BYTES;
            uint64_t a0 = MAKE_SMEM_DESC(base);
            uint64_t a1 = MAKE_SMEM_DESC(base + 16384);
            uint64_t b0 = MAKE_SMEM_DESC(base + 32768);
            uint64_t b1 = MAKE_SMEM_DESC(base + 49152);
            bool acc0 = (it > 0);
#pragma unroll
            for (int ks = 0; ks < 4; ++ks) {
                bool acc = acc0 || (ks > 0);
                tcgen05_mma_f16_ss(tmem,       a0 + ks * 2, b0 + ks * 2, IDESC_BF16, acc);
                tcgen05_mma_f16_ss(tmem + 128, a0 + ks * 2, b1 + ks * 2, IDESC_BF16, acc);
                tcgen05_mma_f16_ss(tmem + 256, a1 + ks * 2, b0 + ks * 2, IDESC_BF16, acc);
                tcgen05_mma_f16_ss(tmem + 384, a1 + ks * 2, b1 + ks * 2, IDESC_BF16, acc);
            }
            TCGEN05_COMMIT_MC(mbar0 + 8 * (G2STAGES + s), cmask);
        }
    } else if (tid == 32) {
        // -------- TMA producer --------
        const int rowA = e * M + m0;
        const int rowB = e * N + n0;
        const int aRow = rowA + (int)rx * 128;
        const uint32_t aDst = (rx ? 16384u : 0u);
        const int bRow = rowB + (int)ry * 128;
        const uint32_t bDst = (ry ? 49152u : 32768u);
        for (int j = 0; j < nchunks; ++j) {
            if (j >= G2STAGES) {
                int c = j - G2STAGES;
                MBARRIER_WAIT_PARITY(mbar0 + 8 * (G2STAGES + c % G2STAGES),
                                     (c / G2STAGES) & 1);
            }
            int s = j % G2STAGES;
            uint32_t base = sbase + (uint32_t)s * G2STAGE_BYTES;
            uint32_t fb = mbar0 + 8 * s;
            MBARRIER_EXPECT_TX(fb, G2STAGE_BYTES);
            int cx = j * 64;
            TMA_LOAD_2D_MC(base + aDst, &tmA, cx, aRow, fb, xmask);
            TMA_LOAD_2D_MC(base + bDst, &tmB, cx, bRow, fb, ymask);
        }
        for (int c = nchunks - G2STAGES; c < nchunks; ++c)
            if (c >= 0)
                MBARRIER_WAIT_PARITY(mbar0 + 8 * (G2STAGES + c % G2STAGES),
                                     (c / G2STAGES) & 1);
    }
    __syncthreads();
    TCGEN05_FENCE_AFTER();

    // epilogue: warp -> m-tile (wid>>2); 8 parts of 32 cols, 2 LDTMs per wait
    {
        int mt = wid >> 2;
        long row = m0 + mt * 128 + (wid & 3) * 32 + lane;
        float as = asc_[(long)e * M + row];
        const float* bs = bsc_ + (long)e * N + n0;
        float* dst = Co + (long)e * M * N + row * N + n0;
#pragma unroll
        for (int pp = 0; pp < 4; ++pp) {
            int p0 = 2 * pp, p1 = 2 * pp + 1;
            uint32_t ta0 = tmem + mt * 256 + ((p0 >= 4) ? 128 : 0) + (p0 & 3) * 32;
            uint32_t ta1 = tmem + mt * 256 + ((p1 >= 4) ? 128 : 0) + (p1 & 3) * 32;
            uint32_t d0[32], d1[32];
            TCGEN05_LD_32X32B_X32(d0, ta0);
            TCGEN05_LD_32X32B_X32(d1, ta1);
            TCGEN05_WAIT_LD();
#pragma unroll
            for (int c = 0; c < 32; c += 4) {
                float4 v;
                v.x = __uint_as_float(d0[c + 0]) * as * bs[p0 * 32 + c + 0];
                v.y = __uint_as_float(d0[c + 1]) * as * bs[p0 * 32 + c + 1];
                v.z = __uint_as_float(d0[c + 2]) * as * bs[p0 * 32 + c + 2];
                v.w = __uint_as_float(d0[c + 3]) * as * bs[p0 * 32 + c + 3];
                *(float4*)(dst + p0 * 32 + c) = v;
            }
#pragma unroll
            for (int c = 0; c < 32; c += 4) {
                float4 v;
                v.x = __uint_as_float(d1[c + 0]) * as * bs[p1 * 32 + c + 0];
                v.y = __uint_as_float(d1[c + 1]) * as * bs[p1 * 32 + c + 1];
                v.z = __uint_as_float(d1[c + 2]) * as * bs[p1 * 32 + c + 2];
                v.w = __uint_as_float(d1[c + 3]) * as * bs[p1 * 32 + c + 3];
                *(float4*)(dst + p1 * 32 + c) = v;
            }
        }
        TCGEN05_FENCE_BEFORE();
    }
    __syncthreads();
    if (wid == 0) {
        TCGEN05_DEALLOC(tmem, 512);
    }
    CLUSTER_SYNC();
#else
    // naive fallback (never selected on sm_103a)
    for (int idx = tid; idx < 256 * 256; idx += 256) {
        int i = idx >> 8, j = idx & 255;
        long r = m0 + i;
        int n = n0 + j;
        const __nv_bfloat16* ar = A + (long)e * M * K + r * (long)K;
        const __nv_bfloat16* br = B + (long)e * N * K + (long)n * K;
        float sum = 0.f;
        for (int k = 0; k < K; ++k)
            sum = fmaf(__bfloat162float(ar[k]), __bfloat162float(br[k]), sum);
        Co[(long)e * M * N + r * N + n] = sum * asc_[(long)e * M + r] * bsc_[(long)e * N + n];
    }
#endif
}

// ---------------- host: tensor-map encode via runtime entry point ------------
typedef CUresult (*TmEncodeFn)(CUtensorMap*, CUtensorMapDataType, cuuint32_t,
    void*, const cuuint64_t*, const cuuint64_t*, const cuuint32_t*, const cuuint32_t*,
    CUtensorMapInterleave, CUtensorMapSwizzle, CUtensorMapL2promotion,
    CUtensorMapFloatOOBfill);

static void make_tm_bf16(TmEncodeFn enc, CUtensorMap* tm, void* base,
                         unsigned dim0, unsigned long long rows) {
    cuuint64_t dims[2] = {(cuuint64_t)dim0, (cuuint64_t)rows};
    cuuint64_t strides[1] = {(cuuint64_t)dim0 * 2};
    cuuint32_t box[2] = {64, 128};        // 64 bf16 = 128B (SW128 span) x 128 rows
    cuuint32_t estr[2] = {1, 1};
    enc(tm, CU_TENSOR_MAP_DATA_TYPE_BFLOAT16, 2, base, dims, strides, box, estr,
        CU_TENSOR_MAP_INTERLEAVE_NONE, CU_TENSOR_MAP_SWIZZLE_128B,
        CU_TENSOR_MAP_L2_PROMOTION_L2_128B, CU_TENSOR_MAP_FLOAT_OOB_FILL_NONE);
}

// ---------------- launch ------------------------------------------------------
extern "C" void kernel_launch(void* const* d_in, const int* in_sizes, int n_in,
                              void* d_out, int out_size) {
    const float* x   = (const float*)d_in[0];   // [E, T, D]
    const float* guw = (const float*)d_in[1];   // [E, 2I, D]
    const float* dw  = (const float*)d_in[2];   // [E, D, I]
    float* out = (float*)d_out;                 // [E, T, D]

    __nv_bfloat16 *xq1, *wq1, *aq, *wq2;
    float *a, *ax1, *aw1, *aa, *aw2, *s1, *si1, *s2, *si2, *xs1, *ws1, *xs2, *ws2;
    cudaGetSymbolAddress((void**)&xq1, g_xq1);
    cudaGetSymbolAddress((void**)&wq1, g_wq1);
    cudaGetSymbolAddress((void**)&aq,  g_aq);
    cudaGetSymbolAddress((void**)&wq2, g_wq2);
    cudaGetSymbolAddress((void**)&a,   g_a);
    cudaGetSymbolAddress((void**)&ax1, g_amax_x1);
    cudaGetSymbolAddress((void**)&aw1, g_amax_w1);
    cudaGetSymbolAddress((void**)&aa,  g_amax_a);
    cudaGetSymbolAddress((void**)&aw2, g_amax_w2);
    cudaGetSymbolAddress((void**)&s1,  g_s1);
    cudaGetSymbolAddress((void**)&si1, g_sinv1);
    cudaGetSymbolAddress((void**)&s2,  g_s2);
    cudaGetSymbolAddress((void**)&si2, g_sinv2);
    cudaGetSymbolAddress((void**)&xs1, g_xs1);
    cudaGetSymbolAddress((void**)&ws1, g_ws1);
    cudaGetSymbolAddress((void**)&xs2, g_xs2);
    cudaGetSymbolAddress((void**)&ws2, g_ws2);

    // driver tensor-map encoder via runtime (no -lcuda needed)
    void* fp = nullptr;
    cudaGetDriverEntryPoint("cuTensorMapEncodeTiled", &fp, cudaEnableDefault);
    TmEncodeFn enc = (TmEncodeFn)fp;
    CUtensorMap tmX1{}, tmW1{}, tmA2{}, tmW2{};
    make_tm_bf16(enc, &tmX1, xq1, D_, (unsigned long long)E_ * T_);
    make_tm_bf16(enc, &tmW1, wq1, D_, (unsigned long long)E_ * TWOI_);
    make_tm_bf16(enc, &tmA2, aq,  I_, (unsigned long long)E_ * T_);
    make_tm_bf16(enc, &tmW2, wq2, I_, (unsigned long long)E_ * D_);

    cudaFuncSetAttribute(gemm1_swiglu_tc, cudaFuncAttributeMaxDynamicSharedMemorySize,
                         F1SMEM_BYTES);
    cudaFuncSetAttribute(gemm2_bf16_tc, cudaFuncAttributeMaxDynamicSharedMemorySize,
                         G2SMEM_BYTES);

    // [0] all three column-amax reductions in one concurrent launch
    colmax_all_kernel<<<dim3(1, 160, E_), 256>>>(x, guw, dw);
    // [1] smooth scale s1 + 1/s1 (+ zero amax_x1/amax_w1 for next replay)
    smooth_scale_zero_kernel<<<(E_ * D_ + 255) / 256, 256>>>(ax1, aw1, s1, si1, E_ * D_);
    // [2] quantize guw + x (bf16-held integers)
    quant_warp_kernel<D_><<<dim3((TWOI_ + T_) / 8, E_), 256>>>(guw, x, s1, si1, wq1, xq1,
                                                               ws1, xs1, TWOI_, T_);
    // [3] fused GEMM1 + SwiGLU (cluster 2x2 multicast)  <- ncu-profiled slot
    gemm1_swiglu_tc<<<dim3(I_ / 128, T_ / 256, E_), 256, F1SMEM_BYTES>>>(
        tmX1, tmW1, xq1, wq1, xs1, ws1);
    // [4] smooth scale s2 + 1/s2 (+ zero amax_a/amax_w2)
    smooth_scale_zero_kernel<<<(E_ * I_ + 255) / 256, 256>>>(aa, aw2, s2, si2, E_ * I_);
    // [5] quantize dw + a
    quant_warp_kernel<I_><<<dim3((D_ + T_) / 8, E_), 256>>>(dw, a, s2, si2, wq2, aq,
                                                            ws2, xs2, D_, T_);
    // [6] GEMM2 -> out (cluster 2x2 multicast)
    gemm2_bf16_tc<<<dim3(D_ / 256, T_ / 256, E_), 256, G2SMEM_BYTES>>>(
        tmA2, tmW2, aq, wq2, out, xs2, ws2);
    (void)in_sizes; (void)n_in; (void)out_size;
}

// round 17
// speedup vs baseline: 4.0613x; 1.0163x over previous
#include <cuda_runtime.h>
#include <cuda.h>
#include <cuda_bf16.h>
#include <cstdint>

// Problem shape (fixed by dataset): E=8, T=2048, D=2048, I=1024
#define E_     8
#define T_     2048
#define D_     2048
#define I_     1024
#define TWOI_  2048
#define EPS_   1e-6f
#define QMAX_  127.0f

// tcgen05/TMA fast path exists only in arch-specific passes (sm_103a/sm_100a).
// sm_103a has NO kind::i8 (ptxas-verified R6) — kind::f16 with bf16-held
// integers (exact for |v|<=127).
#if defined(__CUDA_ARCH__) && defined(__CUDA_ARCH_HAS_FEATURE__)
#  if __CUDA_ARCH_HAS_FEATURE__(SM103_ALL) || __CUDA_ARCH_HAS_FEATURE__(SM100_ALL) || __CUDA_ARCH_HAS_FEATURE__(SM101_ALL)
#    define USE_TC 1
#  endif
#endif
#ifndef USE_TC
#  define USE_TC 0
#endif

// ---------------- scratch (static device globals; no allocation) -------------
__device__ __align__(16) __nv_bfloat16 g_xq1[(long)E_ * T_ * D_];
__device__ __align__(16) __nv_bfloat16 g_wq1[(long)E_ * TWOI_ * D_];
__device__ __align__(16) __nv_bfloat16 g_aq [(long)E_ * T_ * I_];
__device__ __align__(16) __nv_bfloat16 g_wq2[(long)E_ * D_ * I_];
__device__ float  g_a  [(long)E_ * T_ * I_];
__device__ float  g_amax_x1[E_ * D_];
__device__ float  g_amax_w1[E_ * D_];
__device__ float  g_amax_a [E_ * I_];
__device__ float  g_amax_w2[E_ * I_];
__device__ float  g_s1   [E_ * D_];
__device__ float  g_sinv1[E_ * D_];
__device__ float  g_s2   [E_ * I_];
__device__ float  g_sinv2[E_ * I_];
__device__ float  g_xs1[E_ * T_];
__device__ float  g_ws1[E_ * TWOI_];
__device__ float  g_xs2[E_ * T_];
__device__ float  g_ws2[E_ * D_];

// ================= PTX helpers ================================================
__device__ __forceinline__ uint32_t smem_u32(const void* p) {
    return (uint32_t)__cvta_generic_to_shared(p);
}

#if USE_TC
#define MBARRIER_INIT(addr, count) \
    asm volatile("mbarrier.init.shared.b64 [%0], %1;" :: "r"((uint32_t)(addr)), "r"((uint32_t)(count)) : "memory")

#define MBARRIER_EXPECT_TX(addr, bytes) \
    asm volatile("mbarrier.arrive.expect_tx.shared.b64 _, [%0], %1;" \
        :: "r"((uint32_t)(addr)), "r"((uint32_t)(bytes)) : "memory")

#define MBARRIER_WAIT_PARITY(mbar_smem_addr, phase_parity) do { \
    uint32_t _mbar = (uint32_t)(mbar_smem_addr); \
    uint32_t _parity = (uint32_t)(phase_parity); \
    uint32_t _done; \
    asm volatile( \
        "{\n\t.reg .pred p;\n\t" \
        "mbarrier.try_wait.parity.acquire.cta.shared::cta.b64 p, [%1], %2;\n\t" \
        "selp.b32 %0, 1, 0, p;\n\t}" \
        : "=r"(_done) : "r"(_mbar), "r"(_parity) : "memory"); \
    if (!_done) { \
        asm volatile( \
            "{\n\t.reg .pred P1;\n\t" \
            "WAIT_LOOP_%=:\n\t" \
            "mbarrier.try_wait.parity.acquire.cta.shared::cta.b64 P1, [%0], %1, 0x989680;\n\t" \
            "@P1 bra.uni WAIT_DONE_%=;\n\t" \
            "bra.uni WAIT_LOOP_%=;\n\t" \
            "WAIT_DONE_%=:\n\t}" \
            :: "r"(_mbar), "r"(_parity) : "memory"); \
    } \
} while(0)

#define TCGEN05_ALLOC(smem_result_addr, nCols) \
    asm volatile("tcgen05.alloc.cta_group::1.sync.aligned.shared::cta.b32 [%0], %1;" \
        :: "r"((uint32_t)(smem_result_addr)), "r"((uint32_t)(nCols)) : "memory")
#define TCGEN05_DEALLOC(tmem_addr, nCols) \
    asm volatile("tcgen05.dealloc.cta_group::1.sync.aligned.b32 %0, %1;" \
        :: "r"(tmem_addr), "r"((uint32_t)(nCols)))
#define TCGEN05_RELINQUISH() \
    asm volatile("tcgen05.relinquish_alloc_permit.cta_group::1.sync.aligned;")
#define TCGEN05_COMMIT(mbar_smem_addr) \
    asm volatile("tcgen05.commit.cta_group::1.mbarrier::arrive::one.shared::cluster.b64 [%0];" \
        :: "r"((uint32_t)(mbar_smem_addr)) : "memory")
#define TCGEN05_FENCE_AFTER()  asm volatile("tcgen05.fence::after_thread_sync;" ::: "memory")
#define TCGEN05_FENCE_BEFORE() asm volatile("tcgen05.fence::before_thread_sync;" ::: "memory")
#define TCGEN05_WAIT_LD()      asm volatile("tcgen05.wait::ld.sync.aligned;" ::: "memory")

#define TMA_LOAD_2D(smem_addr, tmap, cx, cy, mbar) \
    asm volatile("cp.async.bulk.tensor.2d.shared::cta.global.tile.mbarrier::complete_tx::bytes " \
        "[%0], [%1, {%2, %3}], [%4];" \
        :: "r"((uint32_t)(smem_addr)), "l"(tmap), "r"((int)(cx)), "r"((int)(cy)), \
           "r"((uint32_t)(mbar)) : "memory")

#define TCGEN05_LD_32X32B_X32(r, tmem_addr) \
    asm volatile( \
        "tcgen05.ld.sync.aligned.32x32b.x32.b32 " \
        "{%0, %1, %2, %3, %4, %5, %6, %7, " \
        " %8, %9, %10, %11, %12, %13, %14, %15, " \
        " %16, %17, %18, %19, %20, %21, %22, %23, " \
        " %24, %25, %26, %27, %28, %29, %30, %31}, [%32];" \
        : "=r"((r)[0]),  "=r"((r)[1]),  "=r"((r)[2]),  "=r"((r)[3]), \
          "=r"((r)[4]),  "=r"((r)[5]),  "=r"((r)[6]),  "=r"((r)[7]), \
          "=r"((r)[8]),  "=r"((r)[9]),  "=r"((r)[10]), "=r"((r)[11]), \
          "=r"((r)[12]), "=r"((r)[13]), "=r"((r)[14]), "=r"((r)[15]), \
          "=r"((r)[16]), "=r"((r)[17]), "=r"((r)[18]), "=r"((r)[19]), \
          "=r"((r)[20]), "=r"((r)[21]), "=r"((r)[22]), "=r"((r)[23]), \
          "=r"((r)[24]), "=r"((r)[25]), "=r"((r)[26]), "=r"((r)[27]), \
          "=r"((r)[28]), "=r"((r)[29]), "=r"((r)[30]), "=r"((r)[31]) \
        : "r"(tmem_addr))

// SW128 descriptor (Blackwell, LBO=1, SBO=64; rows are 128 bytes)
static constexpr uint64_t SMEM_DESC_BASE_SW128 =
    (uint64_t(2)  << 61) | (uint64_t(1) << 46) | (uint64_t(64) << 32) | (uint64_t(1) << 16);
#define MAKE_SMEM_DESC(base_addr) \
    (SMEM_DESC_BASE_SW128 | ((uint64_t)((base_addr) >> 4) & 0x3FFF))

// tcgen05 f16 SS MMA (bf16 x bf16 -> f32 TMEM), K=16 per call
__device__ __forceinline__ void tcgen05_mma_f16_ss(
    uint32_t d_tmem, uint64_t a_desc, uint64_t b_desc, uint32_t idesc, bool accum) {
    uint32_t en = accum ? 1u : 0u;
    asm volatile(
        "{\n\t.reg .pred p;\n\t"
        "setp.ne.u32 p, %5, 0;\n\t"
        "tcgen05.mma.cta_group::1.kind::f16 [%0], %1, %2, %3, {%4, %4, %4, %4}, p;\n\t"
        "}"
        :: "r"(d_tmem), "l"(a_desc), "l"(b_desc), "r"(idesc), "r"(0u), "r"(en)
        : "memory");
}

// idesc (kind::f16): dtype=F32(1)<<4, atype=BF16(1)<<7, btype=BF16(1)<<10,
// N/8<<17, M/16<<24.  N=256: the two 128-row B tiles are CONTIGUOUS in smem,
// so one MMA covers both — A is read once per k-step (smem-BW relief).
static constexpr uint32_t IDESC_BF16_N256 =
    (1u << 4) | (1u << 7) | (1u << 10) | ((256u / 8) << 17) | ((128u / 16) << 24);
#endif  // USE_TC

// ---------------- merged column abs-max over rows -----------------------------
__global__ void colmax_all_kernel(const float* __restrict__ x,
                                  const float* __restrict__ guw,
                                  const float* __restrict__ dw) {
    int e = blockIdx.z;
    int yy = blockIdx.y;
    const float* M; float* out; int C, tile;
    if (yy < 64)       { M = x;   out = g_amax_x1; C = 2048; tile = yy; }
    else if (yy < 128) { M = guw; out = g_amax_w1; C = 2048; tile = yy - 64; }
    else               { M = dw;  out = g_amax_w2; C = 1024; tile = yy - 128; }
    int cg = (C == 2048) ? (tile & 1) : 0;
    int rg = (C == 2048) ? (tile >> 1) : tile;
    int c0 = cg * 1024 + threadIdx.x * 4;
    const float4* p = (const float4*)(M + (long)e * 2048 * C + (long)rg * 64 * C + c0);
    long str = C >> 2;
    float4 m = make_float4(0.f, 0.f, 0.f, 0.f);
#pragma unroll 8
    for (int r = 0; r < 64; ++r) {
        float4 v = p[(long)r * str];
        m.x = fmaxf(m.x, fabsf(v.x)); m.y = fmaxf(m.y, fabsf(v.y));
        m.z = fmaxf(m.z, fabsf(v.z)); m.w = fmaxf(m.w, fabsf(v.w));
    }
    unsigned int* o = (unsigned int*)(out + e * C + c0);
    atomicMax(o + 0, __float_as_uint(m.x));
    atomicMax(o + 1, __float_as_uint(m.y));
    atomicMax(o + 2, __float_as_uint(m.z));
    atomicMax(o + 3, __float_as_uint(m.w));
}

// ---------------- smooth scale (+ 1/s) + zero amax for next graph replay -----
__global__ void smooth_scale_zero_kernel(float* __restrict__ ax,
                                         float* __restrict__ aw,
                                         float* __restrict__ s,
                                         float* __restrict__ sinv, int n) {
    int i = blockIdx.x * 256 + threadIdx.x;
    if (i < n) {
        float v = sqrtf(fmaxf(ax[i], EPS_) / fmaxf(aw[i], EPS_));
        v = fmaxf(v, EPS_);
        s[i] = v;
        sinv[i] = 1.0f / v;   // activations multiply by 1/s (<=1ulp vs divide)
        ax[i] = 0.f;
        aw[i] = 0.f;
    }
}

// ---------------- per-row quantization: warp-per-row, single-pass, registers --
// rows [0,Rw): weights (v = W*s); rows [Rw,Rw+Rx): activations (v = X*(1/s)).
template <int C>
__global__ void quant_warp_kernel(const float* __restrict__ W, const float* __restrict__ X,
                                  const float* __restrict__ s, const float* __restrict__ sinv,
                                  __nv_bfloat16* __restrict__ qw, __nv_bfloat16* __restrict__ qx,
                                  float* __restrict__ rsw, float* __restrict__ rsx,
                                  int Rw, int Rx) {
    constexpr int NV = C / 128;
    int e = blockIdx.y;
    int wid = threadIdx.x >> 5, lane = threadIdx.x & 31;
    int rg = blockIdx.x * 8 + wid;
    int mul = (rg < Rw);
    int r = mul ? rg : rg - Rw;
    int R = mul ? Rw : Rx;
    const float* row = (mul ? W : X) + ((long)e * R + r) * (long)C;
    const float* sv  = (mul ? s : sinv) + (long)e * C;

    float4 v[NV];
    float m = 0.f;
#pragma unroll
    for (int i = 0; i < NV; ++i) {
        int c = lane * 4 + i * 128;
        float4 rv = *(const float4*)(row + c);
        float4 svv = *(const float4*)(sv + c);
        float4 vv;
        vv.x = rv.x * svv.x; vv.y = rv.y * svv.y;
        vv.z = rv.z * svv.z; vv.w = rv.w * svv.w;
        v[i] = vv;
        m = fmaxf(m, fmaxf(fmaxf(fabsf(vv.x), fabsf(vv.y)), fmaxf(fabsf(vv.z), fabsf(vv.w))));
    }
#pragma unroll
    for (int off = 16; off > 0; off >>= 1)
        m = fmaxf(m, __shfl_xor_sync(0xFFFFFFFFu, m, off));
    float scale = fmaxf(m, EPS_) * (1.0f / QMAX_);
    if (lane == 0) (mul ? rsw : rsx)[(long)e * R + r] = scale;

    __nv_bfloat16* qr = (mul ? qw : qx) + ((long)e * R + r) * (long)C;
#pragma unroll
    for (int i = 0; i < NV; ++i) {
        int c = lane * 4 + i * 128;
        float q0 = fminf(fmaxf(rintf(v[i].x / scale), -QMAX_), QMAX_);
        float q1 = fminf(fmaxf(rintf(v[i].y / scale), -QMAX_), QMAX_);
        float q2 = fminf(fmaxf(rintf(v[i].z / scale), -QMAX_), QMAX_);
        float q3 = fminf(fmaxf(rintf(v[i].w / scale), -QMAX_), QMAX_);
        __nv_bfloat162 p0 = __floats2bfloat162_rn(q0, q1);
        __nv_bfloat162 p1 = __floats2bfloat162_rn(q2, q3);
        uint2 st;
        st.x = *(uint32_t*)&p0;
        st.y = *(uint32_t*)&p1;
        *(uint2*)(qr + c) = st;
    }
}

// ---------------- GEMM1 + SwiGLU fused (tcgen05 + TMA, M=256, N256-MMA) -------
// Stage = A0+A1+Bg+Bu = 64KB (Bg||Bu contiguous -> one N=256 B operand).
// Per chunk: 8 MMAs (4 k-steps x 2 m-tiles), A read ONCE per k-step.
// Warp-specialized: tid0 consumer (full-wait -> 8 MMA -> commit done);
// tid32 producer (done-wait -> expect_tx -> 4 TMA; final drain by producer).
// TMEM 512 cols: [gate_m0|up_m0]@0..255, [gate_m1|up_m1]@256..511.
#define F1STAGES 3
#define F1STAGE_BYTES 65536
#define F1SMEM_BYTES (F1STAGES * F1STAGE_BYTES + 1024)

__global__ void __launch_bounds__(256, 1)
gemm1_swiglu_tc(const __grid_constant__ CUtensorMap tmA,
                const __grid_constant__ CUtensorMap tmB,
                const __nv_bfloat16* __restrict__ A, const __nv_bfloat16* __restrict__ B,
                const float* __restrict__ asc_, const float* __restrict__ bsc_) {
    extern __shared__ int8_t dynraw[];
    const int tid = threadIdx.x;
    const int e = blockIdx.z;
    const int m0 = blockIdx.y * 256, n0 = blockIdx.x * 128;
#if USE_TC
    __shared__ __align__(16) uint64_t mbar_store[2 * F1STAGES];   // full 0..2, done 3..5
    __shared__ uint32_t tmem_addr_sh;
    __shared__ float cmax[128];

    const uint32_t sbase = (smem_u32(dynraw) + 1023u) & ~1023u;
    const uint32_t mbar0 = smem_u32(&mbar_store[0]);
    const int wid = tid >> 5;
    const int lane = tid & 31;
    const int nchunks = D_ >> 6;   // 32

    if (wid == 0) {
        TCGEN05_ALLOC(smem_u32(&tmem_addr_sh), 512);
        TCGEN05_RELINQUISH();
    }
    if (tid == 0) {
#pragma unroll
        for (int s = 0; s < 2 * F1STAGES; ++s) MBARRIER_INIT(mbar0 + 8 * s, 1);
    }
    for (int i = tid; i < 128; i += 256) cmax[i] = 0.f;
    __syncthreads();
    const uint32_t tmem = tmem_addr_sh;

    if (tid == 0) {
        // -------- MMA consumer --------
        for (int it = 0; it < nchunks; ++it) {
            int s = it % F1STAGES;
            MBARRIER_WAIT_PARITY(mbar0 + 8 * s, (it / F1STAGES) & 1);
            uint32_t base = sbase + (uint32_t)s * F1STAGE_BYTES;
            uint64_t a0 = MAKE_SMEM_DESC(base);
            uint64_t a1 = MAKE_SMEM_DESC(base + 16384);
            uint64_t bd = MAKE_SMEM_DESC(base + 32768);   // Bg||Bu, N=256
            bool acc0 = (it > 0);
#pragma unroll
            for (int ks = 0; ks < 4; ++ks) {
                bool acc = acc0 || (ks > 0);
                tcgen05_mma_f16_ss(tmem,       a0 + ks * 2, bd + ks * 2, IDESC_BF16_N256, acc);
                tcgen05_mma_f16_ss(tmem + 256, a1 + ks * 2, bd + ks * 2, IDESC_BF16_N256, acc);
            }
            TCGEN05_COMMIT(mbar0 + 8 * (F1STAGES + s));
        }
    } else if (tid == 32) {
        // -------- TMA producer (separate warp; independent phase tracking) ----
        const int rowA = e * T_ + m0;
        const int rowG = e * TWOI_ + n0;
        const int rowU = rowG + I_;
        for (int j = 0; j < nchunks; ++j) {
            if (j >= F1STAGES) {
                int c = j - F1STAGES;
                MBARRIER_WAIT_PARITY(mbar0 + 8 * (F1STAGES + c % F1STAGES),
                                     (c / F1STAGES) & 1);
            }
            int s = j % F1STAGES;
            uint32_t base = sbase + (uint32_t)s * F1STAGE_BYTES;
            uint32_t fb = mbar0 + 8 * s;
            MBARRIER_EXPECT_TX(fb, F1STAGE_BYTES);
            int cx = j * 64;
            TMA_LOAD_2D(base,         &tmA, cx, rowA,       fb);
            TMA_LOAD_2D(base + 16384, &tmA, cx, rowA + 128, fb);
            TMA_LOAD_2D(base + 32768, &tmB, cx, rowG,       fb);
            TMA_LOAD_2D(base + 49152, &tmB, cx, rowU,       fb);
        }
        // drain: wait remaining done phases (chunks nchunks-S .. nchunks-1)
        for (int c = nchunks - F1STAGES; c < nchunks; ++c)
            if (c >= 0)
                MBARRIER_WAIT_PARITY(mbar0 + 8 * (F1STAGES + c % F1STAGES),
                                     (c / F1STAGES) & 1);
    }
    // rendezvous: producer has confirmed ALL MMAs complete
    __syncthreads();
    TCGEN05_FENCE_AFTER();

    // epilogue: warp -> m-tile (wid>>2), subpartition rows (wid&3)*32+lane
    {
        int mt = wid >> 2;
        uint32_t tb = tmem + mt * 256;
        long t = m0 + mt * 128 + (wid & 3) * 32 + lane;
        float as = asc_[(long)e * T_ + t];
        float* dstrow = g_a + ((long)e * T_ + t) * (long)I_ + n0;
        const float* bsg = bsc_ + (long)e * TWOI_ + n0;
        const float* bsu = bsc_ + (long)e * TWOI_ + n0 + I_;
#pragma unroll
        for (int part = 0; part < 4; ++part) {
            uint32_t dg[32], du[32];
            TCGEN05_LD_32X32B_X32(dg, tb + part * 32);
            TCGEN05_LD_32X32B_X32(du, tb + 128 + part * 32);
            TCGEN05_WAIT_LD();
            float amx[32];
#pragma unroll
            for (int c = 0; c < 32; c += 4) {
                float4 v;
#pragma unroll
                for (int j2 = 0; j2 < 4; ++j2) {
                    int cc = c + j2;
                    float gv = __uint_as_float(dg[cc]) * as * bsg[part * 32 + cc];
                    float uv = __uint_as_float(du[cc]) * as * bsu[part * 32 + cc];
                    float vv = (gv / (1.0f + expf(-gv))) * uv;
                    ((float*)&v)[j2] = vv;
                    amx[cc] = fabsf(vv);
                }
                *(float4*)(dstrow + part * 32 + c) = v;
            }
#pragma unroll
            for (int c = 0; c < 32; ++c) {
#pragma unroll
                for (int off = 16; off > 0; off >>= 1)
                    amx[c] = fmaxf(amx[c], __shfl_xor_sync(0xFFFFFFFFu, amx[c], off));
            }
            atomicMax((unsigned int*)&cmax[part * 32 + lane],
                      __float_as_uint(amx[lane]));
        }
        TCGEN05_FENCE_BEFORE();
    }
    __syncthreads();
    if (tid < 128)
        atomicMax((unsigned int*)(g_amax_a + (long)e * I_ + n0 + tid),
                  __float_as_uint(cmax[tid]));
    if (wid == 0) {
        TCGEN05_DEALLOC(tmem, 512);
    }
#else
    // naive fallback (never selected on sm_103a; correctness-preserving)
    for (int idx = tid; idx < 256 * 128; idx += 256) {
        int i = idx >> 7, j = idx & 127;
        long t = m0 + i;
        int n = n0 + j;
        const __nv_bfloat16* ar = A + (long)e * T_ * D_ + t * (long)D_;
        const __nv_bfloat16* bg = B + (long)e * TWOI_ * D_ + (long)n * D_;
        const __nv_bfloat16* bu = B + (long)e * TWOI_ * D_ + (long)(n + I_) * D_;
        float sg = 0.f, su = 0.f;
        for (int k = 0; k < D_; ++k) {
            float av = __bfloat162float(ar[k]);
            sg = fmaf(av, __bfloat162float(bg[k]), sg);
            su = fmaf(av, __bfloat162float(bu[k]), su);
        }
        float as = asc_[(long)e * T_ + t];
        float gv = sg * as * bsc_[(long)e * TWOI_ + n];
        float uv = su * as * bsc_[(long)e * TWOI_ + n + I_];
        float vv = (gv / (1.0f + expf(-gv))) * uv;
        g_a[((long)e * T_ + t) * I_ + n] = vv;
        atomicMax((unsigned int*)(g_amax_a + (long)e * I_ + n),
                  __float_as_uint(fabsf(vv)));
    }
#endif
}

// ---------------- GEMM2 (tcgen05 + TMA, M=256 x N=256, N256-MMA) --------------
#define G2STAGES 3
#define G2STAGE_BYTES 65536
#define G2SMEM_BYTES (G2STAGES * G2STAGE_BYTES + 1024)

__global__ void __launch_bounds__(256, 1)
gemm2_bf16_tc(const __grid_constant__ CUtensorMap tmA,
              const __grid_constant__ CUtensorMap tmB,
              const __nv_bfloat16* __restrict__ A, const __nv_bfloat16* __restrict__ B,
              float* __restrict__ Co, const float* __restrict__ asc_,
              const float* __restrict__ bsc_) {
    extern __shared__ int8_t dynraw[];
    const int tid = threadIdx.x;
    const int e = blockIdx.z;
    const int m0 = blockIdx.y * 256, n0 = blockIdx.x * 256;
    const int M = T_, N = D_, K = I_;
#if USE_TC
    __shared__ __align__(16) uint64_t mbar_store[2 * G2STAGES];
    __shared__ uint32_t tmem_addr_sh;

    const uint32_t sbase = (smem_u32(dynraw) + 1023u) & ~1023u;
    const uint32_t mbar0 = smem_u32(&mbar_store[0]);
    const int wid = tid >> 5;
    const int lane = tid & 31;
    const int nchunks = K >> 6;   // 16

    if (wid == 0) {
        TCGEN05_ALLOC(smem_u32(&tmem_addr_sh), 512);
        TCGEN05_RELINQUISH();
    }
    if (tid == 0) {
#pragma unroll
        for (int s = 0; s < 2 * G2STAGES; ++s) MBARRIER_INIT(mbar0 + 8 * s, 1);
    }
    __syncthreads();
    const uint32_t tmem = tmem_addr_sh;

    if (tid == 0) {
        // -------- MMA consumer --------
        for (int it = 0; it < nchunks; ++it) {
            int s = it % G2STAGES;
            MBARRIER_WAIT_PARITY(mbar0 + 8 * s, (it / G2STAGES) & 1);
            uint32_t base = sbase + (uint32_t)s * G2STAGE_BYTES;
            uint64_t a0 = MAKE_SMEM_DESC(base);
            uint64_t a1 = MAKE_SMEM_DESC(base + 16384);
            uint64_t bd = MAKE_SMEM_DESC(base + 32768);   // B0||B1, N=256
            bool acc0 = (it > 0);
#pragma unroll
            for (int ks = 0; ks < 4; ++ks) {
                bool acc = acc0 || (ks > 0);
                tcgen05_mma_f16_ss(tmem,       a0 + ks * 2, bd + ks * 2, IDESC_BF16_N256, acc);
                tcgen05_mma_f16_ss(tmem + 256, a1 + ks * 2, bd + ks * 2, IDESC_BF16_N256, acc);
            }
            TCGEN05_COMMIT(mbar0 + 8 * (G2STAGES + s));
        }
    } else if (tid == 32) {
        // -------- TMA producer --------
        const int rowA = e * M + m0;
        const int rowB = e * N + n0;
        for (int j = 0; j < nchunks; ++j) {
            if (j >= G2STAGES) {
                int c = j - G2STAGES;
                MBARRIER_WAIT_PARITY(mbar0 + 8 * (G2STAGES + c % G2STAGES),
                                     (c / G2STAGES) & 1);
            }
            int s = j % G2STAGES;
            uint32_t base = sbase + (uint32_t)s * G2STAGE_BYTES;
            uint32_t fb = mbar0 + 8 * s;
            MBARRIER_EXPECT_TX(fb, G2STAGE_BYTES);
            int cx = j * 64;
            TMA_LOAD_2D(base,         &tmA, cx, rowA,       fb);
            TMA_LOAD_2D(base + 16384, &tmA, cx, rowA + 128, fb);
            TMA_LOAD_2D(base + 32768, &tmB, cx, rowB,       fb);
            TMA_LOAD_2D(base + 49152, &tmB, cx, rowB + 128, fb);
        }
        for (int c = nchunks - G2STAGES; c < nchunks; ++c)
            if (c >= 0)
                MBARRIER_WAIT_PARITY(mbar0 + 8 * (G2STAGES + c % G2STAGES),
                                     (c / G2STAGES) & 1);
    }
    __syncthreads();
    TCGEN05_FENCE_AFTER();

    // epilogue: warp -> m-tile (wid>>2); 8 parts of 32 cols, 2 LDTMs per wait
    {
        int mt = wid >> 2;
        long row = m0 + mt * 128 + (wid & 3) * 32 + lane;
        float as = asc_[(long)e * M + row];
        const float* bs = bsc_ + (long)e * N + n0;
        float* dst = Co + (long)e * M * N + row * N + n0;
#pragma unroll
        for (int pp = 0; pp < 4; ++pp) {
            int p0 = 2 * pp, p1 = 2 * pp + 1;
            uint32_t ta0 = tmem + mt * 256 + ((p0 >= 4) ? 128 : 0) + (p0 & 3) * 32;
            uint32_t ta1 = tmem + mt * 256 + ((p1 >= 4) ? 128 : 0) + (p1 & 3) * 32;
            uint32_t d0[32], d1[32];
            TCGEN05_LD_32X32B_X32(d0, ta0);
            TCGEN05_LD_32X32B_X32(d1, ta1);
            TCGEN05_WAIT_LD();
#pragma unroll
            for (int c = 0; c < 32; c += 4) {
                float4 v;
                v.x = __uint_as_float(d0[c + 0]) * as * bs[p0 * 32 + c + 0];
                v.y = __uint_as_float(d0[c + 1]) * as * bs[p0 * 32 + c + 1];
                v.z = __uint_as_float(d0[c + 2]) * as * bs[p0 * 32 + c + 2];
                v.w = __uint_as_float(d0[c + 3]) * as * bs[p0 * 32 + c + 3];
                *(float4*)(dst + p0 * 32 + c) = v;
            }
#pragma unroll
            for (int c = 0; c < 32; c += 4) {
                float4 v;
                v.x = __uint_as_float(d1[c + 0]) * as * bs[p1 * 32 + c + 0];
                v.y = __uint_as_float(d1[c + 1]) * as * bs[p1 * 32 + c + 1];
                v.z = __uint_as_float(d1[c + 2]) * as * bs[p1 * 32 + c + 2];
                v.w = __uint_as_float(d1[c + 3]) * as * bs[p1 * 32 + c + 3];
                *(float4*)(dst + p1 * 32 + c) = v;
            }
        }
        TCGEN05_FENCE_BEFORE();
    }
    __syncthreads();
    if (wid == 0) {
        TCGEN05_DEALLOC(tmem, 512);
    }
#else
    // naive fallback (never selected on sm_103a)
    for (int idx = tid; idx < 256 * 256; idx += 256) {
        int i = idx >> 8, j = idx & 255;
        long r = m0 + i;
        int n = n0 + j;
        const __nv_bfloat16* ar = A + (long)e * M * K + r * (long)K;
        const __nv_bfloat16* br = B + (long)e * N * K + (long)n * K;
        float sum = 0.f;
        for (int k = 0; k < K; ++k)
            sum = fmaf(__bfloat162float(ar[k]), __bfloat162float(br[k]), sum);
        Co[(long)e * M * N + r * N + n] = sum * asc_[(long)e * M + r] * bsc_[(long)e * N + n];
    }
#endif
}

// ---------------- host: tensor-map encode via runtime entry point ------------
typedef CUresult (*TmEncodeFn)(CUtensorMap*, CUtensorMapDataType, cuuint32_t,
    void*, const cuuint64_t*, const cuuint64_t*, const cuuint32_t*, const cuuint32_t*,
    CUtensorMapInterleave, CUtensorMapSwizzle, CUtensorMapL2promotion,
    CUtensorMapFloatOOBfill);

static void make_tm_bf16(TmEncodeFn enc, CUtensorMap* tm, void* base,
                         unsigned dim0, unsigned long long rows) {
    cuuint64_t dims[2] = {(cuuint64_t)dim0, (cuuint64_t)rows};
    cuuint64_t strides[1] = {(cuuint64_t)dim0 * 2};
    cuuint32_t box[2] = {64, 128};        // 64 bf16 = 128B (SW128 span) x 128 rows
    cuuint32_t estr[2] = {1, 1};
    enc(tm, CU_TENSOR_MAP_DATA_TYPE_BFLOAT16, 2, base, dims, strides, box, estr,
        CU_TENSOR_MAP_INTERLEAVE_NONE, CU_TENSOR_MAP_SWIZZLE_128B,
        CU_TENSOR_MAP_L2_PROMOTION_L2_128B, CU_TENSOR_MAP_FLOAT_OOB_FILL_NONE);
}

// ---------------- launch ------------------------------------------------------
extern "C" void kernel_launch(void* const* d_in, const int* in_sizes, int n_in,
                              void* d_out, int out_size) {
    const float* x   = (const float*)d_in[0];   // [E, T, D]
    const float* guw = (const float*)d_in[1];   // [E, 2I, D]
    const float* dw  = (const float*)d_in[2];   // [E, D, I]
    float* out = (float*)d_out;                 // [E, T, D]

    __nv_bfloat16 *xq1, *wq1, *aq, *wq2;
    float *a, *ax1, *aw1, *aa, *aw2, *s1, *si1, *s2, *si2, *xs1, *ws1, *xs2, *ws2;
    cudaGetSymbolAddress((void**)&xq1, g_xq1);
    cudaGetSymbolAddress((void**)&wq1, g_wq1);
    cudaGetSymbolAddress((void**)&aq,  g_aq);
    cudaGetSymbolAddress((void**)&wq2, g_wq2);
    cudaGetSymbolAddress((void**)&a,   g_a);
    cudaGetSymbolAddress((void**)&ax1, g_amax_x1);
    cudaGetSymbolAddress((void**)&aw1, g_amax_w1);
    cudaGetSymbolAddress((void**)&aa,  g_amax_a);
    cudaGetSymbolAddress((void**)&aw2, g_amax_w2);
    cudaGetSymbolAddress((void**)&s1,  g_s1);
    cudaGetSymbolAddress((void**)&si1, g_sinv1);
    cudaGetSymbolAddress((void**)&s2,  g_s2);
    cudaGetSymbolAddress((void**)&si2, g_sinv2);
    cudaGetSymbolAddress((void**)&xs1, g_xs1);
    cudaGetSymbolAddress((void**)&ws1, g_ws1);
    cudaGetSymbolAddress((void**)&xs2, g_xs2);
    cudaGetSymbolAddress((void**)&ws2, g_ws2);

    // driver tensor-map encoder via runtime (no -lcuda needed)
    void* fp = nullptr;
    cudaGetDriverEntryPoint("cuTensorMapEncodeTiled", &fp, cudaEnableDefault);
    TmEncodeFn enc = (TmEncodeFn)fp;
    CUtensorMap tmX1{}, tmW1{}, tmA2{}, tmW2{};
    make_tm_bf16(enc, &tmX1, xq1, D_, (unsigned long long)E_ * T_);
    make_tm_bf16(enc, &tmW1, wq1, D_, (unsigned long long)E_ * TWOI_);
    make_tm_bf16(enc, &tmA2, aq,  I_, (unsigned long long)E_ * T_);
    make_tm_bf16(enc, &tmW2, wq2, I_, (unsigned long long)E_ * D_);

    cudaFuncSetAttribute(gemm1_swiglu_tc, cudaFuncAttributeMaxDynamicSharedMemorySize,
                         F1SMEM_BYTES);
    cudaFuncSetAttribute(gemm2_bf16_tc, cudaFuncAttributeMaxDynamicSharedMemorySize,
                         G2SMEM_BYTES);

    // [0] all three column-amax reductions in one concurrent launch
    colmax_all_kernel<<<dim3(1, 160, E_), 256>>>(x, guw, dw);
    // [1] smooth scale s1 + 1/s1 (+ zero amax_x1/amax_w1 for next replay)
    smooth_scale_zero_kernel<<<(E_ * D_ + 255) / 256, 256>>>(ax1, aw1, s1, si1, E_ * D_);
    // [2] quantize guw + x (bf16-held integers)
    quant_warp_kernel<D_><<<dim3((TWOI_ + T_) / 8, E_), 256>>>(guw, x, s1, si1, wq1, xq1,
                                                               ws1, xs1, TWOI_, T_);
    // [3] fused GEMM1 + SwiGLU (N256 MMA)  <- ncu-profiled slot
    gemm1_swiglu_tc<<<dim3(I_ / 128, T_ / 256, E_), 256, F1SMEM_BYTES>>>(
        tmX1, tmW1, xq1, wq1, xs1, ws1);
    // [4] smooth scale s2 + 1/s2 (+ zero amax_a/amax_w2)
    smooth_scale_zero_kernel<<<(E_ * I_ + 255) / 256, 256>>>(aa, aw2, s2, si2, E_ * I_);
    // [5] quantize dw + a
    quant_warp_kernel<I_><<<dim3((D_ + T_) / 8, E_), 256>>>(dw, a, s2, si2, wq2, aq,
                                                            ws2, xs2, D_, T_);
    // [6] GEMM2 -> out (N256 MMA)
    gemm2_bf16_tc<<<dim3(D_ / 256, T_ / 256, E_), 256, G2SMEM_BYTES>>>(
        tmA2, tmW2, aq, wq2, out, xs2, ws2);
    (void)in_sizes; (void)n_in; (void)out_size;
}